// round 1
// baseline (speedup 1.0000x reference)
#include <cuda_runtime.h>
#include <math.h>

// ---------------- problem constants ----------------
#define BB   2
#define SS   2048
#define DM   1024
#define NT   (BB*SS)     // 4096 tokens
#define NH   16
#define HD   64
#define DSTATE 128
#define DFF  4096

// ---------------- device scratch (no allocs allowed) ----------------
__device__ float g_h   [NT*DM];
__device__ float g_q   [NT*DM];
__device__ float g_k   [NT*DM];
__device__ float g_v   [NT*DM];
__device__ float g_attn[NT*DM];
__device__ float g_ff1 [NT*DFF];
__device__ float g_ff2 [NT*DFF];

// ---------------- block reduction ----------------
__device__ __forceinline__ float block_sum(float v, float* sbuf) {
    int lane = threadIdx.x & 31, w = threadIdx.x >> 5;
    #pragma unroll
    for (int o = 16; o; o >>= 1) v += __shfl_xor_sync(0xffffffffu, v, o);
    if (lane == 0) sbuf[w] = v;
    __syncthreads();
    if (w == 0) {
        v = (lane < 8) ? sbuf[lane] : 0.f;
        #pragma unroll
        for (int o = 4; o; o >>= 1) v += __shfl_xor_sync(0xffffffffu, v, o);
        if (lane == 0) sbuf[0] = v;
    }
    __syncthreads();
    float r = sbuf[0];
    __syncthreads();
    return r;
}

// ---------------- fused: x+=rms(x,w1); x+=rms(x,w2); h=rms(x,w3) ----------------
__global__ __launch_bounds__(256) void norm3_fused(
    const float* __restrict__ x,
    const float* __restrict__ w1, const float* __restrict__ w2, const float* __restrict__ w3,
    float* __restrict__ xout, float* __restrict__ hout)
{
    __shared__ float sbuf[32];
    const int t = blockIdx.x;
    const int base = threadIdx.x * 4;
    float4 v  = *(const float4*)(x + (size_t)t*DM + base);
    float4 a1 = *(const float4*)(w1 + base);
    float4 a2 = *(const float4*)(w2 + base);
    float4 a3 = *(const float4*)(w3 + base);

    float ss = v.x*v.x + v.y*v.y + v.z*v.z + v.w*v.w;
    float r = rsqrtf(block_sum(ss, sbuf) * (1.f/DM) + 1e-6f);
    v.x += a1.x*v.x*r; v.y += a1.y*v.y*r; v.z += a1.z*v.z*r; v.w += a1.w*v.w*r;

    ss = v.x*v.x + v.y*v.y + v.z*v.z + v.w*v.w;
    r = rsqrtf(block_sum(ss, sbuf) * (1.f/DM) + 1e-6f);
    v.x += a2.x*v.x*r; v.y += a2.y*v.y*r; v.z += a2.z*v.z*r; v.w += a2.w*v.w*r;
    *(float4*)(xout + (size_t)t*DM + base) = v;

    ss = v.x*v.x + v.y*v.y + v.z*v.z + v.w*v.w;
    r = rsqrtf(block_sum(ss, sbuf) * (1.f/DM) + 1e-6f);
    float4 hv;
    hv.x = a3.x*v.x*r; hv.y = a3.y*v.y*r; hv.z = a3.z*v.z*r; hv.w = a3.w*v.w*r;
    *(float4*)(hout + (size_t)t*DM + base) = hv;
}

// ---------------- plain rmsnorm: out = w * x * rsqrt(mean(x^2)+eps) ----------------
__global__ __launch_bounds__(256) void rmsnorm_k(
    const float* __restrict__ x, const float* __restrict__ w, float* __restrict__ out)
{
    __shared__ float sbuf[32];
    const int t = blockIdx.x;
    const int base = threadIdx.x * 4;
    float4 v = *(const float4*)(x + (size_t)t*DM + base);
    float4 a = *(const float4*)(w + base);
    float ss = v.x*v.x + v.y*v.y + v.z*v.z + v.w*v.w;
    float r = rsqrtf(block_sum(ss, sbuf) * (1.f/DM) + 1e-6f);
    float4 o;
    o.x = a.x*v.x*r; o.y = a.y*v.y*r; o.z = a.z*v.z*r; o.w = a.w*v.w*r;
    *(float4*)(out + (size_t)t*DM + base) = o;
}

// ---------------- SGEMM 128x128x8, 8x8 per thread, epilogue variants ----------------
// EPI: 0 none | 1 +extra (residual) | 2 silu(acc+bias) | 3 (acc+bias)*extra | 4 acc+bias+extra
template<int EPI>
__global__ __launch_bounds__(256) void sgemm_k(
    const float* __restrict__ A, const float* __restrict__ Bm,
    const float* __restrict__ bias, const float* __restrict__ extra,
    float* __restrict__ C, int M, int N, int K)
{
    __shared__ float As[8][128];
    __shared__ float Bs[8][128];
    const int tid = threadIdx.x;
    const int bx = blockIdx.x, by = blockIdx.y;
    const float* Ab = A + (size_t)by*128*K;
    const float* Bb = Bm + (size_t)bx*128;

    const int arow = tid >> 1, acol = (tid & 1) * 4;
    const int brow = tid >> 5, bcol = (tid & 31) * 4;
    const int ty = tid >> 4, tx = tid & 15;

    float acc[8][8];
    #pragma unroll
    for (int i = 0; i < 8; i++)
        #pragma unroll
        for (int j = 0; j < 8; j++) acc[i][j] = 0.f;

    for (int kt = 0; kt < K; kt += 8) {
        float4 av = *(const float4*)(Ab + (size_t)arow*K + kt + acol);
        float4 bv = *(const float4*)(Bb + (size_t)(kt + brow)*N + bcol);
        As[acol+0][arow] = av.x; As[acol+1][arow] = av.y;
        As[acol+2][arow] = av.z; As[acol+3][arow] = av.w;
        *(float4*)(&Bs[brow][bcol]) = bv;
        __syncthreads();
        #pragma unroll
        for (int kk = 0; kk < 8; kk++) {
            float ra[8], rb[8];
            *(float4*)(ra)   = *(const float4*)(&As[kk][ty*8]);
            *(float4*)(ra+4) = *(const float4*)(&As[kk][ty*8+4]);
            *(float4*)(rb)   = *(const float4*)(&Bs[kk][tx*8]);
            *(float4*)(rb+4) = *(const float4*)(&Bs[kk][tx*8+4]);
            #pragma unroll
            for (int i = 0; i < 8; i++)
                #pragma unroll
                for (int j = 0; j < 8; j++) acc[i][j] += ra[i]*rb[j];
        }
        __syncthreads();
    }

    const int row0 = by*128 + ty*8, col0 = bx*128 + tx*8;
    float bv8[8];
    if (EPI >= 2) {
        #pragma unroll
        for (int j = 0; j < 8; j++) bv8[j] = bias[col0 + j];
    }
    #pragma unroll
    for (int i = 0; i < 8; i++) {
        const size_t ro = (size_t)(row0 + i) * N + col0;
        float o[8];
        #pragma unroll
        for (int j = 0; j < 8; j++) {
            float s = acc[i][j];
            if (EPI == 1) s += extra[ro + j];
            if (EPI == 2) { s += bv8[j]; s = s / (1.f + __expf(-s)); }
            if (EPI == 3) { s += bv8[j]; s *= extra[ro + j]; }
            if (EPI == 4) { s += bv8[j] + extra[ro + j]; }
            o[j] = s;
        }
        *(float4*)(C + ro)     = *(float4*)(o);
        *(float4*)(C + ro + 4) = *(float4*)(o + 4);
    }
}

// ---------------- per-(token,head) SiLU-MLP residual on q/k ----------------
// v = silu(v @ w1 + b1) @ w2 + b2 + v ; rows are 65536 contiguous 64-float vectors
__global__ __launch_bounds__(256) void qk_mlp(
    float* __restrict__ qbuf, float* __restrict__ kbuf,
    const float* __restrict__ qw1, const float* __restrict__ qb1,
    const float* __restrict__ qw2, const float* __restrict__ qb2,
    const float* __restrict__ kw1, const float* __restrict__ kb1,
    const float* __restrict__ kw2, const float* __restrict__ kb2)
{
    __shared__ float sw1[HD*DSTATE];   // 32 KB
    __shared__ float sx[16*HD];        // 4 KB
    __shared__ float shid[16*DSTATE];  // 8 KB
    const int tid = threadIdx.x;
    float* data        = blockIdx.y ? kbuf : qbuf;
    const float* w1    = blockIdx.y ? kw1 : qw1;
    const float* b1    = blockIdx.y ? kb1 : qb1;
    const float* w2    = blockIdx.y ? kw2 : qw2;
    const float* b2    = blockIdx.y ? kb2 : qb2;

    for (int i = tid; i < HD*DSTATE; i += 256) sw1[i] = w1[i];
    float* xb = data + (size_t)blockIdx.x * (16*HD);
    for (int i = tid; i < 16*HD; i += 256) sx[i] = xb[i];
    __syncthreads();

    for (int idx = tid; idx < 16*DSTATE; idx += 256) {
        const int r = idx >> 7, j = idx & 127;
        float s = b1[j];
        const float* xr = sx + r*HD;
        #pragma unroll
        for (int d = 0; d < HD; d++) s += xr[d] * sw1[d*DSTATE + j];
        shid[idx] = s / (1.f + __expf(-s));
    }
    __syncthreads();
    for (int idx = tid; idx < 16*HD; idx += 256) {
        const int r = idx >> 6, d = idx & 63;
        float s = b2[d];
        const float* hr = shid + r*DSTATE;
        #pragma unroll
        for (int j = 0; j < DSTATE; j++) s += hr[j] * w2[j*HD + d];
        xb[idx] = sx[idx] + s;
    }
}

// ---------------- causal flash attention: 64 q-rows x 32 k-cols tiles ----------------
__global__ __launch_bounds__(256) void flash_attn(
    const float* __restrict__ Q, const float* __restrict__ K,
    const float* __restrict__ V, float* __restrict__ O)
{
    const int qt = blockIdx.x;   // q tile (64 rows)
    const int h  = blockIdx.y;
    const int b  = blockIdx.z;
    __shared__ float Qs[64][65];
    __shared__ float Ks[32][65];
    __shared__ float Vt[64][33];   // transposed: Vt[d][c]
    __shared__ float Ps[64][33];

    const int tid = threadIdx.x;
    const int ty = tid >> 3;       // 0..31 -> rows 2*ty, 2*ty+1
    const int tx = tid & 7;        // score cols tx*4.. / out dims tx*8..
    const int r0 = 2*ty;

    // load Q tile
    const size_t qbase = ((size_t)(b*SS + qt*64)*NH + h)*HD;
    for (int i = tid; i < 64*16; i += 256) {
        const int r = i >> 4, c4 = (i & 15)*4;
        float4 qv = *(const float4*)(Q + qbase + (size_t)r*DM + c4);
        Qs[r][c4] = qv.x; Qs[r][c4+1] = qv.y; Qs[r][c4+2] = qv.z; Qs[r][c4+3] = qv.w;
    }

    float m[2] = {-1e30f, -1e30f}, l[2] = {0.f, 0.f};
    float accO[2][8];
    #pragma unroll
    for (int rr = 0; rr < 2; rr++)
        #pragma unroll
        for (int dd = 0; dd < 8; dd++) accO[rr][dd] = 0.f;

    const int nk = 2*qt + 2;
    for (int kj = 0; kj < nk; kj++) {
        __syncthreads();
        const size_t kbase = ((size_t)(b*SS + kj*32)*NH + h)*HD;
        for (int i = tid; i < 32*16; i += 256) {
            const int c = i >> 4, d4 = (i & 15)*4;
            float4 kv = *(const float4*)(K + kbase + (size_t)c*DM + d4);
            Ks[c][d4] = kv.x; Ks[c][d4+1] = kv.y; Ks[c][d4+2] = kv.z; Ks[c][d4+3] = kv.w;
            float4 vv = *(const float4*)(V + kbase + (size_t)c*DM + d4);
            Vt[d4][c] = vv.x; Vt[d4+1][c] = vv.y; Vt[d4+2][c] = vv.z; Vt[d4+3][c] = vv.w;
        }
        __syncthreads();

        // scores 2x4
        float s[2][4];
        #pragma unroll
        for (int rr = 0; rr < 2; rr++)
            #pragma unroll
            for (int cc = 0; cc < 4; cc++) s[rr][cc] = 0.f;
        #pragma unroll 4
        for (int d = 0; d < HD; d++) {
            const float q0 = Qs[r0][d], q1 = Qs[r0+1][d];
            #pragma unroll
            for (int cc = 0; cc < 4; cc++) {
                const float kv = Ks[tx*4 + cc][d];
                s[0][cc] += q0*kv;
                s[1][cc] += q1*kv;
            }
        }
        const bool need_mask = (kj*32 + 31 > qt*64);
        #pragma unroll
        for (int rr = 0; rr < 2; rr++) {
            #pragma unroll
            for (int cc = 0; cc < 4; cc++) {
                s[rr][cc] *= 0.125f;
                if (need_mask && (kj*32 + tx*4 + cc > qt*64 + r0 + rr)) s[rr][cc] = -1e30f;
            }
        }
        // online softmax per row (8 tx threads per row)
        #pragma unroll
        for (int rr = 0; rr < 2; rr++) {
            float mx = fmaxf(fmaxf(s[rr][0], s[rr][1]), fmaxf(s[rr][2], s[rr][3]));
            #pragma unroll
            for (int o = 1; o < 8; o <<= 1) mx = fmaxf(mx, __shfl_xor_sync(0xffffffffu, mx, o));
            const float mn = fmaxf(m[rr], mx);
            const float alpha = __expf(m[rr] - mn);
            float sum = 0.f;
            #pragma unroll
            for (int cc = 0; cc < 4; cc++) {
                const float p = __expf(s[rr][cc] - mn);
                Ps[r0+rr][tx*4 + cc] = p;
                sum += p;
            }
            #pragma unroll
            for (int o = 1; o < 8; o <<= 1) sum += __shfl_xor_sync(0xffffffffu, sum, o);
            l[rr] = l[rr]*alpha + sum;
            m[rr] = mn;
            #pragma unroll
            for (int dd = 0; dd < 8; dd++) accO[rr][dd] *= alpha;
        }
        __syncthreads();
        // PV: rows r0,r0+1 ; d = tx*8..tx*8+7
        const int d0 = tx*8;
        #pragma unroll 4
        for (int c = 0; c < 32; c++) {
            const float p0 = Ps[r0][c], p1 = Ps[r0+1][c];
            #pragma unroll
            for (int dd = 0; dd < 8; dd++) {
                const float vv = Vt[d0+dd][c];
                accO[0][dd] += p0*vv;
                accO[1][dd] += p1*vv;
            }
        }
    }

    #pragma unroll
    for (int rr = 0; rr < 2; rr++) {
        const float inv = 1.f / l[rr];
        const size_t ro = ((size_t)(b*SS + qt*64 + r0 + rr)*NH + h)*HD + tx*8;
        float4 o0, o1;
        o0.x = accO[rr][0]*inv; o0.y = accO[rr][1]*inv; o0.z = accO[rr][2]*inv; o0.w = accO[rr][3]*inv;
        o1.x = accO[rr][4]*inv; o1.y = accO[rr][5]*inv; o1.z = accO[rr][6]*inv; o1.w = accO[rr][7]*inv;
        *(float4*)(O + ro)     = o0;
        *(float4*)(O + ro + 4) = o1;
    }
}

// ---------------- launcher ----------------
extern "C" void kernel_launch(void* const* d_in, const int* in_sizes, int n_in,
                              void* d_out, int out_size)
{
    const float* x       = (const float*)d_in[0];
    // d_in[1] = attn_mask (causal, implicit) -- unused
    const float* norm1_w = (const float*)d_in[2];
    const float* norm2_w = (const float*)d_in[3];
    const float* norm3_w = (const float*)d_in[4];
    const float* mlpn_w  = (const float*)d_in[5];
    const float* wq      = (const float*)d_in[6];
    const float* wk      = (const float*)d_in[7];
    const float* wv      = (const float*)d_in[8];
    const float* wo      = (const float*)d_in[9];
    const float* qs_w1   = (const float*)d_in[10];
    const float* qs_b1   = (const float*)d_in[11];
    const float* qs_w2   = (const float*)d_in[12];
    const float* qs_b2   = (const float*)d_in[13];
    const float* ks_w1   = (const float*)d_in[14];
    const float* ks_b1   = (const float*)d_in[15];
    const float* ks_w2   = (const float*)d_in[16];
    const float* ks_b2   = (const float*)d_in[17];
    const float* fc1_w   = (const float*)d_in[18];
    const float* fc1_b   = (const float*)d_in[19];
    const float* fc2_w   = (const float*)d_in[20];
    const float* fc2_b   = (const float*)d_in[21];
    const float* gate_w  = (const float*)d_in[22];
    const float* gate_b  = (const float*)d_in[23];
    float* out = (float*)d_out;

    float *h, *q, *k, *v, *attn, *ff1, *ff2;
    cudaGetSymbolAddress((void**)&h,    g_h);
    cudaGetSymbolAddress((void**)&q,    g_q);
    cudaGetSymbolAddress((void**)&k,    g_k);
    cudaGetSymbolAddress((void**)&v,    g_v);
    cudaGetSymbolAddress((void**)&attn, g_attn);
    cudaGetSymbolAddress((void**)&ff1,  g_ff1);
    cudaGetSymbolAddress((void**)&ff2,  g_ff2);

    // 1. x += rms(x,w1); x += rms(x,w2); h = rms(x,w3)   (x lives in d_out)
    norm3_fused<<<NT, 256>>>(x, norm1_w, norm2_w, norm3_w, out, h);

    // 2. q,k,v projections
    dim3 g1(DM/128, NT/128);   // (8,32)
    sgemm_k<0><<<g1, 256>>>(h, wq, nullptr, nullptr, q, NT, DM, DM);
    sgemm_k<0><<<g1, 256>>>(h, wk, nullptr, nullptr, k, NT, DM, DM);
    sgemm_k<0><<<g1, 256>>>(h, wv, nullptr, nullptr, v, NT, DM, DM);

    // 3. per-head SiLU-MLP residual on q and k (in place)
    qk_mlp<<<dim3(NT*NH/16, 2), 256>>>(q, k, qs_w1, qs_b1, qs_w2, qs_b2,
                                        ks_w1, ks_b1, ks_w2, ks_b2);

    // 4. causal attention
    flash_attn<<<dim3(SS/64, NH, BB), 256>>>(q, k, v, attn);

    // 5. output projection + residual into x
    sgemm_k<1><<<g1, 256>>>(attn, wo, nullptr, out, out, NT, DM, DM);

    // 6. hn = rms(x, mlpn_w)
    rmsnorm_k<<<NT, 256>>>(out, mlpn_w, h);

    // 7. gate = silu(hn@gate_w + b) ; y = gate * (hn@fc1_w + b)
    dim3 g2(DFF/128, NT/128);  // (32,32)
    sgemm_k<2><<<g2, 256>>>(h, gate_w, gate_b, nullptr, ff1, NT, DFF, DM);
    sgemm_k<3><<<g2, 256>>>(h, fc1_w,  fc1_b,  ff1,     ff2, NT, DFF, DM);

    // 8. x += y@fc2_w + b
    sgemm_k<4><<<g1, 256>>>(ff2, fc2_w, fc2_b, out, out, NT, DM, DFF);
}

// round 2
// speedup vs baseline: 1.0043x; 1.0043x over previous
#include <cuda_runtime.h>
#include <math.h>

// ---------------- problem constants ----------------
#define BB   2
#define SS   2048
#define DM   1024
#define NT   (BB*SS)     // 4096 tokens
#define NH   16
#define HD   64
#define DSTATE 128
#define DFF  4096

// ---------------- device scratch (no allocs allowed) ----------------
__device__ float g_h   [NT*DM];
__device__ float g_q   [NT*DM];
__device__ float g_k   [NT*DM];
__device__ float g_v   [NT*DM];
__device__ float g_attn[NT*DM];
__device__ float g_ff1 [NT*DFF];
__device__ float g_ff2 [NT*DFF];

// ---------------- block reduction ----------------
__device__ __forceinline__ float block_sum(float v, float* sbuf) {
    int lane = threadIdx.x & 31, w = threadIdx.x >> 5;
    #pragma unroll
    for (int o = 16; o; o >>= 1) v += __shfl_xor_sync(0xffffffffu, v, o);
    if (lane == 0) sbuf[w] = v;
    __syncthreads();
    if (w == 0) {
        v = (lane < 8) ? sbuf[lane] : 0.f;
        #pragma unroll
        for (int o = 4; o; o >>= 1) v += __shfl_xor_sync(0xffffffffu, v, o);
        if (lane == 0) sbuf[0] = v;
    }
    __syncthreads();
    float r = sbuf[0];
    __syncthreads();
    return r;
}

// ---------------- fused: x+=rms(x,w1); x+=rms(x,w2); h=rms(x,w3) ----------------
__global__ __launch_bounds__(256) void norm3_fused(
    const float* __restrict__ x,
    const float* __restrict__ w1, const float* __restrict__ w2, const float* __restrict__ w3,
    float* __restrict__ xout, float* __restrict__ hout)
{
    __shared__ float sbuf[32];
    const int t = blockIdx.x;
    const int base = threadIdx.x * 4;
    float4 v  = *(const float4*)(x + (size_t)t*DM + base);
    float4 a1 = *(const float4*)(w1 + base);
    float4 a2 = *(const float4*)(w2 + base);
    float4 a3 = *(const float4*)(w3 + base);

    float ss = v.x*v.x + v.y*v.y + v.z*v.z + v.w*v.w;
    float r = rsqrtf(block_sum(ss, sbuf) * (1.f/DM) + 1e-6f);
    v.x += a1.x*v.x*r; v.y += a1.y*v.y*r; v.z += a1.z*v.z*r; v.w += a1.w*v.w*r;

    ss = v.x*v.x + v.y*v.y + v.z*v.z + v.w*v.w;
    r = rsqrtf(block_sum(ss, sbuf) * (1.f/DM) + 1e-6f);
    v.x += a2.x*v.x*r; v.y += a2.y*v.y*r; v.z += a2.z*v.z*r; v.w += a2.w*v.w*r;
    *(float4*)(xout + (size_t)t*DM + base) = v;

    ss = v.x*v.x + v.y*v.y + v.z*v.z + v.w*v.w;
    r = rsqrtf(block_sum(ss, sbuf) * (1.f/DM) + 1e-6f);
    float4 hv;
    hv.x = a3.x*v.x*r; hv.y = a3.y*v.y*r; hv.z = a3.z*v.z*r; hv.w = a3.w*v.w*r;
    *(float4*)(hout + (size_t)t*DM + base) = hv;
}

// ---------------- plain rmsnorm: out = w * x * rsqrt(mean(x^2)+eps) ----------------
__global__ __launch_bounds__(256) void rmsnorm_k(
    const float* __restrict__ x, const float* __restrict__ w, float* __restrict__ out)
{
    __shared__ float sbuf[32];
    const int t = blockIdx.x;
    const int base = threadIdx.x * 4;
    float4 v = *(const float4*)(x + (size_t)t*DM + base);
    float4 a = *(const float4*)(w + base);
    float ss = v.x*v.x + v.y*v.y + v.z*v.z + v.w*v.w;
    float r = rsqrtf(block_sum(ss, sbuf) * (1.f/DM) + 1e-6f);
    float4 o;
    o.x = a.x*v.x*r; o.y = a.y*v.y*r; o.z = a.z*v.z*r; o.w = a.w*v.w*r;
    *(float4*)(out + (size_t)t*DM + base) = o;
}

// ---------------- SGEMM 128x128x8, 8x8 per thread, epilogue variants ----------------
// EPI: 0 none | 1 +extra (residual) | 2 silu(acc+bias) | 3 (acc+bias)*extra | 4 acc+bias+extra
template<int EPI>
__global__ __launch_bounds__(256) void sgemm_k(
    const float* __restrict__ A, const float* __restrict__ Bm,
    const float* __restrict__ bias, const float* __restrict__ extra,
    float* __restrict__ C, int M, int N, int K)
{
    __shared__ float As[8][128];
    __shared__ float Bs[8][128];
    const int tid = threadIdx.x;
    const int bx = blockIdx.x, by = blockIdx.y;
    const float* Ab = A + (size_t)by*128*K;
    const float* Bb = Bm + (size_t)bx*128;

    const int arow = tid >> 1, acol = (tid & 1) * 4;
    const int brow = tid >> 5, bcol = (tid & 31) * 4;
    const int ty = tid >> 4, tx = tid & 15;

    float acc[8][8];
    #pragma unroll
    for (int i = 0; i < 8; i++)
        #pragma unroll
        for (int j = 0; j < 8; j++) acc[i][j] = 0.f;

    for (int kt = 0; kt < K; kt += 8) {
        float4 av = *(const float4*)(Ab + (size_t)arow*K + kt + acol);
        float4 bv = *(const float4*)(Bb + (size_t)(kt + brow)*N + bcol);
        As[acol+0][arow] = av.x; As[acol+1][arow] = av.y;
        As[acol+2][arow] = av.z; As[acol+3][arow] = av.w;
        *(float4*)(&Bs[brow][bcol]) = bv;
        __syncthreads();
        #pragma unroll
        for (int kk = 0; kk < 8; kk++) {
            float ra[8], rb[8];
            *(float4*)(ra)   = *(const float4*)(&As[kk][ty*8]);
            *(float4*)(ra+4) = *(const float4*)(&As[kk][ty*8+4]);
            *(float4*)(rb)   = *(const float4*)(&Bs[kk][tx*8]);
            *(float4*)(rb+4) = *(const float4*)(&Bs[kk][tx*8+4]);
            #pragma unroll
            for (int i = 0; i < 8; i++)
                #pragma unroll
                for (int j = 0; j < 8; j++) acc[i][j] += ra[i]*rb[j];
        }
        __syncthreads();
    }

    const int row0 = by*128 + ty*8, col0 = bx*128 + tx*8;
    float bv8[8];
    if (EPI >= 2) {
        #pragma unroll
        for (int j = 0; j < 8; j++) bv8[j] = bias[col0 + j];
    }
    #pragma unroll
    for (int i = 0; i < 8; i++) {
        const size_t ro = (size_t)(row0 + i) * N + col0;
        float o[8];
        #pragma unroll
        for (int j = 0; j < 8; j++) {
            float s = acc[i][j];
            if (EPI == 1) s += extra[ro + j];
            if (EPI == 2) { s += bv8[j]; s = s / (1.f + __expf(-s)); }
            if (EPI == 3) { s += bv8[j]; s *= extra[ro + j]; }
            if (EPI == 4) { s += bv8[j] + extra[ro + j]; }
            o[j] = s;
        }
        *(float4*)(C + ro)     = *(float4*)(o);
        *(float4*)(C + ro + 4) = *(float4*)(o + 4);
    }
}

// ---------------- per-(token,head) SiLU-MLP residual on q/k ----------------
// v = silu(v @ w1 + b1) @ w2 + b2 + v ; rows are 65536 contiguous 64-float vectors
__global__ __launch_bounds__(256) void qk_mlp(
    float* __restrict__ qbuf, float* __restrict__ kbuf,
    const float* __restrict__ qw1, const float* __restrict__ qb1,
    const float* __restrict__ qw2, const float* __restrict__ qb2,
    const float* __restrict__ kw1, const float* __restrict__ kb1,
    const float* __restrict__ kw2, const float* __restrict__ kb2)
{
    __shared__ float sw1[HD*DSTATE];   // 32 KB
    __shared__ float sx[16*HD];        // 4 KB
    __shared__ float shid[16*DSTATE];  // 8 KB
    const int tid = threadIdx.x;
    float* data        = blockIdx.y ? kbuf : qbuf;
    const float* w1    = blockIdx.y ? kw1 : qw1;
    const float* b1    = blockIdx.y ? kb1 : qb1;
    const float* w2    = blockIdx.y ? kw2 : qw2;
    const float* b2    = blockIdx.y ? kb2 : qb2;

    for (int i = tid; i < HD*DSTATE; i += 256) sw1[i] = w1[i];
    float* xb = data + (size_t)blockIdx.x * (16*HD);
    for (int i = tid; i < 16*HD; i += 256) sx[i] = xb[i];
    __syncthreads();

    for (int idx = tid; idx < 16*DSTATE; idx += 256) {
        const int r = idx >> 7, j = idx & 127;
        float s = b1[j];
        const float* xr = sx + r*HD;
        #pragma unroll
        for (int d = 0; d < HD; d++) s += xr[d] * sw1[d*DSTATE + j];
        shid[idx] = s / (1.f + __expf(-s));
    }
    __syncthreads();
    for (int idx = tid; idx < 16*HD; idx += 256) {
        const int r = idx >> 6, d = idx & 63;
        float s = b2[d];
        const float* hr = shid + r*DSTATE;
        #pragma unroll
        for (int j = 0; j < DSTATE; j++) s += hr[j] * w2[j*HD + d];
        xb[idx] = sx[idx] + s;
    }
}

// ---------------- causal flash attention: 64 q-rows x 32 k-cols tiles ----------------
__global__ __launch_bounds__(256) void flash_attn(
    const float* __restrict__ Q, const float* __restrict__ K,
    const float* __restrict__ V, float* __restrict__ O)
{
    const int qt = blockIdx.x;   // q tile (64 rows)
    const int h  = blockIdx.y;
    const int b  = blockIdx.z;
    __shared__ float Qs[64][65];
    __shared__ float Ks[32][65];
    __shared__ float Vt[64][33];   // transposed: Vt[d][c]
    __shared__ float Ps[64][33];

    const int tid = threadIdx.x;
    const int ty = tid >> 3;       // 0..31 -> rows 2*ty, 2*ty+1
    const int tx = tid & 7;        // score cols tx*4.. / out dims tx*8..
    const int r0 = 2*ty;

    // load Q tile
    const size_t qbase = ((size_t)(b*SS + qt*64)*NH + h)*HD;
    for (int i = tid; i < 64*16; i += 256) {
        const int r = i >> 4, c4 = (i & 15)*4;
        float4 qv = *(const float4*)(Q + qbase + (size_t)r*DM + c4);
        Qs[r][c4] = qv.x; Qs[r][c4+1] = qv.y; Qs[r][c4+2] = qv.z; Qs[r][c4+3] = qv.w;
    }

    float m[2] = {-1e30f, -1e30f}, l[2] = {0.f, 0.f};
    float accO[2][8];
    #pragma unroll
    for (int rr = 0; rr < 2; rr++)
        #pragma unroll
        for (int dd = 0; dd < 8; dd++) accO[rr][dd] = 0.f;

    const int nk = 2*qt + 2;
    for (int kj = 0; kj < nk; kj++) {
        __syncthreads();
        const size_t kbase = ((size_t)(b*SS + kj*32)*NH + h)*HD;
        for (int i = tid; i < 32*16; i += 256) {
            const int c = i >> 4, d4 = (i & 15)*4;
            float4 kv = *(const float4*)(K + kbase + (size_t)c*DM + d4);
            Ks[c][d4] = kv.x; Ks[c][d4+1] = kv.y; Ks[c][d4+2] = kv.z; Ks[c][d4+3] = kv.w;
            float4 vv = *(const float4*)(V + kbase + (size_t)c*DM + d4);
            Vt[d4][c] = vv.x; Vt[d4+1][c] = vv.y; Vt[d4+2][c] = vv.z; Vt[d4+3][c] = vv.w;
        }
        __syncthreads();

        // scores 2x4
        float s[2][4];
        #pragma unroll
        for (int rr = 0; rr < 2; rr++)
            #pragma unroll
            for (int cc = 0; cc < 4; cc++) s[rr][cc] = 0.f;
        #pragma unroll 4
        for (int d = 0; d < HD; d++) {
            const float q0 = Qs[r0][d], q1 = Qs[r0+1][d];
            #pragma unroll
            for (int cc = 0; cc < 4; cc++) {
                const float kv = Ks[tx*4 + cc][d];
                s[0][cc] += q0*kv;
                s[1][cc] += q1*kv;
            }
        }
        const bool need_mask = (kj*32 + 31 > qt*64);
        #pragma unroll
        for (int rr = 0; rr < 2; rr++) {
            #pragma unroll
            for (int cc = 0; cc < 4; cc++) {
                s[rr][cc] *= 0.125f;
                if (need_mask && (kj*32 + tx*4 + cc > qt*64 + r0 + rr)) s[rr][cc] = -1e30f;
            }
        }
        // online softmax per row (8 tx threads per row)
        #pragma unroll
        for (int rr = 0; rr < 2; rr++) {
            float mx = fmaxf(fmaxf(s[rr][0], s[rr][1]), fmaxf(s[rr][2], s[rr][3]));
            #pragma unroll
            for (int o = 1; o < 8; o <<= 1) mx = fmaxf(mx, __shfl_xor_sync(0xffffffffu, mx, o));
            const float mn = fmaxf(m[rr], mx);
            const float alpha = __expf(m[rr] - mn);
            float sum = 0.f;
            #pragma unroll
            for (int cc = 0; cc < 4; cc++) {
                const float p = __expf(s[rr][cc] - mn);
                Ps[r0+rr][tx*4 + cc] = p;
                sum += p;
            }
            #pragma unroll
            for (int o = 1; o < 8; o <<= 1) sum += __shfl_xor_sync(0xffffffffu, sum, o);
            l[rr] = l[rr]*alpha + sum;
            m[rr] = mn;
            #pragma unroll
            for (int dd = 0; dd < 8; dd++) accO[rr][dd] *= alpha;
        }
        __syncthreads();
        // PV: rows r0,r0+1 ; d = tx*8..tx*8+7
        const int d0 = tx*8;
        #pragma unroll 4
        for (int c = 0; c < 32; c++) {
            const float p0 = Ps[r0][c], p1 = Ps[r0+1][c];
            #pragma unroll
            for (int dd = 0; dd < 8; dd++) {
                const float vv = Vt[d0+dd][c];
                accO[0][dd] += p0*vv;
                accO[1][dd] += p1*vv;
            }
        }
    }

    #pragma unroll
    for (int rr = 0; rr < 2; rr++) {
        const float inv = 1.f / l[rr];
        const size_t ro = ((size_t)(b*SS + qt*64 + r0 + rr)*NH + h)*HD + tx*8;
        float4 o0, o1;
        o0.x = accO[rr][0]*inv; o0.y = accO[rr][1]*inv; o0.z = accO[rr][2]*inv; o0.w = accO[rr][3]*inv;
        o1.x = accO[rr][4]*inv; o1.y = accO[rr][5]*inv; o1.z = accO[rr][6]*inv; o1.w = accO[rr][7]*inv;
        *(float4*)(O + ro)     = o0;
        *(float4*)(O + ro + 4) = o1;
    }
}

// ---------------- launcher ----------------
extern "C" void kernel_launch(void* const* d_in, const int* in_sizes, int n_in,
                              void* d_out, int out_size)
{
    const float* x       = (const float*)d_in[0];
    // d_in[1] = attn_mask (causal, implicit) -- unused
    const float* norm1_w = (const float*)d_in[2];
    const float* norm2_w = (const float*)d_in[3];
    const float* norm3_w = (const float*)d_in[4];
    const float* mlpn_w  = (const float*)d_in[5];
    const float* wq      = (const float*)d_in[6];
    const float* wk      = (const float*)d_in[7];
    const float* wv      = (const float*)d_in[8];
    const float* wo      = (const float*)d_in[9];
    const float* qs_w1   = (const float*)d_in[10];
    const float* qs_b1   = (const float*)d_in[11];
    const float* qs_w2   = (const float*)d_in[12];
    const float* qs_b2   = (const float*)d_in[13];
    const float* ks_w1   = (const float*)d_in[14];
    const float* ks_b1   = (const float*)d_in[15];
    const float* ks_w2   = (const float*)d_in[16];
    const float* ks_b2   = (const float*)d_in[17];
    const float* fc1_w   = (const float*)d_in[18];
    const float* fc1_b   = (const float*)d_in[19];
    const float* fc2_w   = (const float*)d_in[20];
    const float* fc2_b   = (const float*)d_in[21];
    const float* gate_w  = (const float*)d_in[22];
    const float* gate_b  = (const float*)d_in[23];
    float* out = (float*)d_out;

    float *h, *q, *k, *v, *attn, *ff1, *ff2;
    cudaGetSymbolAddress((void**)&h,    g_h);
    cudaGetSymbolAddress((void**)&q,    g_q);
    cudaGetSymbolAddress((void**)&k,    g_k);
    cudaGetSymbolAddress((void**)&v,    g_v);
    cudaGetSymbolAddress((void**)&attn, g_attn);
    cudaGetSymbolAddress((void**)&ff1,  g_ff1);
    cudaGetSymbolAddress((void**)&ff2,  g_ff2);

    // 1. x += rms(x,w1); x += rms(x,w2); h = rms(x,w3)   (x lives in d_out)
    norm3_fused<<<NT, 256>>>(x, norm1_w, norm2_w, norm3_w, out, h);

    // 2. q,k,v projections
    dim3 g1(DM/128, NT/128);   // (8,32)
    sgemm_k<0><<<g1, 256>>>(h, wq, nullptr, nullptr, q, NT, DM, DM);
    sgemm_k<0><<<g1, 256>>>(h, wk, nullptr, nullptr, k, NT, DM, DM);
    sgemm_k<0><<<g1, 256>>>(h, wv, nullptr, nullptr, v, NT, DM, DM);

    // 3. per-head SiLU-MLP residual on q and k (in place)
    qk_mlp<<<dim3(NT*NH/16, 2), 256>>>(q, k, qs_w1, qs_b1, qs_w2, qs_b2,
                                        ks_w1, ks_b1, ks_w2, ks_b2);

    // 4. causal attention
    flash_attn<<<dim3(SS/64, NH, BB), 256>>>(q, k, v, attn);

    // 5. output projection + residual into x
    sgemm_k<1><<<g1, 256>>>(attn, wo, nullptr, out, out, NT, DM, DM);

    // 6. hn = rms(x, mlpn_w)
    rmsnorm_k<<<NT, 256>>>(out, mlpn_w, h);

    // 7. gate = silu(hn@gate_w + b) ; y = gate * (hn@fc1_w + b)
    dim3 g2(DFF/128, NT/128);  // (32,32)
    sgemm_k<2><<<g2, 256>>>(h, gate_w, gate_b, nullptr, ff1, NT, DFF, DM);
    sgemm_k<3><<<g2, 256>>>(h, fc1_w,  fc1_b,  ff1,     ff2, NT, DFF, DM);

    // 8. x += y@fc2_w + b
    sgemm_k<4><<<g1, 256>>>(ff2, fc2_w, fc2_b, out, out, NT, DM, DFF);
}

// round 4
// speedup vs baseline: 1.9359x; 1.9275x over previous
#include <cuda_runtime.h>
#include <cuda_bf16.h>
#include <math.h>
#include <stdint.h>

typedef __nv_bfloat16 bf16;

#define BB   2
#define SS_  2048
#define DM   1024
#define NT   (BB*SS_)
#define NH   16
#define HD   64
#define DSTATE 128
#define DFF  4096

// ---------------- device scratch ----------------
__device__ __align__(256) float g_q  [NT*DM];
__device__ __align__(256) float g_k  [NT*DM];
__device__ __align__(256) float g_v  [NT*DM];
__device__ __align__(256) float g_ff1[NT*DFF];
__device__ __align__(256) bf16 g_h_hi[NT*DM],    g_h_lo[NT*DM];
__device__ __align__(256) bf16 g_attn_hi[NT*DM], g_attn_lo[NT*DM];
__device__ __align__(256) bf16 g_ff2_hi[NT*DFF], g_ff2_lo[NT*DFF];
__device__ __align__(256) bf16 g_wqT_hi[DM*DM],  g_wqT_lo[DM*DM];
__device__ __align__(256) bf16 g_wkT_hi[DM*DM],  g_wkT_lo[DM*DM];
__device__ __align__(256) bf16 g_wvT_hi[DM*DM],  g_wvT_lo[DM*DM];
__device__ __align__(256) bf16 g_woT_hi[DM*DM],  g_woT_lo[DM*DM];
__device__ __align__(256) bf16 g_gT_hi[DM*DFF],  g_gT_lo[DM*DFF];
__device__ __align__(256) bf16 g_f1T_hi[DM*DFF], g_f1T_lo[DM*DFF];
__device__ __align__(256) bf16 g_f2T_hi[DFF*DM], g_f2T_lo[DFF*DM];

// ---------------- PTX helpers (family-portable: cp.async / ldmatrix / mma.sync) ----------------
__device__ __forceinline__ uint32_t s2u(const void* p) {
    uint32_t a;
    asm("{ .reg .u64 t; cvta.to.shared.u64 t, %1; cvt.u32.u64 %0, t; }" : "=r"(a) : "l"(p));
    return a;
}
#define CP16(d, s)   asm volatile("cp.async.cg.shared.global [%0], [%1], 16;" :: "r"(d), "l"(s))
#define CP_COMMIT()  asm volatile("cp.async.commit_group;" ::: "memory")
#define CP_WAIT1()   asm volatile("cp.async.wait_group 1;" ::: "memory")

__device__ __forceinline__ void ldm_x4(uint32_t* r, uint32_t addr) {
    asm volatile("ldmatrix.sync.aligned.m8n8.x4.shared.b16 {%0,%1,%2,%3}, [%4];"
        : "=r"(r[0]), "=r"(r[1]), "=r"(r[2]), "=r"(r[3]) : "r"(addr));
}
__device__ __forceinline__ void mma_bf16(float* d, const uint32_t* a, const uint32_t* b) {
    asm volatile("mma.sync.aligned.m16n8k16.row.col.f32.bf16.bf16.f32 "
        "{%0,%1,%2,%3}, {%4,%5,%6,%7}, {%8,%9}, {%0,%1,%2,%3};"
        : "+f"(d[0]), "+f"(d[1]), "+f"(d[2]), "+f"(d[3])
        : "r"(a[0]), "r"(a[1]), "r"(a[2]), "r"(a[3]), "r"(b[0]), "r"(b[1]));
}

// ---------------- misc ----------------
__device__ __forceinline__ float block_sum(float v, float* sbuf) {
    int lane = threadIdx.x & 31, w = threadIdx.x >> 5;
    #pragma unroll
    for (int o = 16; o; o >>= 1) v += __shfl_xor_sync(0xffffffffu, v, o);
    if (lane == 0) sbuf[w] = v;
    __syncthreads();
    if (w == 0) {
        v = (lane < 8) ? sbuf[lane] : 0.f;
        #pragma unroll
        for (int o = 4; o; o >>= 1) v += __shfl_xor_sync(0xffffffffu, v, o);
        if (lane == 0) sbuf[0] = v;
    }
    __syncthreads();
    float r = sbuf[0];
    __syncthreads();
    return r;
}
__device__ __forceinline__ void split_bf16(float x, bf16& h, bf16& l) {
    h = __float2bfloat16(x);
    l = __float2bfloat16(x - __bfloat162float(h));
}

// ---------------- norm kernels ----------------
__global__ __launch_bounds__(256) void norm3_fused(
    const float* __restrict__ x,
    const float* __restrict__ w1, const float* __restrict__ w2, const float* __restrict__ w3,
    float* __restrict__ xout, bf16* __restrict__ h_hi, bf16* __restrict__ h_lo)
{
    __shared__ float sbuf[32];
    const int t = blockIdx.x;
    const int base = threadIdx.x * 4;
    float4 v  = *(const float4*)(x + (size_t)t*DM + base);
    float4 a1 = *(const float4*)(w1 + base);
    float4 a2 = *(const float4*)(w2 + base);
    float4 a3 = *(const float4*)(w3 + base);

    float ss = v.x*v.x + v.y*v.y + v.z*v.z + v.w*v.w;
    float r = rsqrtf(block_sum(ss, sbuf) * (1.f/DM) + 1e-6f);
    v.x += a1.x*v.x*r; v.y += a1.y*v.y*r; v.z += a1.z*v.z*r; v.w += a1.w*v.w*r;

    ss = v.x*v.x + v.y*v.y + v.z*v.z + v.w*v.w;
    r = rsqrtf(block_sum(ss, sbuf) * (1.f/DM) + 1e-6f);
    v.x += a2.x*v.x*r; v.y += a2.y*v.y*r; v.z += a2.z*v.z*r; v.w += a2.w*v.w*r;
    *(float4*)(xout + (size_t)t*DM + base) = v;

    ss = v.x*v.x + v.y*v.y + v.z*v.z + v.w*v.w;
    r = rsqrtf(block_sum(ss, sbuf) * (1.f/DM) + 1e-6f);
    float hv[4] = { a3.x*v.x*r, a3.y*v.y*r, a3.z*v.z*r, a3.w*v.w*r };
    __align__(8) bf16 hh[4], hl[4];
    #pragma unroll
    for (int i = 0; i < 4; i++) split_bf16(hv[i], hh[i], hl[i]);
    *(uint2*)(h_hi + (size_t)t*DM + base) = *(uint2*)hh;
    *(uint2*)(h_lo + (size_t)t*DM + base) = *(uint2*)hl;
}

__global__ __launch_bounds__(256) void rmsnorm_k(
    const float* __restrict__ x, const float* __restrict__ w,
    bf16* __restrict__ o_hi, bf16* __restrict__ o_lo)
{
    __shared__ float sbuf[32];
    const int t = blockIdx.x;
    const int base = threadIdx.x * 4;
    float4 v = *(const float4*)(x + (size_t)t*DM + base);
    float4 a = *(const float4*)(w + base);
    float ss = v.x*v.x + v.y*v.y + v.z*v.z + v.w*v.w;
    float r = rsqrtf(block_sum(ss, sbuf) * (1.f/DM) + 1e-6f);
    float ov[4] = { a.x*v.x*r, a.y*v.y*r, a.z*v.z*r, a.w*v.w*r };
    __align__(8) bf16 hh[4], hl[4];
    #pragma unroll
    for (int i = 0; i < 4; i++) split_bf16(ov[i], hh[i], hl[i]);
    *(uint2*)(o_hi + (size_t)t*DM + base) = *(uint2*)hh;
    *(uint2*)(o_lo + (size_t)t*DM + base) = *(uint2*)hl;
}

// ---------------- weight transpose + split: W[K,N] -> Th/Tl [N,K] ----------------
__global__ __launch_bounds__(256) void wconv(
    const float* __restrict__ W, bf16* __restrict__ Th, bf16* __restrict__ Tl, int K, int N)
{
    __shared__ float t[32][33];
    const int n0 = blockIdx.x*32, k0 = blockIdx.y*32;
    const int tx = threadIdx.x & 31, ty = threadIdx.x >> 5;
    #pragma unroll
    for (int i = ty; i < 32; i += 8)
        t[i][tx] = W[(size_t)(k0 + i)*N + n0 + tx];
    __syncthreads();
    #pragma unroll
    for (int i = ty; i < 32; i += 8) {
        bf16 h, l; split_bf16(t[tx][i], h, l);
        size_t o = (size_t)(n0 + i)*K + k0 + tx;
        Th[o] = h; Tl[o] = l;
    }
}

// ---------------- bf16x3 GEMM via mma.sync: C[M,N] = A[M,K] @ B[N,K]^T ----------------
// 128x128x32 CTA tile, 8 warps (2x4) of 64x32, 3-stage cp.async pipeline.
// EPI: 0 none | 1 +extra | 2 silu(+bias) | 3 (+bias)*extra | 4 +bias+extra
#define GSTAGE 32768                        // Ahi 8K | Alo 8K | Bhi 8K | Blo 8K
#define GSMEM  (3*GSTAGE)

__device__ __forceinline__ uint32_t swz(int row, int chunk) {
    return (uint32_t)(row*64 + ((chunk ^ (row & 3) ^ ((row >> 2) & 1)) << 4));
}

template<int EPI, int OSPLIT>
__global__ __launch_bounds__(256) void gemm_mma(
    const bf16* __restrict__ Ahi, const bf16* __restrict__ Alo,
    const bf16* __restrict__ Bhi, const bf16* __restrict__ Blo,
    const float* __restrict__ bias, const float* __restrict__ extra,
    float* __restrict__ C, bf16* __restrict__ Chi, bf16* __restrict__ Clo,
    int N, int K)
{
    extern __shared__ char smem[];
    const uint32_t sb = s2u(smem);
    const int tid = threadIdx.x;
    const int lane = tid & 31, wid = tid >> 5;
    const int wm = wid >> 2, wn = wid & 3;
    const int row0 = blockIdx.y * 128, col0 = blockIdx.x * 128;
    const int nc = K / 32;

    // ---- load mapping: each thread 8x cp.async of 16B per stage ----
    const int lr = tid >> 1, lc = tid & 1;
    const uint32_t off0 = swz(lr, lc), off1 = swz(lr, lc + 2);
    const bf16* gAh = Ahi + (size_t)(row0 + lr)*K + lc*8;
    const bf16* gAl = Alo + (size_t)(row0 + lr)*K + lc*8;
    const bf16* gBh = Bhi + (size_t)(col0 + lr)*K + lc*8;
    const bf16* gBl = Blo + (size_t)(col0 + lr)*K + lc*8;

    #define GLOAD(st, kc) do { \
        const uint32_t s0 = sb + (uint32_t)(st)*GSTAGE; \
        const int ko = (kc)*32; \
        CP16(s0 +          off0, gAh + ko); CP16(s0 +          off1, gAh + ko + 16); \
        CP16(s0 +  8192 + off0, gAl + ko); CP16(s0 +  8192 + off1, gAl + ko + 16); \
        CP16(s0 + 16384 + off0, gBh + ko); CP16(s0 + 16384 + off1, gBh + ko + 16); \
        CP16(s0 + 24576 + off0, gBl + ko); CP16(s0 + 24576 + off1, gBl + ko + 16); \
    } while (0)

    // ---- fragment address components ----
    const int arow = wm*64 + (lane & 15);
    const int abit = lane >> 4;                              // A chunk half
    const int brow = wn*32 + (lane & 7) + ((lane >> 4) & 1)*8;
    const int bbit = (lane >> 3) & 1;                        // B chunk half

    float acc[4][4][4];
    #pragma unroll
    for (int i = 0; i < 4; i++)
        #pragma unroll
        for (int j = 0; j < 4; j++)
            #pragma unroll
            for (int d2 = 0; d2 < 4; d2++) acc[i][j][d2] = 0.f;

    GLOAD(0, 0); CP_COMMIT();
    GLOAD(1, 1); CP_COMMIT();

    for (int kc = 0; kc < nc; kc++) {
        CP_WAIT1();
        __syncthreads();
        const uint32_t s0 = sb + (uint32_t)(kc % 3)*GSTAGE;
        #pragma unroll
        for (int ks = 0; ks < 2; ks++) {
            uint32_t ah[4][4], al[4][4], bh[2][4], bl[2][4];
            #pragma unroll
            for (int mt = 0; mt < 4; mt++) {
                const uint32_t ao = swz(arow + mt*16, ks*2 + abit);
                ldm_x4(ah[mt], s0 + ao);
                ldm_x4(al[mt], s0 + 8192 + ao);
            }
            #pragma unroll
            for (int n2 = 0; n2 < 2; n2++) {
                const uint32_t bo = swz(brow + n2*16, ks*2 + bbit);
                ldm_x4(bh[n2], s0 + 16384 + bo);
                ldm_x4(bl[n2], s0 + 24576 + bo);
            }
            #pragma unroll
            for (int mt = 0; mt < 4; mt++)
                #pragma unroll
                for (int nt = 0; nt < 4; nt++) {
                    const uint32_t* ph = &bh[nt >> 1][(nt & 1)*2];
                    const uint32_t* pl = &bl[nt >> 1][(nt & 1)*2];
                    mma_bf16(acc[mt][nt], ah[mt], ph);
                    mma_bf16(acc[mt][nt], ah[mt], pl);
                    mma_bf16(acc[mt][nt], al[mt], ph);
                }
        }
        if (kc + 2 < nc) GLOAD((kc + 2) % 3, kc + 2);
        CP_COMMIT();
    }
    #undef GLOAD

    // ---- epilogue ----
    const int erow = lane >> 2;
    const int ecol = (lane & 3)*2;
    #pragma unroll
    for (int mt = 0; mt < 4; mt++)
        #pragma unroll
        for (int hf = 0; hf < 2; hf++) {
            const int row = row0 + wm*64 + mt*16 + erow + hf*8;
            #pragma unroll
            for (int nt = 0; nt < 4; nt++) {
                const int col = col0 + wn*32 + nt*8 + ecol;
                float v0 = acc[mt][nt][hf*2 + 0];
                float v1 = acc[mt][nt][hf*2 + 1];
                const size_t ro = (size_t)row * N + col;
                if (EPI == 1) { float2 e = *(const float2*)(extra + ro); v0 += e.x; v1 += e.y; }
                if (EPI == 2) {
                    v0 += bias[col]; v1 += bias[col + 1];
                    v0 = v0 / (1.f + __expf(-v0)); v1 = v1 / (1.f + __expf(-v1));
                }
                if (EPI == 3) {
                    v0 += bias[col]; v1 += bias[col + 1];
                    float2 e = *(const float2*)(extra + ro); v0 *= e.x; v1 *= e.y;
                }
                if (EPI == 4) {
                    float2 e = *(const float2*)(extra + ro);
                    v0 += bias[col] + e.x; v1 += bias[col + 1] + e.y;
                }
                if (OSPLIT) {
                    bf16 h0, l0, h1, l1;
                    split_bf16(v0, h0, l0); split_bf16(v1, h1, l1);
                    uint32_t ph = ((uint32_t)__bfloat16_as_ushort(h1) << 16) | __bfloat16_as_ushort(h0);
                    uint32_t pl = ((uint32_t)__bfloat16_as_ushort(l1) << 16) | __bfloat16_as_ushort(l0);
                    *(uint32_t*)(Chi + ro) = ph;
                    *(uint32_t*)(Clo + ro) = pl;
                } else {
                    float2 o; o.x = v0; o.y = v1;
                    *(float2*)(C + ro) = o;
                }
            }
        }
}

// ---------------- qk silu-mlp residual, 32 rows/block, register tiled ----------------
#define QK_SMEM ((8192 + 8192 + 32*65 + 32*129) * 4)
__global__ __launch_bounds__(256) void qk_mlp(
    float* __restrict__ qbuf, float* __restrict__ kbuf,
    const float* __restrict__ qw1, const float* __restrict__ qb1,
    const float* __restrict__ qw2, const float* __restrict__ qb2,
    const float* __restrict__ kw1, const float* __restrict__ kb1,
    const float* __restrict__ kw2, const float* __restrict__ kb2)
{
    extern __shared__ float sm[];
    float* sw1  = sm;
    float* sw2  = sm + 8192;
    float* sx   = sm + 16384;
    float* shid = sm + 16384 + 32*65;
    const int tid = threadIdx.x;
    float* data     = blockIdx.y ? kbuf : qbuf;
    const float* w1 = blockIdx.y ? kw1 : qw1;
    const float* b1 = blockIdx.y ? kb1 : qb1;
    const float* w2 = blockIdx.y ? kw2 : qw2;
    const float* b2 = blockIdx.y ? kb2 : qb2;

    for (int i = tid; i < 8192; i += 256) { sw1[i] = w1[i]; sw2[i] = w2[i]; }
    float* xb = data + (size_t)blockIdx.x * (32*HD);
    for (int i = tid; i < 32*HD; i += 256) sx[(i >> 6)*65 + (i & 63)] = xb[i];
    __syncthreads();

    const int rg = tid & 15, cg = tid >> 4;
    {
        const int r0 = rg*2, j0 = cg*8;
        float acc[2][8];
        #pragma unroll
        for (int j = 0; j < 8; j++) { float bv = b1[j0+j]; acc[0][j] = bv; acc[1][j] = bv; }
        #pragma unroll 8
        for (int d = 0; d < 64; d++) {
            const float x0 = sx[r0*65 + d], x1 = sx[r0*65 + 65 + d];
            const float* wr = sw1 + d*128 + j0;
            #pragma unroll
            for (int j = 0; j < 8; j++) { const float wv = wr[j]; acc[0][j] += x0*wv; acc[1][j] += x1*wv; }
        }
        #pragma unroll
        for (int rr = 0; rr < 2; rr++)
            #pragma unroll
            for (int j = 0; j < 8; j++) {
                const float s = acc[rr][j];
                shid[(r0+rr)*129 + j0 + j] = s / (1.f + __expf(-s));
            }
    }
    __syncthreads();
    {
        const int r0 = rg*2, j0 = cg*4;
        float acc[2][4];
        #pragma unroll
        for (int j = 0; j < 4; j++) { float bv = b2[j0+j]; acc[0][j] = bv; acc[1][j] = bv; }
        #pragma unroll 4
        for (int d = 0; d < 128; d++) {
            const float h0 = shid[r0*129 + d], h1 = shid[r0*129 + 129 + d];
            const float* wr = sw2 + d*64 + j0;
            #pragma unroll
            for (int j = 0; j < 4; j++) { const float wv = wr[j]; acc[0][j] += h0*wv; acc[1][j] += h1*wv; }
        }
        #pragma unroll
        for (int rr = 0; rr < 2; rr++) {
            float4 o;
            o.x = acc[rr][0] + sx[(r0+rr)*65 + j0 + 0];
            o.y = acc[rr][1] + sx[(r0+rr)*65 + j0 + 1];
            o.z = acc[rr][2] + sx[(r0+rr)*65 + j0 + 2];
            o.w = acc[rr][3] + sx[(r0+rr)*65 + j0 + 3];
            *(float4*)(xb + (r0+rr)*64 + j0) = o;
        }
    }
}

// ---------------- causal flash attention (fp32), hi/lo bf16 output ----------------
__global__ __launch_bounds__(256) void flash_attn(
    const float* __restrict__ Q, const float* __restrict__ K,
    const float* __restrict__ V, bf16* __restrict__ Ohi, bf16* __restrict__ Olo)
{
    const int qt = blockIdx.x;
    const int h  = blockIdx.y;
    const int b  = blockIdx.z;
    __shared__ float Qs[64][65];
    __shared__ float Ks[32][65];
    __shared__ float Vt[64][33];
    __shared__ float Ps[64][33];

    const int tid = threadIdx.x;
    const int ty = tid >> 3;
    const int tx = tid & 7;
    const int r0 = 2*ty;

    const size_t qbase = ((size_t)(b*SS_ + qt*64)*NH + h)*HD;
    for (int i = tid; i < 64*16; i += 256) {
        const int r = i >> 4, c4 = (i & 15)*4;
        float4 qv = *(const float4*)(Q + qbase + (size_t)r*DM + c4);
        Qs[r][c4] = qv.x; Qs[r][c4+1] = qv.y; Qs[r][c4+2] = qv.z; Qs[r][c4+3] = qv.w;
    }

    float m[2] = {-1e30f, -1e30f}, l[2] = {0.f, 0.f};
    float accO[2][8];
    #pragma unroll
    for (int rr = 0; rr < 2; rr++)
        #pragma unroll
        for (int dd = 0; dd < 8; dd++) accO[rr][dd] = 0.f;

    const int nk = 2*qt + 2;
    for (int kj = 0; kj < nk; kj++) {
        __syncthreads();
        const size_t kbase = ((size_t)(b*SS_ + kj*32)*NH + h)*HD;
        for (int i = tid; i < 32*16; i += 256) {
            const int c = i >> 4, d4 = (i & 15)*4;
            float4 kv = *(const float4*)(K + kbase + (size_t)c*DM + d4);
            Ks[c][d4] = kv.x; Ks[c][d4+1] = kv.y; Ks[c][d4+2] = kv.z; Ks[c][d4+3] = kv.w;
            float4 vv = *(const float4*)(V + kbase + (size_t)c*DM + d4);
            Vt[d4][c] = vv.x; Vt[d4+1][c] = vv.y; Vt[d4+2][c] = vv.z; Vt[d4+3][c] = vv.w;
        }
        __syncthreads();

        float s[2][4];
        #pragma unroll
        for (int rr = 0; rr < 2; rr++)
            #pragma unroll
            for (int cc = 0; cc < 4; cc++) s[rr][cc] = 0.f;
        #pragma unroll 4
        for (int d = 0; d < HD; d++) {
            const float q0 = Qs[r0][d], q1 = Qs[r0+1][d];
            #pragma unroll
            for (int cc = 0; cc < 4; cc++) {
                const float kv = Ks[tx*4 + cc][d];
                s[0][cc] += q0*kv;
                s[1][cc] += q1*kv;
            }
        }
        const bool need_mask = (kj*32 + 31 > qt*64);
        #pragma unroll
        for (int rr = 0; rr < 2; rr++)
            #pragma unroll
            for (int cc = 0; cc < 4; cc++) {
                s[rr][cc] *= 0.125f;
                if (need_mask && (kj*32 + tx*4 + cc > qt*64 + r0 + rr)) s[rr][cc] = -1e30f;
            }
        #pragma unroll
        for (int rr = 0; rr < 2; rr++) {
            float mx = fmaxf(fmaxf(s[rr][0], s[rr][1]), fmaxf(s[rr][2], s[rr][3]));
            #pragma unroll
            for (int o = 1; o < 8; o <<= 1) mx = fmaxf(mx, __shfl_xor_sync(0xffffffffu, mx, o));
            const float mn = fmaxf(m[rr], mx);
            const float alpha = __expf(m[rr] - mn);
            float sum = 0.f;
            #pragma unroll
            for (int cc = 0; cc < 4; cc++) {
                const float p = __expf(s[rr][cc] - mn);
                Ps[r0+rr][tx*4 + cc] = p;
                sum += p;
            }
            #pragma unroll
            for (int o = 1; o < 8; o <<= 1) sum += __shfl_xor_sync(0xffffffffu, sum, o);
            l[rr] = l[rr]*alpha + sum;
            m[rr] = mn;
            #pragma unroll
            for (int dd = 0; dd < 8; dd++) accO[rr][dd] *= alpha;
        }
        __syncthreads();
        const int d0 = tx*8;
        #pragma unroll 4
        for (int c = 0; c < 32; c++) {
            const float p0 = Ps[r0][c], p1 = Ps[r0+1][c];
            #pragma unroll
            for (int dd = 0; dd < 8; dd++) {
                const float vv = Vt[d0+dd][c];
                accO[0][dd] += p0*vv;
                accO[1][dd] += p1*vv;
            }
        }
    }

    #pragma unroll
    for (int rr = 0; rr < 2; rr++) {
        const float inv = 1.f / l[rr];
        const size_t ro = ((size_t)(b*SS_ + qt*64 + r0 + rr)*NH + h)*HD + tx*8;
        __align__(16) bf16 hv[8], lv[8];
        #pragma unroll
        for (int dd = 0; dd < 8; dd++) split_bf16(accO[rr][dd]*inv, hv[dd], lv[dd]);
        *(uint4*)(Ohi + ro) = *(uint4*)hv;
        *(uint4*)(Olo + ro) = *(uint4*)lv;
    }
}

// ---------------- launcher ----------------
extern "C" void kernel_launch(void* const* d_in, const int* in_sizes, int n_in,
                              void* d_out, int out_size)
{
    const float* x       = (const float*)d_in[0];
    const float* norm1_w = (const float*)d_in[2];
    const float* norm2_w = (const float*)d_in[3];
    const float* norm3_w = (const float*)d_in[4];
    const float* mlpn_w  = (const float*)d_in[5];
    const float* wq      = (const float*)d_in[6];
    const float* wk      = (const float*)d_in[7];
    const float* wv      = (const float*)d_in[8];
    const float* wo      = (const float*)d_in[9];
    const float* qs_w1   = (const float*)d_in[10];
    const float* qs_b1   = (const float*)d_in[11];
    const float* qs_w2   = (const float*)d_in[12];
    const float* qs_b2   = (const float*)d_in[13];
    const float* ks_w1   = (const float*)d_in[14];
    const float* ks_b1   = (const float*)d_in[15];
    const float* ks_w2   = (const float*)d_in[16];
    const float* ks_b2   = (const float*)d_in[17];
    const float* fc1_w   = (const float*)d_in[18];
    const float* fc1_b   = (const float*)d_in[19];
    const float* fc2_w   = (const float*)d_in[20];
    const float* fc2_b   = (const float*)d_in[21];
    const float* gate_w  = (const float*)d_in[22];
    const float* gate_b  = (const float*)d_in[23];
    float* out = (float*)d_out;

    float *q, *k, *v, *ff1;
    bf16 *hh, *hl, *ah, *al, *f2h, *f2l;
    bf16 *wqh, *wql, *wkh, *wkl, *wvh, *wvl, *woh, *wol, *gh, *gl, *f1h, *f1l, *fch, *fcl;
    cudaGetSymbolAddress((void**)&q,   g_q);
    cudaGetSymbolAddress((void**)&k,   g_k);
    cudaGetSymbolAddress((void**)&v,   g_v);
    cudaGetSymbolAddress((void**)&ff1, g_ff1);
    cudaGetSymbolAddress((void**)&hh,  g_h_hi);    cudaGetSymbolAddress((void**)&hl,  g_h_lo);
    cudaGetSymbolAddress((void**)&ah,  g_attn_hi); cudaGetSymbolAddress((void**)&al,  g_attn_lo);
    cudaGetSymbolAddress((void**)&f2h, g_ff2_hi);  cudaGetSymbolAddress((void**)&f2l, g_ff2_lo);
    cudaGetSymbolAddress((void**)&wqh, g_wqT_hi);  cudaGetSymbolAddress((void**)&wql, g_wqT_lo);
    cudaGetSymbolAddress((void**)&wkh, g_wkT_hi);  cudaGetSymbolAddress((void**)&wkl, g_wkT_lo);
    cudaGetSymbolAddress((void**)&wvh, g_wvT_hi);  cudaGetSymbolAddress((void**)&wvl, g_wvT_lo);
    cudaGetSymbolAddress((void**)&woh, g_woT_hi);  cudaGetSymbolAddress((void**)&wol, g_woT_lo);
    cudaGetSymbolAddress((void**)&gh,  g_gT_hi);   cudaGetSymbolAddress((void**)&gl,  g_gT_lo);
    cudaGetSymbolAddress((void**)&f1h, g_f1T_hi);  cudaGetSymbolAddress((void**)&f1l, g_f1T_lo);
    cudaGetSymbolAddress((void**)&fch, g_f2T_hi);  cudaGetSymbolAddress((void**)&fcl, g_f2T_lo);

    cudaFuncSetAttribute(gemm_mma<0,0>, cudaFuncAttributeMaxDynamicSharedMemorySize, GSMEM);
    cudaFuncSetAttribute(gemm_mma<1,0>, cudaFuncAttributeMaxDynamicSharedMemorySize, GSMEM);
    cudaFuncSetAttribute(gemm_mma<2,0>, cudaFuncAttributeMaxDynamicSharedMemorySize, GSMEM);
    cudaFuncSetAttribute(gemm_mma<3,1>, cudaFuncAttributeMaxDynamicSharedMemorySize, GSMEM);
    cudaFuncSetAttribute(gemm_mma<4,0>, cudaFuncAttributeMaxDynamicSharedMemorySize, GSMEM);
    cudaFuncSetAttribute(qk_mlp, cudaFuncAttributeMaxDynamicSharedMemorySize, QK_SMEM);

    // weight convert (transpose + bf16 split)
    wconv<<<dim3(DM/32, DM/32),  256>>>(wq,     wqh, wql, DM,  DM);
    wconv<<<dim3(DM/32, DM/32),  256>>>(wk,     wkh, wkl, DM,  DM);
    wconv<<<dim3(DM/32, DM/32),  256>>>(wv,     wvh, wvl, DM,  DM);
    wconv<<<dim3(DM/32, DM/32),  256>>>(wo,     woh, wol, DM,  DM);
    wconv<<<dim3(DFF/32, DM/32), 256>>>(gate_w, gh,  gl,  DM,  DFF);
    wconv<<<dim3(DFF/32, DM/32), 256>>>(fc1_w,  f1h, f1l, DM,  DFF);
    wconv<<<dim3(DM/32, DFF/32), 256>>>(fc2_w,  fch, fcl, DFF, DM);

    // 1. mamba stages + pre-attn norm
    norm3_fused<<<NT, 256>>>(x, norm1_w, norm2_w, norm3_w, out, hh, hl);

    // 2. q,k,v projections (tensor cores)
    dim3 g1(DM/128, NT/128);
    gemm_mma<0,0><<<g1, 256, GSMEM>>>(hh, hl, wqh, wql, nullptr, nullptr, q, nullptr, nullptr, DM, DM);
    gemm_mma<0,0><<<g1, 256, GSMEM>>>(hh, hl, wkh, wkl, nullptr, nullptr, k, nullptr, nullptr, DM, DM);
    gemm_mma<0,0><<<g1, 256, GSMEM>>>(hh, hl, wvh, wvl, nullptr, nullptr, v, nullptr, nullptr, DM, DM);

    // 3. per-head SiLU-MLP residual
    qk_mlp<<<dim3(NT*NH/32, 2), 256, QK_SMEM>>>(q, k, qs_w1, qs_b1, qs_w2, qs_b2,
                                                 ks_w1, ks_b1, ks_w2, ks_b2);

    // 4. causal attention -> hi/lo
    flash_attn<<<dim3(SS_/64, NH, BB), 256>>>(q, k, v, ah, al);

    // 5. out projection + residual
    gemm_mma<1,0><<<g1, 256, GSMEM>>>(ah, al, woh, wol, nullptr, out, out, nullptr, nullptr, DM, DM);

    // 6. mlp norm
    rmsnorm_k<<<NT, 256>>>(out, mlpn_w, hh, hl);

    // 7. gate & fc1 (fc1 writes bf16 hi/lo for fc2)
    dim3 g2(DFF/128, NT/128);
    gemm_mma<2,0><<<g2, 256, GSMEM>>>(hh, hl, gh, gl, gate_b, nullptr, ff1, nullptr, nullptr, DFF, DM);
    gemm_mma<3,1><<<g2, 256, GSMEM>>>(hh, hl, f1h, f1l, fc1_b, ff1, nullptr, f2h, f2l, DFF, DM);

    // 8. fc2 + residual
    gemm_mma<4,0><<<g1, 256, GSMEM>>>(f2h, f2l, fch, fcl, fc2_b, out, out, nullptr, nullptr, DM, DFF);
}

// round 5
// speedup vs baseline: 1.9608x; 1.0129x over previous
#include <cuda_runtime.h>
#include <cuda_bf16.h>
#include <math.h>
#include <stdint.h>

typedef __nv_bfloat16 bf16;

#define BB   2
#define SS_  2048
#define DM   1024
#define NT   (BB*SS_)
#define NH   16
#define HD   64
#define DSTATE 128
#define DFF  4096

// ---------------- device scratch ----------------
__device__ __align__(256) float g_q  [NT*DM];
__device__ __align__(256) float g_k  [NT*DM];
__device__ __align__(256) float g_v  [NT*DM];
__device__ __align__(256) float g_ff1[NT*DFF];
__device__ __align__(256) bf16 g_h_hi[NT*DM],    g_h_lo[NT*DM];
__device__ __align__(256) bf16 g_attn_hi[NT*DM], g_attn_lo[NT*DM];
__device__ __align__(256) bf16 g_ff2_hi[NT*DFF], g_ff2_lo[NT*DFF];
__device__ __align__(256) bf16 g_wqT_hi[DM*DM],  g_wqT_lo[DM*DM];
__device__ __align__(256) bf16 g_wkT_hi[DM*DM],  g_wkT_lo[DM*DM];
__device__ __align__(256) bf16 g_wvT_hi[DM*DM],  g_wvT_lo[DM*DM];
__device__ __align__(256) bf16 g_woT_hi[DM*DM],  g_woT_lo[DM*DM];
__device__ __align__(256) bf16 g_gT_hi[DM*DFF],  g_gT_lo[DM*DFF];
__device__ __align__(256) bf16 g_f1T_hi[DM*DFF], g_f1T_lo[DM*DFF];
__device__ __align__(256) bf16 g_f2T_hi[DFF*DM], g_f2T_lo[DFF*DM];

// ---------------- PTX helpers (family-portable) ----------------
__device__ __forceinline__ uint32_t s2u(const void* p) {
    uint32_t a;
    asm("{ .reg .u64 t; cvta.to.shared.u64 t, %1; cvt.u32.u64 %0, t; }" : "=r"(a) : "l"(p));
    return a;
}
#define CP16(d, s)   asm volatile("cp.async.cg.shared.global [%0], [%1], 16;" :: "r"(d), "l"(s))
#define CP_COMMIT()  asm volatile("cp.async.commit_group;" ::: "memory")
#define CP_WAIT1()   asm volatile("cp.async.wait_group 1;" ::: "memory")

__device__ __forceinline__ void ldm_x4(uint32_t* r, uint32_t addr) {
    asm volatile("ldmatrix.sync.aligned.m8n8.x4.shared.b16 {%0,%1,%2,%3}, [%4];"
        : "=r"(r[0]), "=r"(r[1]), "=r"(r[2]), "=r"(r[3]) : "r"(addr));
}
__device__ __forceinline__ void mma_bf16(float* d, const uint32_t* a, const uint32_t* b) {
    asm volatile("mma.sync.aligned.m16n8k16.row.col.f32.bf16.bf16.f32 "
        "{%0,%1,%2,%3}, {%4,%5,%6,%7}, {%8,%9}, {%0,%1,%2,%3};"
        : "+f"(d[0]), "+f"(d[1]), "+f"(d[2]), "+f"(d[3])
        : "r"(a[0]), "r"(a[1]), "r"(a[2]), "r"(a[3]), "r"(b[0]), "r"(b[1]));
}

// ---------------- misc ----------------
__device__ __forceinline__ float block_sum(float v, float* sbuf) {
    int lane = threadIdx.x & 31, w = threadIdx.x >> 5;
    #pragma unroll
    for (int o = 16; o; o >>= 1) v += __shfl_xor_sync(0xffffffffu, v, o);
    if (lane == 0) sbuf[w] = v;
    __syncthreads();
    if (w == 0) {
        v = (lane < 8) ? sbuf[lane] : 0.f;
        #pragma unroll
        for (int o = 4; o; o >>= 1) v += __shfl_xor_sync(0xffffffffu, v, o);
        if (lane == 0) sbuf[0] = v;
    }
    __syncthreads();
    float r = sbuf[0];
    __syncthreads();
    return r;
}
__device__ __forceinline__ void split_bf16(float x, bf16& h, bf16& l) {
    h = __float2bfloat16(x);
    l = __float2bfloat16(x - __bfloat162float(h));
}
__device__ __forceinline__ uint32_t pk(bf16 a, bf16 b) {
    return ((uint32_t)__bfloat16_as_ushort(b) << 16) | __bfloat16_as_ushort(a);
}

// ---------------- norm kernels ----------------
__global__ __launch_bounds__(256) void norm3_fused(
    const float* __restrict__ x,
    const float* __restrict__ w1, const float* __restrict__ w2, const float* __restrict__ w3,
    float* __restrict__ xout, bf16* __restrict__ h_hi, bf16* __restrict__ h_lo)
{
    __shared__ float sbuf[32];
    const int t = blockIdx.x;
    const int base = threadIdx.x * 4;
    float4 v  = *(const float4*)(x + (size_t)t*DM + base);
    float4 a1 = *(const float4*)(w1 + base);
    float4 a2 = *(const float4*)(w2 + base);
    float4 a3 = *(const float4*)(w3 + base);

    float ss = v.x*v.x + v.y*v.y + v.z*v.z + v.w*v.w;
    float r = rsqrtf(block_sum(ss, sbuf) * (1.f/DM) + 1e-6f);
    v.x += a1.x*v.x*r; v.y += a1.y*v.y*r; v.z += a1.z*v.z*r; v.w += a1.w*v.w*r;

    ss = v.x*v.x + v.y*v.y + v.z*v.z + v.w*v.w;
    r = rsqrtf(block_sum(ss, sbuf) * (1.f/DM) + 1e-6f);
    v.x += a2.x*v.x*r; v.y += a2.y*v.y*r; v.z += a2.z*v.z*r; v.w += a2.w*v.w*r;
    *(float4*)(xout + (size_t)t*DM + base) = v;

    ss = v.x*v.x + v.y*v.y + v.z*v.z + v.w*v.w;
    r = rsqrtf(block_sum(ss, sbuf) * (1.f/DM) + 1e-6f);
    float hv[4] = { a3.x*v.x*r, a3.y*v.y*r, a3.z*v.z*r, a3.w*v.w*r };
    __align__(8) bf16 hh[4], hl[4];
    #pragma unroll
    for (int i = 0; i < 4; i++) split_bf16(hv[i], hh[i], hl[i]);
    *(uint2*)(h_hi + (size_t)t*DM + base) = *(uint2*)hh;
    *(uint2*)(h_lo + (size_t)t*DM + base) = *(uint2*)hl;
}

__global__ __launch_bounds__(256) void rmsnorm_k(
    const float* __restrict__ x, const float* __restrict__ w,
    bf16* __restrict__ o_hi, bf16* __restrict__ o_lo)
{
    __shared__ float sbuf[32];
    const int t = blockIdx.x;
    const int base = threadIdx.x * 4;
    float4 v = *(const float4*)(x + (size_t)t*DM + base);
    float4 a = *(const float4*)(w + base);
    float ss = v.x*v.x + v.y*v.y + v.z*v.z + v.w*v.w;
    float r = rsqrtf(block_sum(ss, sbuf) * (1.f/DM) + 1e-6f);
    float ov[4] = { a.x*v.x*r, a.y*v.y*r, a.z*v.z*r, a.w*v.w*r };
    __align__(8) bf16 hh[4], hl[4];
    #pragma unroll
    for (int i = 0; i < 4; i++) split_bf16(ov[i], hh[i], hl[i]);
    *(uint2*)(o_hi + (size_t)t*DM + base) = *(uint2*)hh;
    *(uint2*)(o_lo + (size_t)t*DM + base) = *(uint2*)hl;
}

// ---------------- weight transpose + split, 64x64 tiles: W[K,N] -> Th/Tl [N,K] ----------------
__global__ __launch_bounds__(256) void wconv64(
    const float* __restrict__ W, bf16* __restrict__ Th, bf16* __restrict__ Tl, int K, int N)
{
    __shared__ float t[64][65];
    const int n0 = blockIdx.x*64, k0 = blockIdx.y*64;
    const int tid = threadIdx.x;
    {
        const int r = tid >> 2, c0 = (tid & 3) * 16;
        const float* src = W + (size_t)(k0 + r)*N + n0 + c0;
        #pragma unroll
        for (int j = 0; j < 4; j++) {
            float4 vv = *(const float4*)(src + j*4);
            t[r][c0 + j*4 + 0] = vv.x; t[r][c0 + j*4 + 1] = vv.y;
            t[r][c0 + j*4 + 2] = vv.z; t[r][c0 + j*4 + 3] = vv.w;
        }
    }
    __syncthreads();
    {
        const int n = tid >> 2, ks = (tid & 3) * 16;
        uint32_t ph[8], pl[8];
        #pragma unroll
        for (int j = 0; j < 8; j++) {
            float a = t[ks + j*2][n], c = t[ks + j*2 + 1][n];
            bf16 ha, la, hc, lc;
            split_bf16(a, ha, la); split_bf16(c, hc, lc);
            ph[j] = pk(ha, hc); pl[j] = pk(la, lc);
        }
        const size_t ou = ((size_t)(n0 + n)*K + k0 + ks) >> 1;   // u32 units
        uint32_t* dh = (uint32_t*)Th + ou;
        uint32_t* dl = (uint32_t*)Tl + ou;
        *(uint4*)(dh)     = make_uint4(ph[0], ph[1], ph[2], ph[3]);
        *(uint4*)(dh + 4) = make_uint4(ph[4], ph[5], ph[6], ph[7]);
        *(uint4*)(dl)     = make_uint4(pl[0], pl[1], pl[2], pl[3]);
        *(uint4*)(dl + 4) = make_uint4(pl[4], pl[5], pl[6], pl[7]);
    }
}

// ---------------- bf16x3 GEMM via mma.sync: C[M,N] = A[M,K] @ B[N,K]^T ----------------
#define GSTAGE 32768
#define GSMEM  (3*GSTAGE)

__device__ __forceinline__ uint32_t swz(int row, int chunk) {
    return (uint32_t)(row*64 + ((chunk ^ (row & 3) ^ ((row >> 2) & 1)) << 4));
}

template<int EPI, int OSPLIT>
__global__ __launch_bounds__(256) void gemm_mma(
    const bf16* __restrict__ Ahi, const bf16* __restrict__ Alo,
    const bf16* __restrict__ Bhi, const bf16* __restrict__ Blo,
    const float* __restrict__ bias, const float* __restrict__ extra,
    float* __restrict__ C, bf16* __restrict__ Chi, bf16* __restrict__ Clo,
    int N, int K)
{
    extern __shared__ char smem[];
    const uint32_t sb = s2u(smem);
    const int tid = threadIdx.x;
    const int lane = tid & 31, wid = tid >> 5;
    const int wm = wid >> 2, wn = wid & 3;
    const int row0 = blockIdx.y * 128, col0 = blockIdx.x * 128;
    const int nc = K / 32;

    const int lr = tid >> 1, lc = tid & 1;
    const uint32_t off0 = swz(lr, lc), off1 = swz(lr, lc + 2);
    const bf16* gAh = Ahi + (size_t)(row0 + lr)*K + lc*8;
    const bf16* gAl = Alo + (size_t)(row0 + lr)*K + lc*8;
    const bf16* gBh = Bhi + (size_t)(col0 + lr)*K + lc*8;
    const bf16* gBl = Blo + (size_t)(col0 + lr)*K + lc*8;

    #define GLOAD(st, kc) do { \
        const uint32_t s0 = sb + (uint32_t)(st)*GSTAGE; \
        const int ko = (kc)*32; \
        CP16(s0 +          off0, gAh + ko); CP16(s0 +          off1, gAh + ko + 16); \
        CP16(s0 +  8192 + off0, gAl + ko); CP16(s0 +  8192 + off1, gAl + ko + 16); \
        CP16(s0 + 16384 + off0, gBh + ko); CP16(s0 + 16384 + off1, gBh + ko + 16); \
        CP16(s0 + 24576 + off0, gBl + ko); CP16(s0 + 24576 + off1, gBl + ko + 16); \
    } while (0)

    const int arow = wm*64 + (lane & 15);
    const int abit = lane >> 4;
    const int brow = wn*32 + (lane & 7) + ((lane >> 4) & 1)*8;
    const int bbit = (lane >> 3) & 1;

    float acc[4][4][4];
    #pragma unroll
    for (int i = 0; i < 4; i++)
        #pragma unroll
        for (int j = 0; j < 4; j++)
            #pragma unroll
            for (int d2 = 0; d2 < 4; d2++) acc[i][j][d2] = 0.f;

    GLOAD(0, 0); CP_COMMIT();
    GLOAD(1, 1); CP_COMMIT();

    for (int kc = 0; kc < nc; kc++) {
        CP_WAIT1();
        __syncthreads();
        const uint32_t s0 = sb + (uint32_t)(kc % 3)*GSTAGE;
        #pragma unroll
        for (int ks = 0; ks < 2; ks++) {
            uint32_t ah[4][4], al[4][4], bh[2][4], bl[2][4];
            #pragma unroll
            for (int mt = 0; mt < 4; mt++) {
                const uint32_t ao = swz(arow + mt*16, ks*2 + abit);
                ldm_x4(ah[mt], s0 + ao);
                ldm_x4(al[mt], s0 + 8192 + ao);
            }
            #pragma unroll
            for (int n2 = 0; n2 < 2; n2++) {
                const uint32_t bo = swz(brow + n2*16, ks*2 + bbit);
                ldm_x4(bh[n2], s0 + 16384 + bo);
                ldm_x4(bl[n2], s0 + 24576 + bo);
            }
            #pragma unroll
            for (int mt = 0; mt < 4; mt++)
                #pragma unroll
                for (int nt = 0; nt < 4; nt++) {
                    const uint32_t* ph = &bh[nt >> 1][(nt & 1)*2];
                    const uint32_t* pl = &bl[nt >> 1][(nt & 1)*2];
                    mma_bf16(acc[mt][nt], ah[mt], ph);
                    mma_bf16(acc[mt][nt], ah[mt], pl);
                    mma_bf16(acc[mt][nt], al[mt], ph);
                }
        }
        if (kc + 2 < nc) GLOAD((kc + 2) % 3, kc + 2);
        CP_COMMIT();
    }
    #undef GLOAD

    const int erow = lane >> 2;
    const int ecol = (lane & 3)*2;
    #pragma unroll
    for (int mt = 0; mt < 4; mt++)
        #pragma unroll
        for (int hf = 0; hf < 2; hf++) {
            const int row = row0 + wm*64 + mt*16 + erow + hf*8;
            #pragma unroll
            for (int nt = 0; nt < 4; nt++) {
                const int col = col0 + wn*32 + nt*8 + ecol;
                float v0 = acc[mt][nt][hf*2 + 0];
                float v1 = acc[mt][nt][hf*2 + 1];
                const size_t ro = (size_t)row * N + col;
                if (EPI == 1) { float2 e = *(const float2*)(extra + ro); v0 += e.x; v1 += e.y; }
                if (EPI == 2) {
                    v0 += bias[col]; v1 += bias[col + 1];
                    v0 = v0 / (1.f + __expf(-v0)); v1 = v1 / (1.f + __expf(-v1));
                }
                if (EPI == 3) {
                    v0 += bias[col]; v1 += bias[col + 1];
                    float2 e = *(const float2*)(extra + ro); v0 *= e.x; v1 *= e.y;
                }
                if (EPI == 4) {
                    float2 e = *(const float2*)(extra + ro);
                    v0 += bias[col] + e.x; v1 += bias[col + 1] + e.y;
                }
                if (OSPLIT) {
                    bf16 h0, l0, h1, l1;
                    split_bf16(v0, h0, l0); split_bf16(v1, h1, l1);
                    *(uint32_t*)(Chi + ro) = pk(h0, h1);
                    *(uint32_t*)(Clo + ro) = pk(l0, l1);
                } else {
                    float2 o; o.x = v0; o.y = v1;
                    *(float2*)(C + ro) = o;
                }
            }
        }
}

// ---------------- qk silu-mlp residual ----------------
#define QK_SMEM ((8192 + 8192 + 32*65 + 32*129) * 4)
__global__ __launch_bounds__(256) void qk_mlp(
    float* __restrict__ qbuf, float* __restrict__ kbuf,
    const float* __restrict__ qw1, const float* __restrict__ qb1,
    const float* __restrict__ qw2, const float* __restrict__ qb2,
    const float* __restrict__ kw1, const float* __restrict__ kb1,
    const float* __restrict__ kw2, const float* __restrict__ kb2)
{
    extern __shared__ float sm[];
    float* sw1  = sm;
    float* sw2  = sm + 8192;
    float* sx   = sm + 16384;
    float* shid = sm + 16384 + 32*65;
    const int tid = threadIdx.x;
    float* data     = blockIdx.y ? kbuf : qbuf;
    const float* w1 = blockIdx.y ? kw1 : qw1;
    const float* b1 = blockIdx.y ? kb1 : qb1;
    const float* w2 = blockIdx.y ? kw2 : qw2;
    const float* b2 = blockIdx.y ? kb2 : qb2;

    for (int i = tid; i < 8192; i += 256) { sw1[i] = w1[i]; sw2[i] = w2[i]; }
    float* xb = data + (size_t)blockIdx.x * (32*HD);
    for (int i = tid; i < 32*HD; i += 256) sx[(i >> 6)*65 + (i & 63)] = xb[i];
    __syncthreads();

    const int rg = tid & 15, cg = tid >> 4;
    {
        const int r0 = rg*2, j0 = cg*8;
        float acc[2][8];
        #pragma unroll
        for (int j = 0; j < 8; j++) { float bv = b1[j0+j]; acc[0][j] = bv; acc[1][j] = bv; }
        #pragma unroll 8
        for (int d = 0; d < 64; d++) {
            const float x0 = sx[r0*65 + d], x1 = sx[r0*65 + 65 + d];
            const float* wr = sw1 + d*128 + j0;
            #pragma unroll
            for (int j = 0; j < 8; j++) { const float wv = wr[j]; acc[0][j] += x0*wv; acc[1][j] += x1*wv; }
        }
        #pragma unroll
        for (int rr = 0; rr < 2; rr++)
            #pragma unroll
            for (int j = 0; j < 8; j++) {
                const float s = acc[rr][j];
                shid[(r0+rr)*129 + j0 + j] = s / (1.f + __expf(-s));
            }
    }
    __syncthreads();
    {
        const int r0 = rg*2, j0 = cg*4;
        float acc[2][4];
        #pragma unroll
        for (int j = 0; j < 4; j++) { float bv = b2[j0+j]; acc[0][j] = bv; acc[1][j] = bv; }
        #pragma unroll 4
        for (int d = 0; d < 128; d++) {
            const float h0 = shid[r0*129 + d], h1 = shid[r0*129 + 129 + d];
            const float* wr = sw2 + d*64 + j0;
            #pragma unroll
            for (int j = 0; j < 4; j++) { const float wv = wr[j]; acc[0][j] += h0*wv; acc[1][j] += h1*wv; }
        }
        #pragma unroll
        for (int rr = 0; rr < 2; rr++) {
            float4 o;
            o.x = acc[rr][0] + sx[(r0+rr)*65 + j0 + 0];
            o.y = acc[rr][1] + sx[(r0+rr)*65 + j0 + 1];
            o.z = acc[rr][2] + sx[(r0+rr)*65 + j0 + 2];
            o.w = acc[rr][3] + sx[(r0+rr)*65 + j0 + 3];
            *(float4*)(xb + (r0+rr)*64 + j0) = o;
        }
    }
}

// ---------------- tensor-core causal flash attention (bf16x3) ----------------
// 128 q-rows x 64 k-cols per iter, 8 warps x 16 q-rows. Padded 72-elem rows in smem.
#define FA_QH 0u
#define FA_QL 18432u
#define FA_KH 36864u
#define FA_KL 46080u
#define FA_VH 55296u
#define FA_VL 64512u
#define FA_SMEM 73728

__global__ __launch_bounds__(256) void flash_mma(
    const float* __restrict__ Q, const float* __restrict__ K,
    const float* __restrict__ V, bf16* __restrict__ Ohi, bf16* __restrict__ Olo)
{
    extern __shared__ char sm_[];
    const uint32_t sb = s2u(sm_);
    const int tid = threadIdx.x;
    const int lane = tid & 31, wid = tid >> 5;
    const int qt = blockIdx.x, h = blockIdx.y, b = blockIdx.z;
    const int qb = qt * 128;
    const int m0 = wid * 16;

    // ---- Q tile -> smem bf16 hi/lo ----
    {
        const int r = tid >> 1;
        const int half = tid & 1;
        const float* Qg = Q + ((size_t)(b*SS_ + qb + r)*NH + h)*HD + half*32;
        char* dst = sm_ + FA_QH + r*144 + half*64;
        char* dstl = sm_ + FA_QL + r*144 + half*64;
        #pragma unroll
        for (int j = 0; j < 8; j++) {
            float4 qv = *(const float4*)(Qg + j*4);
            bf16 h0,l0,h1,l1,h2,l2,h3,l3;
            split_bf16(qv.x,h0,l0); split_bf16(qv.y,h1,l1);
            split_bf16(qv.z,h2,l2); split_bf16(qv.w,h3,l3);
            *(uint32_t*)(dst  + j*8)     = pk(h0,h1);
            *(uint32_t*)(dst  + j*8 + 4) = pk(h2,h3);
            *(uint32_t*)(dstl + j*8)     = pk(l0,l1);
            *(uint32_t*)(dstl + j*8 + 4) = pk(l2,l3);
        }
    }

    float mstate[2] = {-1e30f, -1e30f};
    float lsum[2]   = {0.f, 0.f};
    float o[8][4];
    #pragma unroll
    for (int i = 0; i < 8; i++)
        #pragma unroll
        for (int e = 0; e < 4; e++) o[i][e] = 0.f;

    const int nk = 2*qt + 2;
    for (int kj = 0; kj < nk; kj++) {
        __syncthreads();
        // ---- K,V tile -> smem (V transposed) ----
        {
            const int r = tid >> 2;
            const int dbase = (tid & 3) * 16;
            const size_t gb = ((size_t)(b*SS_ + kj*64 + r)*NH + h)*HD + dbase;
            const float* Kg = K + gb;
            const float* Vg = V + gb;
            #pragma unroll
            for (int j = 0; j < 4; j++) {
                float4 kv = *(const float4*)(Kg + j*4);
                bf16 h0,l0,h1,l1,h2,l2,h3,l3;
                split_bf16(kv.x,h0,l0); split_bf16(kv.y,h1,l1);
                split_bf16(kv.z,h2,l2); split_bf16(kv.w,h3,l3);
                const uint32_t ko = r*144 + (dbase + j*4)*2;
                *(uint32_t*)(sm_ + FA_KH + ko)     = pk(h0,h1);
                *(uint32_t*)(sm_ + FA_KH + ko + 4) = pk(h2,h3);
                *(uint32_t*)(sm_ + FA_KL + ko)     = pk(l0,l1);
                *(uint32_t*)(sm_ + FA_KL + ko + 4) = pk(l2,l3);

                float4 vv = *(const float4*)(Vg + j*4);
                bf16 vh[4], vl[4];
                split_bf16(vv.x,vh[0],vl[0]); split_bf16(vv.y,vh[1],vl[1]);
                split_bf16(vv.z,vh[2],vl[2]); split_bf16(vv.w,vh[3],vl[3]);
                #pragma unroll
                for (int t = 0; t < 4; t++) {
                    const int d = dbase + j*4 + t;
                    *(bf16*)(sm_ + FA_VH + d*144 + r*2) = vh[t];
                    *(bf16*)(sm_ + FA_VL + d*144 + r*2) = vl[t];
                }
            }
        }
        __syncthreads();

        // warps whose entire 16-row block is above the diagonal for this k tile: skip compute
        if (kj*64 > qb + m0 + 15) continue;

        // ---- S = Q K^T (bf16x3) ----
        float s[8][4];
        #pragma unroll
        for (int i = 0; i < 8; i++)
            #pragma unroll
            for (int e = 0; e < 4; e++) s[i][e] = 0.f;

        #pragma unroll
        for (int ks = 0; ks < 4; ks++) {
            uint32_t qh4[4], ql4[4];
            const uint32_t ao = (uint32_t)((m0 + (lane & 15))*144 + ks*32 + (lane >> 4)*16);
            ldm_x4(qh4, sb + FA_QH + ao);
            ldm_x4(ql4, sb + FA_QL + ao);
            #pragma unroll
            for (int n2 = 0; n2 < 4; n2++) {
                uint32_t kh4[4], kl4[4];
                const uint32_t bo = (uint32_t)((n2*16 + (lane & 7) + ((lane >> 4) & 1)*8)*144
                                               + ks*32 + ((lane >> 3) & 1)*16);
                ldm_x4(kh4, sb + FA_KH + bo);
                ldm_x4(kl4, sb + FA_KL + bo);
                mma_bf16(s[n2*2],   qh4, &kh4[0]);
                mma_bf16(s[n2*2],   qh4, &kl4[0]);
                mma_bf16(s[n2*2],   ql4, &kh4[0]);
                mma_bf16(s[n2*2+1], qh4, &kh4[2]);
                mma_bf16(s[n2*2+1], qh4, &kl4[2]);
                mma_bf16(s[n2*2+1], ql4, &kh4[2]);
            }
        }

        // ---- scale + causal mask ----
        const bool need_mask = (kj*64 + 63 > qb + m0);
        #pragma unroll
        for (int nt = 0; nt < 8; nt++)
            #pragma unroll
            for (int e = 0; e < 4; e++) {
                float val = s[nt][e] * 0.125f;
                if (need_mask) {
                    const int col = kj*64 + nt*8 + (lane & 3)*2 + (e & 1);
                    const int row = qb + m0 + (lane >> 2) + (e >> 1)*8;
                    if (col > row) val = -1e30f;
                }
                s[nt][e] = val;
            }

        // ---- online softmax (quad reduction) ----
        float mx[2] = {-1e30f, -1e30f};
        #pragma unroll
        for (int nt = 0; nt < 8; nt++) {
            mx[0] = fmaxf(mx[0], fmaxf(s[nt][0], s[nt][1]));
            mx[1] = fmaxf(mx[1], fmaxf(s[nt][2], s[nt][3]));
        }
        #pragma unroll
        for (int hf = 0; hf < 2; hf++) {
            mx[hf] = fmaxf(mx[hf], __shfl_xor_sync(0xffffffffu, mx[hf], 1));
            mx[hf] = fmaxf(mx[hf], __shfl_xor_sync(0xffffffffu, mx[hf], 2));
        }
        float al2[2];
        #pragma unroll
        for (int hf = 0; hf < 2; hf++) {
            const float mn = fmaxf(fmaxf(mstate[hf], mx[hf]), -1e20f);
            al2[hf] = __expf(mstate[hf] - mn);
            mstate[hf] = mn;
        }
        float sum[2] = {0.f, 0.f};
        #pragma unroll
        for (int nt = 0; nt < 8; nt++)
            #pragma unroll
            for (int e = 0; e < 4; e++) {
                const float p = __expf(s[nt][e] - mstate[e >> 1]);
                s[nt][e] = p;
                sum[e >> 1] += p;
            }
        #pragma unroll
        for (int hf = 0; hf < 2; hf++) {
            sum[hf] += __shfl_xor_sync(0xffffffffu, sum[hf], 1);
            sum[hf] += __shfl_xor_sync(0xffffffffu, sum[hf], 2);
            lsum[hf] = lsum[hf]*al2[hf] + sum[hf];
        }
        #pragma unroll
        for (int nt = 0; nt < 8; nt++)
            #pragma unroll
            for (int e = 0; e < 4; e++) o[nt][e] *= al2[e >> 1];

        // ---- O += P V (bf16x3; C-frag -> A-frag identity) ----
        #pragma unroll
        for (int ks2 = 0; ks2 < 4; ks2++) {
            uint32_t pah[4], pal[4];
            {
                bf16 h0,l0,h1,l1;
                split_bf16(s[2*ks2][0],h0,l0);   split_bf16(s[2*ks2][1],h1,l1);
                pah[0] = pk(h0,h1); pal[0] = pk(l0,l1);
                split_bf16(s[2*ks2][2],h0,l0);   split_bf16(s[2*ks2][3],h1,l1);
                pah[1] = pk(h0,h1); pal[1] = pk(l0,l1);
                split_bf16(s[2*ks2+1][0],h0,l0); split_bf16(s[2*ks2+1][1],h1,l1);
                pah[2] = pk(h0,h1); pal[2] = pk(l0,l1);
                split_bf16(s[2*ks2+1][2],h0,l0); split_bf16(s[2*ks2+1][3],h1,l1);
                pah[3] = pk(h0,h1); pal[3] = pk(l0,l1);
            }
            #pragma unroll
            for (int dn2 = 0; dn2 < 4; dn2++) {
                uint32_t vh4[4], vl4[4];
                const uint32_t bo = (uint32_t)((dn2*16 + (lane & 7) + ((lane >> 4) & 1)*8)*144
                                               + ks2*32 + ((lane >> 3) & 1)*16);
                ldm_x4(vh4, sb + FA_VH + bo);
                ldm_x4(vl4, sb + FA_VL + bo);
                mma_bf16(o[dn2*2],   pah, &vh4[0]);
                mma_bf16(o[dn2*2],   pah, &vl4[0]);
                mma_bf16(o[dn2*2],   pal, &vh4[0]);
                mma_bf16(o[dn2*2+1], pah, &vh4[2]);
                mma_bf16(o[dn2*2+1], pah, &vl4[2]);
                mma_bf16(o[dn2*2+1], pal, &vh4[2]);
            }
        }
    }

    // ---- epilogue: normalize, split, store ----
    const float inv0 = 1.f / lsum[0];
    const float inv1 = 1.f / lsum[1];
    #pragma unroll
    for (int nt = 0; nt < 8; nt++)
        #pragma unroll
        for (int hf = 0; hf < 2; hf++) {
            const float inv = hf ? inv1 : inv0;
            const float v0 = o[nt][hf*2 + 0] * inv;
            const float v1 = o[nt][hf*2 + 1] * inv;
            bf16 h0, l0, h1, l1;
            split_bf16(v0, h0, l0); split_bf16(v1, h1, l1);
            const int row = qb + m0 + (lane >> 2) + hf*8;
            const int d0 = nt*8 + (lane & 3)*2;
            const size_t ro = ((size_t)(b*SS_ + row)*NH + h)*HD + d0;
            *(uint32_t*)(Ohi + ro) = pk(h0, h1);
            *(uint32_t*)(Olo + ro) = pk(l0, l1);
        }
}

// ---------------- launcher ----------------
extern "C" void kernel_launch(void* const* d_in, const int* in_sizes, int n_in,
                              void* d_out, int out_size)
{
    const float* x       = (const float*)d_in[0];
    const float* norm1_w = (const float*)d_in[2];
    const float* norm2_w = (const float*)d_in[3];
    const float* norm3_w = (const float*)d_in[4];
    const float* mlpn_w  = (const float*)d_in[5];
    const float* wq      = (const float*)d_in[6];
    const float* wk      = (const float*)d_in[7];
    const float* wv      = (const float*)d_in[8];
    const float* wo      = (const float*)d_in[9];
    const float* qs_w1   = (const float*)d_in[10];
    const float* qs_b1   = (const float*)d_in[11];
    const float* qs_w2   = (const float*)d_in[12];
    const float* qs_b2   = (const float*)d_in[13];
    const float* ks_w1   = (const float*)d_in[14];
    const float* ks_b1   = (const float*)d_in[15];
    const float* ks_w2   = (const float*)d_in[16];
    const float* ks_b2   = (const float*)d_in[17];
    const float* fc1_w   = (const float*)d_in[18];
    const float* fc1_b   = (const float*)d_in[19];
    const float* fc2_w   = (const float*)d_in[20];
    const float* fc2_b   = (const float*)d_in[21];
    const float* gate_w  = (const float*)d_in[22];
    const float* gate_b  = (const float*)d_in[23];
    float* out = (float*)d_out;

    float *q, *k, *v, *ff1;
    bf16 *hh, *hl, *ah, *al, *f2h, *f2l;
    bf16 *wqh, *wql, *wkh, *wkl, *wvh, *wvl, *woh, *wol, *gh, *gl, *f1h, *f1l, *fch, *fcl;
    cudaGetSymbolAddress((void**)&q,   g_q);
    cudaGetSymbolAddress((void**)&k,   g_k);
    cudaGetSymbolAddress((void**)&v,   g_v);
    cudaGetSymbolAddress((void**)&ff1, g_ff1);
    cudaGetSymbolAddress((void**)&hh,  g_h_hi);    cudaGetSymbolAddress((void**)&hl,  g_h_lo);
    cudaGetSymbolAddress((void**)&ah,  g_attn_hi); cudaGetSymbolAddress((void**)&al,  g_attn_lo);
    cudaGetSymbolAddress((void**)&f2h, g_ff2_hi);  cudaGetSymbolAddress((void**)&f2l, g_ff2_lo);
    cudaGetSymbolAddress((void**)&wqh, g_wqT_hi);  cudaGetSymbolAddress((void**)&wql, g_wqT_lo);
    cudaGetSymbolAddress((void**)&wkh, g_wkT_hi);  cudaGetSymbolAddress((void**)&wkl, g_wkT_lo);
    cudaGetSymbolAddress((void**)&wvh, g_wvT_hi);  cudaGetSymbolAddress((void**)&wvl, g_wvT_lo);
    cudaGetSymbolAddress((void**)&woh, g_woT_hi);  cudaGetSymbolAddress((void**)&wol, g_woT_lo);
    cudaGetSymbolAddress((void**)&gh,  g_gT_hi);   cudaGetSymbolAddress((void**)&gl,  g_gT_lo);
    cudaGetSymbolAddress((void**)&f1h, g_f1T_hi);  cudaGetSymbolAddress((void**)&f1l, g_f1T_lo);
    cudaGetSymbolAddress((void**)&fch, g_f2T_hi);  cudaGetSymbolAddress((void**)&fcl, g_f2T_lo);

    cudaFuncSetAttribute(gemm_mma<0,0>, cudaFuncAttributeMaxDynamicSharedMemorySize, GSMEM);
    cudaFuncSetAttribute(gemm_mma<1,0>, cudaFuncAttributeMaxDynamicSharedMemorySize, GSMEM);
    cudaFuncSetAttribute(gemm_mma<2,0>, cudaFuncAttributeMaxDynamicSharedMemorySize, GSMEM);
    cudaFuncSetAttribute(gemm_mma<3,1>, cudaFuncAttributeMaxDynamicSharedMemorySize, GSMEM);
    cudaFuncSetAttribute(gemm_mma<4,0>, cudaFuncAttributeMaxDynamicSharedMemorySize, GSMEM);
    cudaFuncSetAttribute(qk_mlp, cudaFuncAttributeMaxDynamicSharedMemorySize, QK_SMEM);
    cudaFuncSetAttribute(flash_mma, cudaFuncAttributeMaxDynamicSharedMemorySize, FA_SMEM);

    // weight convert (transpose + bf16 split)
    wconv64<<<dim3(DM/64, DM/64),  256>>>(wq,     wqh, wql, DM,  DM);
    wconv64<<<dim3(DM/64, DM/64),  256>>>(wk,     wkh, wkl, DM,  DM);
    wconv64<<<dim3(DM/64, DM/64),  256>>>(wv,     wvh, wvl, DM,  DM);
    wconv64<<<dim3(DM/64, DM/64),  256>>>(wo,     woh, wol, DM,  DM);
    wconv64<<<dim3(DFF/64, DM/64), 256>>>(gate_w, gh,  gl,  DM,  DFF);
    wconv64<<<dim3(DFF/64, DM/64), 256>>>(fc1_w,  f1h, f1l, DM,  DFF);
    wconv64<<<dim3(DM/64, DFF/64), 256>>>(fc2_w,  fch, fcl, DFF, DM);

    // 1. mamba stages + pre-attn norm
    norm3_fused<<<NT, 256>>>(x, norm1_w, norm2_w, norm3_w, out, hh, hl);

    // 2. q,k,v projections
    dim3 g1(DM/128, NT/128);
    gemm_mma<0,0><<<g1, 256, GSMEM>>>(hh, hl, wqh, wql, nullptr, nullptr, q, nullptr, nullptr, DM, DM);
    gemm_mma<0,0><<<g1, 256, GSMEM>>>(hh, hl, wkh, wkl, nullptr, nullptr, k, nullptr, nullptr, DM, DM);
    gemm_mma<0,0><<<g1, 256, GSMEM>>>(hh, hl, wvh, wvl, nullptr, nullptr, v, nullptr, nullptr, DM, DM);

    // 3. per-head SiLU-MLP residual
    qk_mlp<<<dim3(NT*NH/32, 2), 256, QK_SMEM>>>(q, k, qs_w1, qs_b1, qs_w2, qs_b2,
                                                 ks_w1, ks_b1, ks_w2, ks_b2);

    // 4. causal attention (tensor cores) -> hi/lo
    flash_mma<<<dim3(SS_/128, NH, BB), 256, FA_SMEM>>>(q, k, v, ah, al);

    // 5. out projection + residual
    gemm_mma<1,0><<<g1, 256, GSMEM>>>(ah, al, woh, wol, nullptr, out, out, nullptr, nullptr, DM, DM);

    // 6. mlp norm
    rmsnorm_k<<<NT, 256>>>(out, mlpn_w, hh, hl);

    // 7. gate & fc1
    dim3 g2(DFF/128, NT/128);
    gemm_mma<2,0><<<g2, 256, GSMEM>>>(hh, hl, gh, gl, gate_b, nullptr, ff1, nullptr, nullptr, DFF, DM);
    gemm_mma<3,1><<<g2, 256, GSMEM>>>(hh, hl, f1h, f1l, fc1_b, ff1, nullptr, f2h, f2l, DFF, DM);

    // 8. fc2 + residual
    gemm_mma<4,0><<<g1, 256, GSMEM>>>(f2h, f2l, fch, fcl, fc2_b, out, out, nullptr, nullptr, DM, DFF);
}

// round 6
// speedup vs baseline: 3.0345x; 1.5476x over previous
#include <cuda_runtime.h>
#include <cuda_bf16.h>
#include <math.h>
#include <stdint.h>

typedef __nv_bfloat16 bf16;

#define BB   2
#define SS_  2048
#define DM   1024
#define NT   (BB*SS_)
#define NH   16
#define HD   64
#define DSTATE 128
#define DFF  4096

// ---------------- device scratch ----------------
__device__ __align__(256) float g_ff1[NT*DFF];
__device__ __align__(256) bf16 g_q_hi[NT*DM],    g_q_lo[NT*DM];
__device__ __align__(256) bf16 g_k_hi[NT*DM],    g_k_lo[NT*DM];
__device__ __align__(256) bf16 g_v_hi[NT*DM],    g_v_lo[NT*DM];
__device__ __align__(256) bf16 g_h_hi[NT*DM],    g_h_lo[NT*DM];
__device__ __align__(256) bf16 g_attn_hi[NT*DM], g_attn_lo[NT*DM];
__device__ __align__(256) bf16 g_ff2_hi[NT*DFF], g_ff2_lo[NT*DFF];
__device__ __align__(256) bf16 g_wqT_hi[DM*DM],  g_wqT_lo[DM*DM];
__device__ __align__(256) bf16 g_wkT_hi[DM*DM],  g_wkT_lo[DM*DM];
__device__ __align__(256) bf16 g_wvT_hi[DM*DM],  g_wvT_lo[DM*DM];
__device__ __align__(256) bf16 g_woT_hi[DM*DM],  g_woT_lo[DM*DM];
__device__ __align__(256) bf16 g_gT_hi[DM*DFF],  g_gT_lo[DM*DFF];
__device__ __align__(256) bf16 g_f1T_hi[DM*DFF], g_f1T_lo[DM*DFF];
__device__ __align__(256) bf16 g_f2T_hi[DFF*DM], g_f2T_lo[DFF*DM];

// ---------------- PTX helpers (family-portable) ----------------
__device__ __forceinline__ uint32_t s2u(const void* p) {
    uint32_t a;
    asm("{ .reg .u64 t; cvta.to.shared.u64 t, %1; cvt.u32.u64 %0, t; }" : "=r"(a) : "l"(p));
    return a;
}
#define CP16(d, s)   asm volatile("cp.async.cg.shared.global [%0], [%1], 16;" :: "r"(d), "l"(s))
#define CP_COMMIT()  asm volatile("cp.async.commit_group;" ::: "memory")
#define CP_WAIT1()   asm volatile("cp.async.wait_group 1;" ::: "memory")

__device__ __forceinline__ void ldm_x4(uint32_t* r, uint32_t addr) {
    asm volatile("ldmatrix.sync.aligned.m8n8.x4.shared.b16 {%0,%1,%2,%3}, [%4];"
        : "=r"(r[0]), "=r"(r[1]), "=r"(r[2]), "=r"(r[3]) : "r"(addr));
}
__device__ __forceinline__ void mma_bf16(float* d, const uint32_t* a, const uint32_t* b) {
    asm volatile("mma.sync.aligned.m16n8k16.row.col.f32.bf16.bf16.f32 "
        "{%0,%1,%2,%3}, {%4,%5,%6,%7}, {%8,%9}, {%0,%1,%2,%3};"
        : "+f"(d[0]), "+f"(d[1]), "+f"(d[2]), "+f"(d[3])
        : "r"(a[0]), "r"(a[1]), "r"(a[2]), "r"(a[3]), "r"(b[0]), "r"(b[1]));
}

// ---------------- misc ----------------
__device__ __forceinline__ float block_sum(float v, float* sbuf) {
    int lane = threadIdx.x & 31, w = threadIdx.x >> 5;
    #pragma unroll
    for (int o = 16; o; o >>= 1) v += __shfl_xor_sync(0xffffffffu, v, o);
    if (lane == 0) sbuf[w] = v;
    __syncthreads();
    if (w == 0) {
        v = (lane < 8) ? sbuf[lane] : 0.f;
        #pragma unroll
        for (int o = 4; o; o >>= 1) v += __shfl_xor_sync(0xffffffffu, v, o);
        if (lane == 0) sbuf[0] = v;
    }
    __syncthreads();
    float r = sbuf[0];
    __syncthreads();
    return r;
}
__device__ __forceinline__ void split_bf16(float x, bf16& h, bf16& l) {
    h = __float2bfloat16(x);
    l = __float2bfloat16(x - __bfloat162float(h));
}
__device__ __forceinline__ uint32_t pk(bf16 a, bf16 b) {
    return ((uint32_t)__bfloat16_as_ushort(b) << 16) | __bfloat16_as_ushort(a);
}

// ---------------- norm kernels ----------------
__global__ __launch_bounds__(256) void norm3_fused(
    const float* __restrict__ x,
    const float* __restrict__ w1, const float* __restrict__ w2, const float* __restrict__ w3,
    float* __restrict__ xout, bf16* __restrict__ h_hi, bf16* __restrict__ h_lo)
{
    __shared__ float sbuf[32];
    const int t = blockIdx.x;
    const int base = threadIdx.x * 4;
    float4 v  = *(const float4*)(x + (size_t)t*DM + base);
    float4 a1 = *(const float4*)(w1 + base);
    float4 a2 = *(const float4*)(w2 + base);
    float4 a3 = *(const float4*)(w3 + base);

    float ss = v.x*v.x + v.y*v.y + v.z*v.z + v.w*v.w;
    float r = rsqrtf(block_sum(ss, sbuf) * (1.f/DM) + 1e-6f);
    v.x += a1.x*v.x*r; v.y += a1.y*v.y*r; v.z += a1.z*v.z*r; v.w += a1.w*v.w*r;

    ss = v.x*v.x + v.y*v.y + v.z*v.z + v.w*v.w;
    r = rsqrtf(block_sum(ss, sbuf) * (1.f/DM) + 1e-6f);
    v.x += a2.x*v.x*r; v.y += a2.y*v.y*r; v.z += a2.z*v.z*r; v.w += a2.w*v.w*r;
    *(float4*)(xout + (size_t)t*DM + base) = v;

    ss = v.x*v.x + v.y*v.y + v.z*v.z + v.w*v.w;
    r = rsqrtf(block_sum(ss, sbuf) * (1.f/DM) + 1e-6f);
    float hv[4] = { a3.x*v.x*r, a3.y*v.y*r, a3.z*v.z*r, a3.w*v.w*r };
    __align__(8) bf16 hh[4], hl[4];
    #pragma unroll
    for (int i = 0; i < 4; i++) split_bf16(hv[i], hh[i], hl[i]);
    *(uint2*)(h_hi + (size_t)t*DM + base) = *(uint2*)hh;
    *(uint2*)(h_lo + (size_t)t*DM + base) = *(uint2*)hl;
}

__global__ __launch_bounds__(256) void rmsnorm_k(
    const float* __restrict__ x, const float* __restrict__ w,
    bf16* __restrict__ o_hi, bf16* __restrict__ o_lo)
{
    __shared__ float sbuf[32];
    const int t = blockIdx.x;
    const int base = threadIdx.x * 4;
    float4 v = *(const float4*)(x + (size_t)t*DM + base);
    float4 a = *(const float4*)(w + base);
    float ss = v.x*v.x + v.y*v.y + v.z*v.z + v.w*v.w;
    float r = rsqrtf(block_sum(ss, sbuf) * (1.f/DM) + 1e-6f);
    float ov[4] = { a.x*v.x*r, a.y*v.y*r, a.z*v.z*r, a.w*v.w*r };
    __align__(8) bf16 hh[4], hl[4];
    #pragma unroll
    for (int i = 0; i < 4; i++) split_bf16(ov[i], hh[i], hl[i]);
    *(uint2*)(o_hi + (size_t)t*DM + base) = *(uint2*)hh;
    *(uint2*)(o_lo + (size_t)t*DM + base) = *(uint2*)hl;
}

// ---------------- fused weight transpose + split (single launch) ----------------
struct WAll {
    const float* src[7];
    bf16* th[7];
    bf16* tl[7];
};

__global__ __launch_bounds__(256) void wconv_all(WAll wa)
{
    __shared__ float t[64][65];
    const int id = blockIdx.x;
    int m, tbase;
    if (id < 1024)      { m = id >> 8; tbase = m << 8; }
    else if (id < 2048) { m = 4; tbase = 1024; }
    else if (id < 3072) { m = 5; tbase = 2048; }
    else                { m = 6; tbase = 3072; }
    const int K = (m == 6) ? DFF : DM;
    const int N = (m == 4 || m == 5) ? DFF : DM;
    const int tt = id - tbase;
    const int ntx = N / 64;
    const int n0 = (tt % ntx) * 64, k0 = (tt / ntx) * 64;
    const float* W = wa.src[m];
    bf16* Th = wa.th[m];
    bf16* Tl = wa.tl[m];

    const int tid = threadIdx.x;
    {
        const int r = tid >> 2, c0 = (tid & 3) * 16;
        const float* src = W + (size_t)(k0 + r)*N + n0 + c0;
        #pragma unroll
        for (int j = 0; j < 4; j++) {
            float4 vv = *(const float4*)(src + j*4);
            t[r][c0 + j*4 + 0] = vv.x; t[r][c0 + j*4 + 1] = vv.y;
            t[r][c0 + j*4 + 2] = vv.z; t[r][c0 + j*4 + 3] = vv.w;
        }
    }
    __syncthreads();
    {
        const int n = tid >> 2, ks = (tid & 3) * 16;
        uint32_t ph[8], pl[8];
        #pragma unroll
        for (int j = 0; j < 8; j++) {
            float a = t[ks + j*2][n], c = t[ks + j*2 + 1][n];
            bf16 ha, la, hc, lc;
            split_bf16(a, ha, la); split_bf16(c, hc, lc);
            ph[j] = pk(ha, hc); pl[j] = pk(la, lc);
        }
        const size_t ou = ((size_t)(n0 + n)*K + k0 + ks) >> 1;
        uint32_t* dh = (uint32_t*)Th + ou;
        uint32_t* dl = (uint32_t*)Tl + ou;
        *(uint4*)(dh)     = make_uint4(ph[0], ph[1], ph[2], ph[3]);
        *(uint4*)(dh + 4) = make_uint4(ph[4], ph[5], ph[6], ph[7]);
        *(uint4*)(dl)     = make_uint4(pl[0], pl[1], pl[2], pl[3]);
        *(uint4*)(dl + 4) = make_uint4(pl[4], pl[5], pl[6], pl[7]);
    }
}

// ---------------- bf16x3 GEMM via mma.sync: C[M,N] = A[M,K] @ B[N,K]^T ----------------
#define GSTAGE 32768
#define GSMEM  (3*GSTAGE)

__device__ __forceinline__ uint32_t swz(int row, int chunk) {
    return (uint32_t)(row*64 + ((chunk ^ (row & 3) ^ ((row >> 2) & 1)) << 4));
}

template<int EPI, int OSPLIT>
__global__ __launch_bounds__(256) void gemm_mma(
    const bf16* __restrict__ Ahi, const bf16* __restrict__ Alo,
    const bf16* __restrict__ Bhi, const bf16* __restrict__ Blo,
    const float* __restrict__ bias, const float* __restrict__ extra,
    float* __restrict__ C, bf16* __restrict__ Chi, bf16* __restrict__ Clo,
    int N, int K)
{
    extern __shared__ char smem[];
    const uint32_t sb = s2u(smem);
    const int tid = threadIdx.x;
    const int lane = tid & 31, wid = tid >> 5;
    const int wm = wid >> 2, wn = wid & 3;
    const int row0 = blockIdx.y * 128, col0 = blockIdx.x * 128;
    const int nc = K / 32;

    const int lr = tid >> 1, lc = tid & 1;
    const uint32_t off0 = swz(lr, lc), off1 = swz(lr, lc + 2);
    const bf16* gAh = Ahi + (size_t)(row0 + lr)*K + lc*8;
    const bf16* gAl = Alo + (size_t)(row0 + lr)*K + lc*8;
    const bf16* gBh = Bhi + (size_t)(col0 + lr)*K + lc*8;
    const bf16* gBl = Blo + (size_t)(col0 + lr)*K + lc*8;

    #define GLOAD(st, kc) do { \
        const uint32_t s0 = sb + (uint32_t)(st)*GSTAGE; \
        const int ko = (kc)*32; \
        CP16(s0 +          off0, gAh + ko); CP16(s0 +          off1, gAh + ko + 16); \
        CP16(s0 +  8192 + off0, gAl + ko); CP16(s0 +  8192 + off1, gAl + ko + 16); \
        CP16(s0 + 16384 + off0, gBh + ko); CP16(s0 + 16384 + off1, gBh + ko + 16); \
        CP16(s0 + 24576 + off0, gBl + ko); CP16(s0 + 24576 + off1, gBl + ko + 16); \
    } while (0)

    const int arow = wm*64 + (lane & 15);
    const int abit = lane >> 4;
    const int brow = wn*32 + (lane & 7) + ((lane >> 4) & 1)*8;
    const int bbit = (lane >> 3) & 1;

    float acc[4][4][4];
    #pragma unroll
    for (int i = 0; i < 4; i++)
        #pragma unroll
        for (int j = 0; j < 4; j++)
            #pragma unroll
            for (int d2 = 0; d2 < 4; d2++) acc[i][j][d2] = 0.f;

    GLOAD(0, 0); CP_COMMIT();
    GLOAD(1, 1); CP_COMMIT();

    for (int kc = 0; kc < nc; kc++) {
        CP_WAIT1();
        __syncthreads();
        const uint32_t s0 = sb + (uint32_t)(kc % 3)*GSTAGE;
        #pragma unroll
        for (int ks = 0; ks < 2; ks++) {
            uint32_t ah[4][4], al[4][4], bh[2][4], bl[2][4];
            #pragma unroll
            for (int mt = 0; mt < 4; mt++) {
                const uint32_t ao = swz(arow + mt*16, ks*2 + abit);
                ldm_x4(ah[mt], s0 + ao);
                ldm_x4(al[mt], s0 + 8192 + ao);
            }
            #pragma unroll
            for (int n2 = 0; n2 < 2; n2++) {
                const uint32_t bo = swz(brow + n2*16, ks*2 + bbit);
                ldm_x4(bh[n2], s0 + 16384 + bo);
                ldm_x4(bl[n2], s0 + 24576 + bo);
            }
            #pragma unroll
            for (int mt = 0; mt < 4; mt++)
                #pragma unroll
                for (int nt = 0; nt < 4; nt++) {
                    const uint32_t* ph = &bh[nt >> 1][(nt & 1)*2];
                    const uint32_t* pl = &bl[nt >> 1][(nt & 1)*2];
                    mma_bf16(acc[mt][nt], ah[mt], ph);
                    mma_bf16(acc[mt][nt], ah[mt], pl);
                    mma_bf16(acc[mt][nt], al[mt], ph);
                }
        }
        if (kc + 2 < nc) GLOAD((kc + 2) % 3, kc + 2);
        CP_COMMIT();
    }
    #undef GLOAD

    const int erow = lane >> 2;
    const int ecol = (lane & 3)*2;
    #pragma unroll
    for (int mt = 0; mt < 4; mt++)
        #pragma unroll
        for (int hf = 0; hf < 2; hf++) {
            const int row = row0 + wm*64 + mt*16 + erow + hf*8;
            #pragma unroll
            for (int nt = 0; nt < 4; nt++) {
                const int col = col0 + wn*32 + nt*8 + ecol;
                float v0 = acc[mt][nt][hf*2 + 0];
                float v1 = acc[mt][nt][hf*2 + 1];
                const size_t ro = (size_t)row * N + col;
                if (EPI == 1) { float2 e = *(const float2*)(extra + ro); v0 += e.x; v1 += e.y; }
                if (EPI == 2) {
                    v0 += bias[col]; v1 += bias[col + 1];
                    v0 = v0 / (1.f + __expf(-v0)); v1 = v1 / (1.f + __expf(-v1));
                }
                if (EPI == 3) {
                    v0 += bias[col]; v1 += bias[col + 1];
                    float2 e = *(const float2*)(extra + ro); v0 *= e.x; v1 *= e.y;
                }
                if (EPI == 4) {
                    float2 e = *(const float2*)(extra + ro);
                    v0 += bias[col] + e.x; v1 += bias[col + 1] + e.y;
                }
                if (OSPLIT) {
                    bf16 h0, l0, h1, l1;
                    split_bf16(v0, h0, l0); split_bf16(v1, h1, l1);
                    *(uint32_t*)(Chi + ro) = pk(h0, h1);
                    *(uint32_t*)(Clo + ro) = pk(l0, l1);
                } else {
                    float2 o; o.x = v0; o.y = v1;
                    *(float2*)(C + ro) = o;
                }
            }
        }
}

// ---------------- qk silu-mlp residual (bf16 hi/lo in-place) ----------------
#define QK_SMEM ((8192 + 8192 + 32*65 + 32*129) * 4)
__global__ __launch_bounds__(256) void qk_mlp(
    bf16* __restrict__ qh, bf16* __restrict__ ql,
    bf16* __restrict__ kh, bf16* __restrict__ kl,
    const float* __restrict__ qw1, const float* __restrict__ qb1,
    const float* __restrict__ qw2, const float* __restrict__ qb2,
    const float* __restrict__ kw1, const float* __restrict__ kb1,
    const float* __restrict__ kw2, const float* __restrict__ kb2)
{
    extern __shared__ float sm[];
    float* sw1  = sm;
    float* sw2  = sm + 8192;
    float* sx   = sm + 16384;
    float* shid = sm + 16384 + 32*65;
    const int tid = threadIdx.x;
    bf16* xh = blockIdx.y ? kh : qh;
    bf16* xl = blockIdx.y ? kl : ql;
    const float* w1 = blockIdx.y ? kw1 : qw1;
    const float* b1 = blockIdx.y ? kb1 : qb1;
    const float* w2 = blockIdx.y ? kw2 : qw2;
    const float* b2 = blockIdx.y ? kb2 : qb2;

    for (int i = tid; i < 8192; i += 256) { sw1[i] = w1[i]; sw2[i] = w2[i]; }
    bf16* xbh = xh + (size_t)blockIdx.x * (32*HD);
    bf16* xbl = xl + (size_t)blockIdx.x * (32*HD);
    for (int i = tid; i < 32*HD; i += 256)
        sx[(i >> 6)*65 + (i & 63)] = __bfloat162float(xbh[i]) + __bfloat162float(xbl[i]);
    __syncthreads();

    const int rg = tid & 15, cg = tid >> 4;
    {
        const int r0 = rg*2, j0 = cg*8;
        float acc[2][8];
        #pragma unroll
        for (int j = 0; j < 8; j++) { float bv = b1[j0+j]; acc[0][j] = bv; acc[1][j] = bv; }
        #pragma unroll 8
        for (int d = 0; d < 64; d++) {
            const float x0 = sx[r0*65 + d], x1 = sx[r0*65 + 65 + d];
            const float* wr = sw1 + d*128 + j0;
            #pragma unroll
            for (int j = 0; j < 8; j++) { const float wv = wr[j]; acc[0][j] += x0*wv; acc[1][j] += x1*wv; }
        }
        #pragma unroll
        for (int rr = 0; rr < 2; rr++)
            #pragma unroll
            for (int j = 0; j < 8; j++) {
                const float s = acc[rr][j];
                shid[(r0+rr)*129 + j0 + j] = s / (1.f + __expf(-s));
            }
    }
    __syncthreads();
    {
        const int r0 = rg*2, j0 = cg*4;
        float acc[2][4];
        #pragma unroll
        for (int j = 0; j < 4; j++) { float bv = b2[j0+j]; acc[0][j] = bv; acc[1][j] = bv; }
        #pragma unroll 4
        for (int d = 0; d < 128; d++) {
            const float h0 = shid[r0*129 + d], h1 = shid[r0*129 + 129 + d];
            const float* wr = sw2 + d*64 + j0;
            #pragma unroll
            for (int j = 0; j < 4; j++) { const float wv = wr[j]; acc[0][j] += h0*wv; acc[1][j] += h1*wv; }
        }
        #pragma unroll
        for (int rr = 0; rr < 2; rr++) {
            float o[4];
            #pragma unroll
            for (int j = 0; j < 4; j++)
                o[j] = acc[rr][j] + sx[(r0+rr)*65 + j0 + j];
            bf16 h0,l0,h1,l1,h2,l2,h3,l3;
            split_bf16(o[0],h0,l0); split_bf16(o[1],h1,l1);
            split_bf16(o[2],h2,l2); split_bf16(o[3],h3,l3);
            const int oo = (r0+rr)*64 + j0;
            *(uint2*)(xbh + oo) = make_uint2(pk(h0,h1), pk(h2,h3));
            *(uint2*)(xbl + oo) = make_uint2(pk(l0,l1), pk(l2,l3));
        }
    }
}

// ---------------- tensor-core causal flash attention (bf16x3, pre-split inputs) ----------------
#define FA_QH 0u
#define FA_QL 18432u
#define FA_KH 36864u
#define FA_KL 46080u
#define FA_VH 55296u
#define FA_VL 64512u
#define FA_SMEM 73728

__global__ __launch_bounds__(256) void flash_mma(
    const bf16* __restrict__ Qh, const bf16* __restrict__ Ql,
    const bf16* __restrict__ Kh, const bf16* __restrict__ Kl,
    const bf16* __restrict__ Vh, const bf16* __restrict__ Vl,
    bf16* __restrict__ Ohi, bf16* __restrict__ Olo)
{
    extern __shared__ char sm_[];
    const uint32_t sb = s2u(sm_);
    const int tid = threadIdx.x;
    const int lane = tid & 31, wid = tid >> 5;
    const int qt = blockIdx.x, h = blockIdx.y, b = blockIdx.z;
    const int qb = qt * 128;
    const int m0 = wid * 16;

    // ---- Q tile -> smem (direct bf16 copy) ----
    {
        const int r = tid >> 1;
        const int half = tid & 1;
        const size_t go = ((size_t)(b*SS_ + qb + r)*NH + h)*HD + half*32;
        const uint4* srcH = (const uint4*)(Qh + go);
        const uint4* srcL = (const uint4*)(Ql + go);
        uint4* dstH = (uint4*)(sm_ + FA_QH + r*144 + half*64);
        uint4* dstL = (uint4*)(sm_ + FA_QL + r*144 + half*64);
        #pragma unroll
        for (int j = 0; j < 4; j++) { dstH[j] = srcH[j]; dstL[j] = srcL[j]; }
    }

    float mstate[2] = {-1e30f, -1e30f};
    float lsum[2]   = {0.f, 0.f};
    float o[8][4];
    #pragma unroll
    for (int i = 0; i < 8; i++)
        #pragma unroll
        for (int e = 0; e < 4; e++) o[i][e] = 0.f;

    const int nk = 2*qt + 2;
    for (int kj = 0; kj < nk; kj++) {
        __syncthreads();
        // ---- K,V tile -> smem (K direct, V transposed) ----
        {
            const int r = tid >> 2;
            const int d0 = (tid & 3) * 16;
            const size_t gb = ((size_t)(b*SS_ + kj*64 + r)*NH + h)*HD + d0;
            // K hi/lo: straight copy
            *(uint4*)(sm_ + FA_KH + r*144 + d0*2)      = *(const uint4*)(Kh + gb);
            *(uint4*)(sm_ + FA_KH + r*144 + d0*2 + 16) = *(const uint4*)(Kh + gb + 8);
            *(uint4*)(sm_ + FA_KL + r*144 + d0*2)      = *(const uint4*)(Kl + gb);
            *(uint4*)(sm_ + FA_KL + r*144 + d0*2 + 16) = *(const uint4*)(Kl + gb + 8);
            // V hi/lo: transpose-scatter
            union { uint4 u[2]; bf16 b[16]; } vh, vl;
            vh.u[0] = *(const uint4*)(Vh + gb); vh.u[1] = *(const uint4*)(Vh + gb + 8);
            vl.u[0] = *(const uint4*)(Vl + gb); vl.u[1] = *(const uint4*)(Vl + gb + 8);
            #pragma unroll
            for (int t = 0; t < 16; t++) {
                *(bf16*)(sm_ + FA_VH + (d0 + t)*144 + r*2) = vh.b[t];
                *(bf16*)(sm_ + FA_VL + (d0 + t)*144 + r*2) = vl.b[t];
            }
        }
        __syncthreads();

        if (kj*64 > qb + m0 + 15) continue;

        // ---- S = Q K^T (bf16x3) ----
        float s[8][4];
        #pragma unroll
        for (int i = 0; i < 8; i++)
            #pragma unroll
            for (int e = 0; e < 4; e++) s[i][e] = 0.f;

        #pragma unroll
        for (int ks = 0; ks < 4; ks++) {
            uint32_t qh4[4], ql4[4];
            const uint32_t ao = (uint32_t)((m0 + (lane & 15))*144 + ks*32 + (lane >> 4)*16);
            ldm_x4(qh4, sb + FA_QH + ao);
            ldm_x4(ql4, sb + FA_QL + ao);
            #pragma unroll
            for (int n2 = 0; n2 < 4; n2++) {
                uint32_t kh4[4], kl4[4];
                const uint32_t bo = (uint32_t)((n2*16 + (lane & 7) + ((lane >> 4) & 1)*8)*144
                                               + ks*32 + ((lane >> 3) & 1)*16);
                ldm_x4(kh4, sb + FA_KH + bo);
                ldm_x4(kl4, sb + FA_KL + bo);
                mma_bf16(s[n2*2],   qh4, &kh4[0]);
                mma_bf16(s[n2*2],   qh4, &kl4[0]);
                mma_bf16(s[n2*2],   ql4, &kh4[0]);
                mma_bf16(s[n2*2+1], qh4, &kh4[2]);
                mma_bf16(s[n2*2+1], qh4, &kl4[2]);
                mma_bf16(s[n2*2+1], ql4, &kh4[2]);
            }
        }

        // ---- scale + causal mask ----
        const bool need_mask = (kj*64 + 63 > qb + m0);
        #pragma unroll
        for (int nt = 0; nt < 8; nt++)
            #pragma unroll
            for (int e = 0; e < 4; e++) {
                float val = s[nt][e] * 0.125f;
                if (need_mask) {
                    const int col = kj*64 + nt*8 + (lane & 3)*2 + (e & 1);
                    const int row = qb + m0 + (lane >> 2) + (e >> 1)*8;
                    if (col > row) val = -1e30f;
                }
                s[nt][e] = val;
            }

        // ---- online softmax (quad reduction) ----
        float mx[2] = {-1e30f, -1e30f};
        #pragma unroll
        for (int nt = 0; nt < 8; nt++) {
            mx[0] = fmaxf(mx[0], fmaxf(s[nt][0], s[nt][1]));
            mx[1] = fmaxf(mx[1], fmaxf(s[nt][2], s[nt][3]));
        }
        #pragma unroll
        for (int hf = 0; hf < 2; hf++) {
            mx[hf] = fmaxf(mx[hf], __shfl_xor_sync(0xffffffffu, mx[hf], 1));
            mx[hf] = fmaxf(mx[hf], __shfl_xor_sync(0xffffffffu, mx[hf], 2));
        }
        float al2[2];
        #pragma unroll
        for (int hf = 0; hf < 2; hf++) {
            const float mn = fmaxf(fmaxf(mstate[hf], mx[hf]), -1e20f);
            al2[hf] = __expf(mstate[hf] - mn);
            mstate[hf] = mn;
        }
        float sum[2] = {0.f, 0.f};
        #pragma unroll
        for (int nt = 0; nt < 8; nt++)
            #pragma unroll
            for (int e = 0; e < 4; e++) {
                const float p = __expf(s[nt][e] - mstate[e >> 1]);
                s[nt][e] = p;
                sum[e >> 1] += p;
            }
        #pragma unroll
        for (int hf = 0; hf < 2; hf++) {
            sum[hf] += __shfl_xor_sync(0xffffffffu, sum[hf], 1);
            sum[hf] += __shfl_xor_sync(0xffffffffu, sum[hf], 2);
            lsum[hf] = lsum[hf]*al2[hf] + sum[hf];
        }
        #pragma unroll
        for (int nt = 0; nt < 8; nt++)
            #pragma unroll
            for (int e = 0; e < 4; e++) o[nt][e] *= al2[e >> 1];

        // ---- O += P V (bf16x3) ----
        #pragma unroll
        for (int ks2 = 0; ks2 < 4; ks2++) {
            uint32_t pah[4], pal[4];
            {
                bf16 h0,l0,h1,l1;
                split_bf16(s[2*ks2][0],h0,l0);   split_bf16(s[2*ks2][1],h1,l1);
                pah[0] = pk(h0,h1); pal[0] = pk(l0,l1);
                split_bf16(s[2*ks2][2],h0,l0);   split_bf16(s[2*ks2][3],h1,l1);
                pah[1] = pk(h0,h1); pal[1] = pk(l0,l1);
                split_bf16(s[2*ks2+1][0],h0,l0); split_bf16(s[2*ks2+1][1],h1,l1);
                pah[2] = pk(h0,h1); pal[2] = pk(l0,l1);
                split_bf16(s[2*ks2+1][2],h0,l0); split_bf16(s[2*ks2+1][3],h1,l1);
                pah[3] = pk(h0,h1); pal[3] = pk(l0,l1);
            }
            #pragma unroll
            for (int dn2 = 0; dn2 < 4; dn2++) {
                uint32_t vh4[4], vl4[4];
                const uint32_t bo = (uint32_t)((dn2*16 + (lane & 7) + ((lane >> 4) & 1)*8)*144
                                               + ks2*32 + ((lane >> 3) & 1)*16);
                ldm_x4(vh4, sb + FA_VH + bo);
                ldm_x4(vl4, sb + FA_VL + bo);
                mma_bf16(o[dn2*2],   pah, &vh4[0]);
                mma_bf16(o[dn2*2],   pah, &vl4[0]);
                mma_bf16(o[dn2*2],   pal, &vh4[0]);
                mma_bf16(o[dn2*2+1], pah, &vh4[2]);
                mma_bf16(o[dn2*2+1], pah, &vl4[2]);
                mma_bf16(o[dn2*2+1], pal, &vh4[2]);
            }
        }
    }

    // ---- epilogue ----
    const float inv0 = 1.f / lsum[0];
    const float inv1 = 1.f / lsum[1];
    #pragma unroll
    for (int nt = 0; nt < 8; nt++)
        #pragma unroll
        for (int hf = 0; hf < 2; hf++) {
            const float inv = hf ? inv1 : inv0;
            const float v0 = o[nt][hf*2 + 0] * inv;
            const float v1 = o[nt][hf*2 + 1] * inv;
            bf16 h0, l0, h1, l1;
            split_bf16(v0, h0, l0); split_bf16(v1, h1, l1);
            const int row = qb + m0 + (lane >> 2) + hf*8;
            const int d0 = nt*8 + (lane & 3)*2;
            const size_t ro = ((size_t)(b*SS_ + row)*NH + h)*HD + d0;
            *(uint32_t*)(Ohi + ro) = pk(h0, h1);
            *(uint32_t*)(Olo + ro) = pk(l0, l1);
        }
}

// ---------------- launcher ----------------
extern "C" void kernel_launch(void* const* d_in, const int* in_sizes, int n_in,
                              void* d_out, int out_size)
{
    const float* x       = (const float*)d_in[0];
    const float* norm1_w = (const float*)d_in[2];
    const float* norm2_w = (const float*)d_in[3];
    const float* norm3_w = (const float*)d_in[4];
    const float* mlpn_w  = (const float*)d_in[5];
    const float* wq      = (const float*)d_in[6];
    const float* wk      = (const float*)d_in[7];
    const float* wv      = (const float*)d_in[8];
    const float* wo      = (const float*)d_in[9];
    const float* qs_w1   = (const float*)d_in[10];
    const float* qs_b1   = (const float*)d_in[11];
    const float* qs_w2   = (const float*)d_in[12];
    const float* qs_b2   = (const float*)d_in[13];
    const float* ks_w1   = (const float*)d_in[14];
    const float* ks_b1   = (const float*)d_in[15];
    const float* ks_w2   = (const float*)d_in[16];
    const float* ks_b2   = (const float*)d_in[17];
    const float* fc1_w   = (const float*)d_in[18];
    const float* fc1_b   = (const float*)d_in[19];
    const float* fc2_w   = (const float*)d_in[20];
    const float* fc2_b   = (const float*)d_in[21];
    const float* gate_w  = (const float*)d_in[22];
    const float* gate_b  = (const float*)d_in[23];
    float* out = (float*)d_out;

    float *ff1;
    bf16 *qh, *ql, *kh, *kl, *vh, *vl;
    bf16 *hh, *hl, *ah, *al, *f2h, *f2l;
    bf16 *wqh, *wql, *wkh, *wkl, *wvh, *wvl, *woh, *wol, *gh, *gl, *f1h, *f1l, *fch, *fcl;
    cudaGetSymbolAddress((void**)&ff1, g_ff1);
    cudaGetSymbolAddress((void**)&qh,  g_q_hi);    cudaGetSymbolAddress((void**)&ql,  g_q_lo);
    cudaGetSymbolAddress((void**)&kh,  g_k_hi);    cudaGetSymbolAddress((void**)&kl,  g_k_lo);
    cudaGetSymbolAddress((void**)&vh,  g_v_hi);    cudaGetSymbolAddress((void**)&vl,  g_v_lo);
    cudaGetSymbolAddress((void**)&hh,  g_h_hi);    cudaGetSymbolAddress((void**)&hl,  g_h_lo);
    cudaGetSymbolAddress((void**)&ah,  g_attn_hi); cudaGetSymbolAddress((void**)&al,  g_attn_lo);
    cudaGetSymbolAddress((void**)&f2h, g_ff2_hi);  cudaGetSymbolAddress((void**)&f2l, g_ff2_lo);
    cudaGetSymbolAddress((void**)&wqh, g_wqT_hi);  cudaGetSymbolAddress((void**)&wql, g_wqT_lo);
    cudaGetSymbolAddress((void**)&wkh, g_wkT_hi);  cudaGetSymbolAddress((void**)&wkl, g_wkT_lo);
    cudaGetSymbolAddress((void**)&wvh, g_wvT_hi);  cudaGetSymbolAddress((void**)&wvl, g_wvT_lo);
    cudaGetSymbolAddress((void**)&woh, g_woT_hi);  cudaGetSymbolAddress((void**)&wol, g_woT_lo);
    cudaGetSymbolAddress((void**)&gh,  g_gT_hi);   cudaGetSymbolAddress((void**)&gl,  g_gT_lo);
    cudaGetSymbolAddress((void**)&f1h, g_f1T_hi);  cudaGetSymbolAddress((void**)&f1l, g_f1T_lo);
    cudaGetSymbolAddress((void**)&fch, g_f2T_hi);  cudaGetSymbolAddress((void**)&fcl, g_f2T_lo);

    cudaFuncSetAttribute(gemm_mma<0,1>, cudaFuncAttributeMaxDynamicSharedMemorySize, GSMEM);
    cudaFuncSetAttribute(gemm_mma<1,0>, cudaFuncAttributeMaxDynamicSharedMemorySize, GSMEM);
    cudaFuncSetAttribute(gemm_mma<2,0>, cudaFuncAttributeMaxDynamicSharedMemorySize, GSMEM);
    cudaFuncSetAttribute(gemm_mma<3,1>, cudaFuncAttributeMaxDynamicSharedMemorySize, GSMEM);
    cudaFuncSetAttribute(gemm_mma<4,0>, cudaFuncAttributeMaxDynamicSharedMemorySize, GSMEM);
    cudaFuncSetAttribute(qk_mlp, cudaFuncAttributeMaxDynamicSharedMemorySize, QK_SMEM);
    cudaFuncSetAttribute(flash_mma, cudaFuncAttributeMaxDynamicSharedMemorySize, FA_SMEM);

    // launch 1: all weight converts fused
    WAll wa;
    wa.src[0] = wq;     wa.th[0] = wqh; wa.tl[0] = wql;
    wa.src[1] = wk;     wa.th[1] = wkh; wa.tl[1] = wkl;
    wa.src[2] = wv;     wa.th[2] = wvh; wa.tl[2] = wvl;
    wa.src[3] = wo;     wa.th[3] = woh; wa.tl[3] = wol;
    wa.src[4] = gate_w; wa.th[4] = gh;  wa.tl[4] = gl;
    wa.src[5] = fc1_w;  wa.th[5] = f1h; wa.tl[5] = f1l;
    wa.src[6] = fc2_w;  wa.th[6] = fch; wa.tl[6] = fcl;
    wconv_all<<<4096, 256>>>(wa);

    // launch 2: mamba stages + pre-attn norm
    norm3_fused<<<NT, 256>>>(x, norm1_w, norm2_w, norm3_w, out, hh, hl);

    // launches 3,4: q,k projections (split output)
    dim3 g1(DM/128, NT/128);
    gemm_mma<0,1><<<g1, 256, GSMEM>>>(hh, hl, wqh, wql, nullptr, nullptr, nullptr, qh, ql, DM, DM);
    gemm_mma<0,1><<<g1, 256, GSMEM>>>(hh, hl, wkh, wkl, nullptr, nullptr, nullptr, kh, kl, DM, DM);

    // launch 5: per-head SiLU-MLP residual on q,k
    qk_mlp<<<dim3(NT*NH/32, 2), 256, QK_SMEM>>>(qh, ql, kh, kl,
                                                 qs_w1, qs_b1, qs_w2, qs_b2,
                                                 ks_w1, ks_b1, ks_w2, ks_b2);

    // launch 6 (ncu captures this one): v projection
    gemm_mma<0,1><<<g1, 256, GSMEM>>>(hh, hl, wvh, wvl, nullptr, nullptr, nullptr, vh, vl, DM, DM);

    // launch 7: causal attention
    flash_mma<<<dim3(SS_/128, NH, BB), 256, FA_SMEM>>>(qh, ql, kh, kl, vh, vl, ah, al);

    // launch 8: out projection + residual
    gemm_mma<1,0><<<g1, 256, GSMEM>>>(ah, al, woh, wol, nullptr, out, out, nullptr, nullptr, DM, DM);

    // launch 9: mlp norm
    rmsnorm_k<<<NT, 256>>>(out, mlpn_w, hh, hl);

    // launches 10,11: gate & fc1
    dim3 g2(DFF/128, NT/128);
    gemm_mma<2,0><<<g2, 256, GSMEM>>>(hh, hl, gh, gl, gate_b, nullptr, ff1, nullptr, nullptr, DFF, DM);
    gemm_mma<3,1><<<g2, 256, GSMEM>>>(hh, hl, f1h, f1l, fc1_b, ff1, nullptr, f2h, f2l, DFF, DM);

    // launch 12: fc2 + residual
    gemm_mma<4,0><<<g1, 256, GSMEM>>>(f2h, f2l, fch, fcl, fc2_b, out, out, nullptr, nullptr, DM, DFF);
}

// round 7
// speedup vs baseline: 3.0763x; 1.0138x over previous
#include <cuda_runtime.h>
#include <cuda_bf16.h>
#include <math.h>
#include <stdint.h>

typedef __nv_bfloat16 bf16;

#define BB   2
#define SS_  2048
#define DM   1024
#define NT   (BB*SS_)
#define NH   16
#define HD   64
#define DSTATE 128
#define DFF  4096

// ---------------- device scratch ----------------
__device__ __align__(256) bf16 g_qkv_hi[NT*3*DM], g_qkv_lo[NT*3*DM];
__device__ __align__(256) bf16 g_h_hi[NT*DM],     g_h_lo[NT*DM];
__device__ __align__(256) bf16 g_attn_hi[NT*DM],  g_attn_lo[NT*DM];
__device__ __align__(256) bf16 g_ff2_hi[NT*DFF],  g_ff2_lo[NT*DFF];
__device__ __align__(256) bf16 g_wqkvT_hi[3*DM*DM], g_wqkvT_lo[3*DM*DM];
__device__ __align__(256) bf16 g_woT_hi[DM*DM],   g_woT_lo[DM*DM];
__device__ __align__(256) bf16 g_gf1T_hi[2*DFF*DM], g_gf1T_lo[2*DFF*DM];  // interleaved gate/fc1
__device__ __align__(256) bf16 g_f2T_hi[DFF*DM],  g_f2T_lo[DFF*DM];

// ---------------- PTX helpers (family-portable) ----------------
__device__ __forceinline__ uint32_t s2u(const void* p) {
    uint32_t a;
    asm("{ .reg .u64 t; cvta.to.shared.u64 t, %1; cvt.u32.u64 %0, t; }" : "=r"(a) : "l"(p));
    return a;
}
#define CP16(d, s)   asm volatile("cp.async.cg.shared.global [%0], [%1], 16;" :: "r"(d), "l"(s))
#define CP_COMMIT()  asm volatile("cp.async.commit_group;" ::: "memory")
#define CP_WAIT1()   asm volatile("cp.async.wait_group 1;" ::: "memory")

__device__ __forceinline__ void ldm_x4(uint32_t* r, uint32_t addr) {
    asm volatile("ldmatrix.sync.aligned.m8n8.x4.shared.b16 {%0,%1,%2,%3}, [%4];"
        : "=r"(r[0]), "=r"(r[1]), "=r"(r[2]), "=r"(r[3]) : "r"(addr));
}
__device__ __forceinline__ void mma_bf16(float* d, const uint32_t* a, const uint32_t* b) {
    asm volatile("mma.sync.aligned.m16n8k16.row.col.f32.bf16.bf16.f32 "
        "{%0,%1,%2,%3}, {%4,%5,%6,%7}, {%8,%9}, {%0,%1,%2,%3};"
        : "+f"(d[0]), "+f"(d[1]), "+f"(d[2]), "+f"(d[3])
        : "r"(a[0]), "r"(a[1]), "r"(a[2]), "r"(a[3]), "r"(b[0]), "r"(b[1]));
}

// ---------------- misc ----------------
__device__ __forceinline__ float block_sum(float v, float* sbuf) {
    int lane = threadIdx.x & 31, w = threadIdx.x >> 5;
    #pragma unroll
    for (int o = 16; o; o >>= 1) v += __shfl_xor_sync(0xffffffffu, v, o);
    if (lane == 0) sbuf[w] = v;
    __syncthreads();
    if (w == 0) {
        v = (lane < 8) ? sbuf[lane] : 0.f;
        #pragma unroll
        for (int o = 4; o; o >>= 1) v += __shfl_xor_sync(0xffffffffu, v, o);
        if (lane == 0) sbuf[0] = v;
    }
    __syncthreads();
    float r = sbuf[0];
    __syncthreads();
    return r;
}
__device__ __forceinline__ void split_bf16(float x, bf16& h, bf16& l) {
    h = __float2bfloat16(x);
    l = __float2bfloat16(x - __bfloat162float(h));
}
__device__ __forceinline__ uint32_t pk(bf16 a, bf16 b) {
    return ((uint32_t)__bfloat16_as_ushort(b) << 16) | __bfloat16_as_ushort(a);
}

// ---------------- norm kernels ----------------
__global__ __launch_bounds__(256) void norm3_fused(
    const float* __restrict__ x,
    const float* __restrict__ w1, const float* __restrict__ w2, const float* __restrict__ w3,
    float* __restrict__ xout, bf16* __restrict__ h_hi, bf16* __restrict__ h_lo)
{
    __shared__ float sbuf[32];
    const int t = blockIdx.x;
    const int base = threadIdx.x * 4;
    float4 v  = *(const float4*)(x + (size_t)t*DM + base);
    float4 a1 = *(const float4*)(w1 + base);
    float4 a2 = *(const float4*)(w2 + base);
    float4 a3 = *(const float4*)(w3 + base);

    float ss = v.x*v.x + v.y*v.y + v.z*v.z + v.w*v.w;
    float r = rsqrtf(block_sum(ss, sbuf) * (1.f/DM) + 1e-6f);
    v.x += a1.x*v.x*r; v.y += a1.y*v.y*r; v.z += a1.z*v.z*r; v.w += a1.w*v.w*r;

    ss = v.x*v.x + v.y*v.y + v.z*v.z + v.w*v.w;
    r = rsqrtf(block_sum(ss, sbuf) * (1.f/DM) + 1e-6f);
    v.x += a2.x*v.x*r; v.y += a2.y*v.y*r; v.z += a2.z*v.z*r; v.w += a2.w*v.w*r;
    *(float4*)(xout + (size_t)t*DM + base) = v;

    ss = v.x*v.x + v.y*v.y + v.z*v.z + v.w*v.w;
    r = rsqrtf(block_sum(ss, sbuf) * (1.f/DM) + 1e-6f);
    float hv[4] = { a3.x*v.x*r, a3.y*v.y*r, a3.z*v.z*r, a3.w*v.w*r };
    __align__(8) bf16 hh[4], hl[4];
    #pragma unroll
    for (int i = 0; i < 4; i++) split_bf16(hv[i], hh[i], hl[i]);
    *(uint2*)(h_hi + (size_t)t*DM + base) = *(uint2*)hh;
    *(uint2*)(h_lo + (size_t)t*DM + base) = *(uint2*)hl;
}

__global__ __launch_bounds__(256) void rmsnorm_k(
    const float* __restrict__ x, const float* __restrict__ w,
    bf16* __restrict__ o_hi, bf16* __restrict__ o_lo)
{
    __shared__ float sbuf[32];
    const int t = blockIdx.x;
    const int base = threadIdx.x * 4;
    float4 v = *(const float4*)(x + (size_t)t*DM + base);
    float4 a = *(const float4*)(w + base);
    float ss = v.x*v.x + v.y*v.y + v.z*v.z + v.w*v.w;
    float r = rsqrtf(block_sum(ss, sbuf) * (1.f/DM) + 1e-6f);
    float ov[4] = { a.x*v.x*r, a.y*v.y*r, a.z*v.z*r, a.w*v.w*r };
    __align__(8) bf16 hh[4], hl[4];
    #pragma unroll
    for (int i = 0; i < 4; i++) split_bf16(ov[i], hh[i], hl[i]);
    *(uint2*)(o_hi + (size_t)t*DM + base) = *(uint2*)hh;
    *(uint2*)(o_lo + (size_t)t*DM + base) = *(uint2*)hl;
}

// ---------------- fused weight transpose + split (single launch) ----------------
// m 0..2 -> qkv segments of g_wqkvT (base-offset per m)
// m 4 (gate), 5 (fc1) -> interleaved rows of g_gf1T: row_out = 2*n + (m==5)
struct WAll {
    const float* src[7];
    bf16* th[7];
    bf16* tl[7];
};

__global__ __launch_bounds__(256) void wconv_all(WAll wa)
{
    __shared__ float t[64][65];
    const int id = blockIdx.x;
    int m, tbase;
    if (id < 1024)      { m = id >> 8; tbase = m << 8; }
    else if (id < 2048) { m = 4; tbase = 1024; }
    else if (id < 3072) { m = 5; tbase = 2048; }
    else                { m = 6; tbase = 3072; }
    const int K = (m == 6) ? DFF : DM;
    const int N = (m == 4 || m == 5) ? DFF : DM;
    const int tt = id - tbase;
    const int ntx = N / 64;
    const int n0 = (tt % ntx) * 64, k0 = (tt / ntx) * 64;
    const float* W = wa.src[m];
    bf16* Th = wa.th[m];
    bf16* Tl = wa.tl[m];
    const bool ilv = (m == 4 || m == 5);
    const int foff = (m == 5) ? 1 : 0;

    const int tid = threadIdx.x;
    {
        const int r = tid >> 2, c0 = (tid & 3) * 16;
        const float* src = W + (size_t)(k0 + r)*N + n0 + c0;
        #pragma unroll
        for (int j = 0; j < 4; j++) {
            float4 vv = *(const float4*)(src + j*4);
            t[r][c0 + j*4 + 0] = vv.x; t[r][c0 + j*4 + 1] = vv.y;
            t[r][c0 + j*4 + 2] = vv.z; t[r][c0 + j*4 + 3] = vv.w;
        }
    }
    __syncthreads();
    {
        const int n = tid >> 2, ks = (tid & 3) * 16;
        uint32_t ph[8], pl[8];
        #pragma unroll
        for (int j = 0; j < 8; j++) {
            float a = t[ks + j*2][n], c = t[ks + j*2 + 1][n];
            bf16 ha, la, hc, lc;
            split_bf16(a, ha, la); split_bf16(c, hc, lc);
            ph[j] = pk(ha, hc); pl[j] = pk(la, lc);
        }
        const size_t row_out = ilv ? (size_t)(2*(n0 + n) + foff) : (size_t)(n0 + n);
        const size_t ou = (row_out*K + k0 + ks) >> 1;
        uint32_t* dh = (uint32_t*)Th + ou;
        uint32_t* dl = (uint32_t*)Tl + ou;
        *(uint4*)(dh)     = make_uint4(ph[0], ph[1], ph[2], ph[3]);
        *(uint4*)(dh + 4) = make_uint4(ph[4], ph[5], ph[6], ph[7]);
        *(uint4*)(dl)     = make_uint4(pl[0], pl[1], pl[2], pl[3]);
        *(uint4*)(dl + 4) = make_uint4(pl[4], pl[5], pl[6], pl[7]);
    }
}

// ---------------- bf16x3 GEMM via mma.sync: C[M,N] = A[M,K] @ B[N,K]^T ----------------
// EPI: 0 none | 1 +extra | 4 +bias+extra | 5 gate/fc1 interleaved (silu(v0+b1)*(v1+b2) -> N/2 cols)
#define GSTAGE 32768
#define GSMEM  (3*GSTAGE)

__device__ __forceinline__ uint32_t swz(int row, int chunk) {
    return (uint32_t)(row*64 + ((chunk ^ (row & 3) ^ ((row >> 2) & 1)) << 4));
}

template<int EPI, int OSPLIT>
__global__ __launch_bounds__(256) void gemm_mma(
    const bf16* __restrict__ Ahi, const bf16* __restrict__ Alo,
    const bf16* __restrict__ Bhi, const bf16* __restrict__ Blo,
    const float* __restrict__ bias, const float* __restrict__ bias2,
    const float* __restrict__ extra,
    float* __restrict__ C, bf16* __restrict__ Chi, bf16* __restrict__ Clo,
    int N, int K)
{
    extern __shared__ char smem[];
    const uint32_t sb = s2u(smem);
    const int tid = threadIdx.x;
    const int lane = tid & 31, wid = tid >> 5;
    const int wm = wid >> 2, wn = wid & 3;
    const int row0 = blockIdx.y * 128, col0 = blockIdx.x * 128;
    const int nc = K / 32;

    const int lr = tid >> 1, lc = tid & 1;
    const uint32_t off0 = swz(lr, lc), off1 = swz(lr, lc + 2);
    const bf16* gAh = Ahi + (size_t)(row0 + lr)*K + lc*8;
    const bf16* gAl = Alo + (size_t)(row0 + lr)*K + lc*8;
    const bf16* gBh = Bhi + (size_t)(col0 + lr)*K + lc*8;
    const bf16* gBl = Blo + (size_t)(col0 + lr)*K + lc*8;

    #define GLOAD(st, kc) do { \
        const uint32_t s0 = sb + (uint32_t)(st)*GSTAGE; \
        const int ko = (kc)*32; \
        CP16(s0 +          off0, gAh + ko); CP16(s0 +          off1, gAh + ko + 16); \
        CP16(s0 +  8192 + off0, gAl + ko); CP16(s0 +  8192 + off1, gAl + ko + 16); \
        CP16(s0 + 16384 + off0, gBh + ko); CP16(s0 + 16384 + off1, gBh + ko + 16); \
        CP16(s0 + 24576 + off0, gBl + ko); CP16(s0 + 24576 + off1, gBl + ko + 16); \
    } while (0)

    const int arow = wm*64 + (lane & 15);
    const int abit = lane >> 4;
    const int brow = wn*32 + (lane & 7) + ((lane >> 4) & 1)*8;
    const int bbit = (lane >> 3) & 1;

    float acc[4][4][4];
    #pragma unroll
    for (int i = 0; i < 4; i++)
        #pragma unroll
        for (int j = 0; j < 4; j++)
            #pragma unroll
            for (int d2 = 0; d2 < 4; d2++) acc[i][j][d2] = 0.f;

    GLOAD(0, 0); CP_COMMIT();
    GLOAD(1, 1); CP_COMMIT();

    for (int kc = 0; kc < nc; kc++) {
        CP_WAIT1();
        __syncthreads();
        const uint32_t s0 = sb + (uint32_t)(kc % 3)*GSTAGE;
        #pragma unroll
        for (int ks = 0; ks < 2; ks++) {
            uint32_t ah[4][4], al[4][4], bh[2][4], bl[2][4];
            #pragma unroll
            for (int mt = 0; mt < 4; mt++) {
                const uint32_t ao = swz(arow + mt*16, ks*2 + abit);
                ldm_x4(ah[mt], s0 + ao);
                ldm_x4(al[mt], s0 + 8192 + ao);
            }
            #pragma unroll
            for (int n2 = 0; n2 < 2; n2++) {
                const uint32_t bo = swz(brow + n2*16, ks*2 + bbit);
                ldm_x4(bh[n2], s0 + 16384 + bo);
                ldm_x4(bl[n2], s0 + 24576 + bo);
            }
            #pragma unroll
            for (int mt = 0; mt < 4; mt++)
                #pragma unroll
                for (int nt = 0; nt < 4; nt++) {
                    const uint32_t* ph = &bh[nt >> 1][(nt & 1)*2];
                    const uint32_t* pl = &bl[nt >> 1][(nt & 1)*2];
                    mma_bf16(acc[mt][nt], ah[mt], ph);
                    mma_bf16(acc[mt][nt], ah[mt], pl);
                    mma_bf16(acc[mt][nt], al[mt], ph);
                }
        }
        if (kc + 2 < nc) GLOAD((kc + 2) % 3, kc + 2);
        CP_COMMIT();
    }
    #undef GLOAD

    const int erow = lane >> 2;
    const int ecol = (lane & 3)*2;
    #pragma unroll
    for (int mt = 0; mt < 4; mt++)
        #pragma unroll
        for (int hf = 0; hf < 2; hf++) {
            const int row = row0 + wm*64 + mt*16 + erow + hf*8;
            #pragma unroll
            for (int nt = 0; nt < 4; nt++) {
                const int col = col0 + wn*32 + nt*8 + ecol;
                float v0 = acc[mt][nt][hf*2 + 0];
                float v1 = acc[mt][nt][hf*2 + 1];
                if (EPI == 5) {
                    // interleaved gate/fc1: v0 = gate col j, v1 = fc1 col j, j = col/2
                    const int j = col >> 1;
                    float g = v0 + bias[j];
                    float f = v1 + bias2[j];
                    g = g / (1.f + __expf(-g));
                    const float rv = g * f;
                    bf16 h0, l0; split_bf16(rv, h0, l0);
                    const size_t po = (size_t)row * (size_t)(N >> 1) + j;
                    Chi[po] = h0; Clo[po] = l0;
                    continue;
                }
                const size_t ro = (size_t)row * N + col;
                if (EPI == 1) { float2 e = *(const float2*)(extra + ro); v0 += e.x; v1 += e.y; }
                if (EPI == 4) {
                    float2 e = *(const float2*)(extra + ro);
                    v0 += bias[col] + e.x; v1 += bias[col + 1] + e.y;
                }
                if (OSPLIT) {
                    bf16 h0, l0, h1, l1;
                    split_bf16(v0, h0, l0); split_bf16(v1, h1, l1);
                    *(uint32_t*)(Chi + ro) = pk(h0, h1);
                    *(uint32_t*)(Clo + ro) = pk(l0, l1);
                } else {
                    float2 o; o.x = v0; o.y = v1;
                    *(float2*)(C + ro) = o;
                }
            }
        }
}

// ---------------- qk silu-mlp residual (qkv layout, bf16 hi/lo in-place) ----------------
// 32 rows/block = 2 tokens x 16 heads. seg = blockIdx.y*1024 (0 = q, 1024 = k).
#define QK_SMEM ((8192 + 8192 + 32*65 + 32*129) * 4)
__global__ __launch_bounds__(256) void qk_mlp(
    bf16* __restrict__ qkvh, bf16* __restrict__ qkvl,
    const float* __restrict__ qw1, const float* __restrict__ qb1,
    const float* __restrict__ qw2, const float* __restrict__ qb2,
    const float* __restrict__ kw1, const float* __restrict__ kb1,
    const float* __restrict__ kw2, const float* __restrict__ kb2)
{
    extern __shared__ float sm[];
    float* sw1  = sm;
    float* sw2  = sm + 8192;
    float* sx   = sm + 16384;
    float* shid = sm + 16384 + 32*65;
    const int tid = threadIdx.x;
    const int t0 = blockIdx.x * 2;
    const int seg = blockIdx.y * 1024;
    const float* w1 = blockIdx.y ? kw1 : qw1;
    const float* b1 = blockIdx.y ? kb1 : qb1;
    const float* w2 = blockIdx.y ? kw2 : qw2;
    const float* b2 = blockIdx.y ? kb2 : qb2;

    for (int i = tid; i < 8192; i += 256) { sw1[i] = w1[i]; sw2[i] = w2[i]; }
    for (int i = tid; i < 32*HD; i += 256) {
        const int r = i >> 6, c = i & 63;
        const size_t ga = (size_t)(t0 + (r >> 4))*3072 + seg + (size_t)(r & 15)*64 + c;
        sx[r*65 + c] = __bfloat162float(qkvh[ga]) + __bfloat162float(qkvl[ga]);
    }
    __syncthreads();

    const int rg = tid & 15, cg = tid >> 4;
    {
        const int r0 = rg*2, j0 = cg*8;
        float acc[2][8];
        #pragma unroll
        for (int j = 0; j < 8; j++) { float bv = b1[j0+j]; acc[0][j] = bv; acc[1][j] = bv; }
        #pragma unroll 8
        for (int d = 0; d < 64; d++) {
            const float x0 = sx[r0*65 + d], x1 = sx[r0*65 + 65 + d];
            const float* wr = sw1 + d*128 + j0;
            #pragma unroll
            for (int j = 0; j < 8; j++) { const float wv = wr[j]; acc[0][j] += x0*wv; acc[1][j] += x1*wv; }
        }
        #pragma unroll
        for (int rr = 0; rr < 2; rr++)
            #pragma unroll
            for (int j = 0; j < 8; j++) {
                const float s = acc[rr][j];
                shid[(r0+rr)*129 + j0 + j] = s / (1.f + __expf(-s));
            }
    }
    __syncthreads();
    {
        const int r0 = rg*2, j0 = cg*4;
        float acc[2][4];
        #pragma unroll
        for (int j = 0; j < 4; j++) { float bv = b2[j0+j]; acc[0][j] = bv; acc[1][j] = bv; }
        #pragma unroll 4
        for (int d = 0; d < 128; d++) {
            const float h0 = shid[r0*129 + d], h1 = shid[r0*129 + 129 + d];
            const float* wr = sw2 + d*64 + j0;
            #pragma unroll
            for (int j = 0; j < 4; j++) { const float wv = wr[j]; acc[0][j] += h0*wv; acc[1][j] += h1*wv; }
        }
        #pragma unroll
        for (int rr = 0; rr < 2; rr++) {
            const int row = r0 + rr;
            float o[4];
            #pragma unroll
            for (int j = 0; j < 4; j++)
                o[j] = acc[rr][j] + sx[row*65 + j0 + j];
            bf16 h0,l0,h1,l1,h2,l2,h3,l3;
            split_bf16(o[0],h0,l0); split_bf16(o[1],h1,l1);
            split_bf16(o[2],h2,l2); split_bf16(o[3],h3,l3);
            const size_t ga = (size_t)(t0 + (row >> 4))*3072 + seg + (size_t)(row & 15)*64 + j0;
            *(uint2*)(qkvh + ga) = make_uint2(pk(h0,h1), pk(h2,h3));
            *(uint2*)(qkvl + ga) = make_uint2(pk(l0,l1), pk(l2,l3));
        }
    }
}

// ---------------- tensor-core causal flash attention (bf16x3, qkv layout) ----------------
#define FA_QH 0u
#define FA_QL 18432u
#define FA_KH 36864u
#define FA_KL 46080u
#define FA_VH 55296u
#define FA_VL 64512u
#define FA_SMEM 73728

__global__ __launch_bounds__(256) void flash_mma(
    const bf16* __restrict__ QKVh, const bf16* __restrict__ QKVl,
    bf16* __restrict__ Ohi, bf16* __restrict__ Olo)
{
    extern __shared__ char sm_[];
    const uint32_t sb = s2u(sm_);
    const int tid = threadIdx.x;
    const int lane = tid & 31, wid = tid >> 5;
    const int qt = (int)gridDim.x - 1 - (int)blockIdx.x;  // heavy tiles first
    const int h = blockIdx.y, b = blockIdx.z;
    const int qb = qt * 128;
    const int m0 = wid * 16;

    // ---- Q tile -> smem ----
    {
        const int r = tid >> 1;
        const int half = tid & 1;
        const size_t go = (size_t)(b*SS_ + qb + r)*3072 + h*64 + half*32;
        const uint4* srcH = (const uint4*)(QKVh + go);
        const uint4* srcL = (const uint4*)(QKVl + go);
        uint4* dstH = (uint4*)(sm_ + FA_QH + r*144 + half*64);
        uint4* dstL = (uint4*)(sm_ + FA_QL + r*144 + half*64);
        #pragma unroll
        for (int j = 0; j < 4; j++) { dstH[j] = srcH[j]; dstL[j] = srcL[j]; }
    }

    float mstate[2] = {-1e30f, -1e30f};
    float lsum[2]   = {0.f, 0.f};
    float o[8][4];
    #pragma unroll
    for (int i = 0; i < 8; i++)
        #pragma unroll
        for (int e = 0; e < 4; e++) o[i][e] = 0.f;

    const int nk = 2*qt + 2;
    for (int kj = 0; kj < nk; kj++) {
        __syncthreads();
        {
            const int r = tid >> 2;
            const int d0 = (tid & 3) * 16;
            const size_t gb = (size_t)(b*SS_ + kj*64 + r)*3072 + 1024 + h*64 + d0;
            *(uint4*)(sm_ + FA_KH + r*144 + d0*2)      = *(const uint4*)(QKVh + gb);
            *(uint4*)(sm_ + FA_KH + r*144 + d0*2 + 16) = *(const uint4*)(QKVh + gb + 8);
            *(uint4*)(sm_ + FA_KL + r*144 + d0*2)      = *(const uint4*)(QKVl + gb);
            *(uint4*)(sm_ + FA_KL + r*144 + d0*2 + 16) = *(const uint4*)(QKVl + gb + 8);
            union { uint4 u[2]; bf16 b[16]; } vh, vl;
            vh.u[0] = *(const uint4*)(QKVh + gb + 1024); vh.u[1] = *(const uint4*)(QKVh + gb + 1032);
            vl.u[0] = *(const uint4*)(QKVl + gb + 1024); vl.u[1] = *(const uint4*)(QKVl + gb + 1032);
            #pragma unroll
            for (int t = 0; t < 16; t++) {
                *(bf16*)(sm_ + FA_VH + (d0 + t)*144 + r*2) = vh.b[t];
                *(bf16*)(sm_ + FA_VL + (d0 + t)*144 + r*2) = vl.b[t];
            }
        }
        __syncthreads();

        if (kj*64 > qb + m0 + 15) continue;

        float s[8][4];
        #pragma unroll
        for (int i = 0; i < 8; i++)
            #pragma unroll
            for (int e = 0; e < 4; e++) s[i][e] = 0.f;

        #pragma unroll
        for (int ks = 0; ks < 4; ks++) {
            uint32_t qh4[4], ql4[4];
            const uint32_t ao = (uint32_t)((m0 + (lane & 15))*144 + ks*32 + (lane >> 4)*16);
            ldm_x4(qh4, sb + FA_QH + ao);
            ldm_x4(ql4, sb + FA_QL + ao);
            #pragma unroll
            for (int n2 = 0; n2 < 4; n2++) {
                uint32_t kh4[4], kl4[4];
                const uint32_t bo = (uint32_t)((n2*16 + (lane & 7) + ((lane >> 4) & 1)*8)*144
                                               + ks*32 + ((lane >> 3) & 1)*16);
                ldm_x4(kh4, sb + FA_KH + bo);
                ldm_x4(kl4, sb + FA_KL + bo);
                mma_bf16(s[n2*2],   qh4, &kh4[0]);
                mma_bf16(s[n2*2],   qh4, &kl4[0]);
                mma_bf16(s[n2*2],   ql4, &kh4[0]);
                mma_bf16(s[n2*2+1], qh4, &kh4[2]);
                mma_bf16(s[n2*2+1], qh4, &kl4[2]);
                mma_bf16(s[n2*2+1], ql4, &kh4[2]);
            }
        }

        const bool need_mask = (kj*64 + 63 > qb + m0);
        #pragma unroll
        for (int nt = 0; nt < 8; nt++)
            #pragma unroll
            for (int e = 0; e < 4; e++) {
                float val = s[nt][e] * 0.125f;
                if (need_mask) {
                    const int col = kj*64 + nt*8 + (lane & 3)*2 + (e & 1);
                    const int row = qb + m0 + (lane >> 2) + (e >> 1)*8;
                    if (col > row) val = -1e30f;
                }
                s[nt][e] = val;
            }

        float mx[2] = {-1e30f, -1e30f};
        #pragma unroll
        for (int nt = 0; nt < 8; nt++) {
            mx[0] = fmaxf(mx[0], fmaxf(s[nt][0], s[nt][1]));
            mx[1] = fmaxf(mx[1], fmaxf(s[nt][2], s[nt][3]));
        }
        #pragma unroll
        for (int hf = 0; hf < 2; hf++) {
            mx[hf] = fmaxf(mx[hf], __shfl_xor_sync(0xffffffffu, mx[hf], 1));
            mx[hf] = fmaxf(mx[hf], __shfl_xor_sync(0xffffffffu, mx[hf], 2));
        }
        float al2[2];
        #pragma unroll
        for (int hf = 0; hf < 2; hf++) {
            const float mn = fmaxf(fmaxf(mstate[hf], mx[hf]), -1e20f);
            al2[hf] = __expf(mstate[hf] - mn);
            mstate[hf] = mn;
        }
        float sum[2] = {0.f, 0.f};
        #pragma unroll
        for (int nt = 0; nt < 8; nt++)
            #pragma unroll
            for (int e = 0; e < 4; e++) {
                const float p = __expf(s[nt][e] - mstate[e >> 1]);
                s[nt][e] = p;
                sum[e >> 1] += p;
            }
        #pragma unroll
        for (int hf = 0; hf < 2; hf++) {
            sum[hf] += __shfl_xor_sync(0xffffffffu, sum[hf], 1);
            sum[hf] += __shfl_xor_sync(0xffffffffu, sum[hf], 2);
            lsum[hf] = lsum[hf]*al2[hf] + sum[hf];
        }
        #pragma unroll
        for (int nt = 0; nt < 8; nt++)
            #pragma unroll
            for (int e = 0; e < 4; e++) o[nt][e] *= al2[e >> 1];

        #pragma unroll
        for (int ks2 = 0; ks2 < 4; ks2++) {
            uint32_t pah[4], pal[4];
            {
                bf16 h0,l0,h1,l1;
                split_bf16(s[2*ks2][0],h0,l0);   split_bf16(s[2*ks2][1],h1,l1);
                pah[0] = pk(h0,h1); pal[0] = pk(l0,l1);
                split_bf16(s[2*ks2][2],h0,l0);   split_bf16(s[2*ks2][3],h1,l1);
                pah[1] = pk(h0,h1); pal[1] = pk(l0,l1);
                split_bf16(s[2*ks2+1][0],h0,l0); split_bf16(s[2*ks2+1][1],h1,l1);
                pah[2] = pk(h0,h1); pal[2] = pk(l0,l1);
                split_bf16(s[2*ks2+1][2],h0,l0); split_bf16(s[2*ks2+1][3],h1,l1);
                pah[3] = pk(h0,h1); pal[3] = pk(l0,l1);
            }
            #pragma unroll
            for (int dn2 = 0; dn2 < 4; dn2++) {
                uint32_t vh4[4], vl4[4];
                const uint32_t bo = (uint32_t)((dn2*16 + (lane & 7) + ((lane >> 4) & 1)*8)*144
                                               + ks2*32 + ((lane >> 3) & 1)*16);
                ldm_x4(vh4, sb + FA_VH + bo);
                ldm_x4(vl4, sb + FA_VL + bo);
                mma_bf16(o[dn2*2],   pah, &vh4[0]);
                mma_bf16(o[dn2*2],   pah, &vl4[0]);
                mma_bf16(o[dn2*2],   pal, &vh4[0]);
                mma_bf16(o[dn2*2+1], pah, &vh4[2]);
                mma_bf16(o[dn2*2+1], pah, &vl4[2]);
                mma_bf16(o[dn2*2+1], pal, &vh4[2]);
            }
        }
    }

    const float inv0 = 1.f / lsum[0];
    const float inv1 = 1.f / lsum[1];
    #pragma unroll
    for (int nt = 0; nt < 8; nt++)
        #pragma unroll
        for (int hf = 0; hf < 2; hf++) {
            const float inv = hf ? inv1 : inv0;
            const float v0 = o[nt][hf*2 + 0] * inv;
            const float v1 = o[nt][hf*2 + 1] * inv;
            bf16 h0, l0, h1, l1;
            split_bf16(v0, h0, l0); split_bf16(v1, h1, l1);
            const int row = qb + m0 + (lane >> 2) + hf*8;
            const int d0 = nt*8 + (lane & 3)*2;
            const size_t ro = ((size_t)(b*SS_ + row)*NH + h)*HD + d0;
            *(uint32_t*)(Ohi + ro) = pk(h0, h1);
            *(uint32_t*)(Olo + ro) = pk(l0, l1);
        }
}

// ---------------- launcher ----------------
extern "C" void kernel_launch(void* const* d_in, const int* in_sizes, int n_in,
                              void* d_out, int out_size)
{
    const float* x       = (const float*)d_in[0];
    const float* norm1_w = (const float*)d_in[2];
    const float* norm2_w = (const float*)d_in[3];
    const float* norm3_w = (const float*)d_in[4];
    const float* mlpn_w  = (const float*)d_in[5];
    const float* wq      = (const float*)d_in[6];
    const float* wk      = (const float*)d_in[7];
    const float* wv      = (const float*)d_in[8];
    const float* wo      = (const float*)d_in[9];
    const float* qs_w1   = (const float*)d_in[10];
    const float* qs_b1   = (const float*)d_in[11];
    const float* qs_w2   = (const float*)d_in[12];
    const float* qs_b2   = (const float*)d_in[13];
    const float* ks_w1   = (const float*)d_in[14];
    const float* ks_b1   = (const float*)d_in[15];
    const float* ks_w2   = (const float*)d_in[16];
    const float* ks_b2   = (const float*)d_in[17];
    const float* fc1_w   = (const float*)d_in[18];
    const float* fc1_b   = (const float*)d_in[19];
    const float* fc2_w   = (const float*)d_in[20];
    const float* fc2_b   = (const float*)d_in[21];
    const float* gate_w  = (const float*)d_in[22];
    const float* gate_b  = (const float*)d_in[23];
    float* out = (float*)d_out;

    bf16 *qkvh, *qkvl, *hh, *hl, *ah, *al, *f2h, *f2l;
    bf16 *wqkvh, *wqkvl, *woh, *wol, *gf1h, *gf1l, *fch, *fcl;
    cudaGetSymbolAddress((void**)&qkvh, g_qkv_hi);   cudaGetSymbolAddress((void**)&qkvl, g_qkv_lo);
    cudaGetSymbolAddress((void**)&hh,  g_h_hi);      cudaGetSymbolAddress((void**)&hl,  g_h_lo);
    cudaGetSymbolAddress((void**)&ah,  g_attn_hi);   cudaGetSymbolAddress((void**)&al,  g_attn_lo);
    cudaGetSymbolAddress((void**)&f2h, g_ff2_hi);    cudaGetSymbolAddress((void**)&f2l, g_ff2_lo);
    cudaGetSymbolAddress((void**)&wqkvh, g_wqkvT_hi); cudaGetSymbolAddress((void**)&wqkvl, g_wqkvT_lo);
    cudaGetSymbolAddress((void**)&woh, g_woT_hi);    cudaGetSymbolAddress((void**)&wol, g_woT_lo);
    cudaGetSymbolAddress((void**)&gf1h, g_gf1T_hi);  cudaGetSymbolAddress((void**)&gf1l, g_gf1T_lo);
    cudaGetSymbolAddress((void**)&fch, g_f2T_hi);    cudaGetSymbolAddress((void**)&fcl, g_f2T_lo);

    cudaFuncSetAttribute(gemm_mma<0,1>, cudaFuncAttributeMaxDynamicSharedMemorySize, GSMEM);
    cudaFuncSetAttribute(gemm_mma<1,0>, cudaFuncAttributeMaxDynamicSharedMemorySize, GSMEM);
    cudaFuncSetAttribute(gemm_mma<5,0>, cudaFuncAttributeMaxDynamicSharedMemorySize, GSMEM);
    cudaFuncSetAttribute(gemm_mma<4,0>, cudaFuncAttributeMaxDynamicSharedMemorySize, GSMEM);
    cudaFuncSetAttribute(qk_mlp, cudaFuncAttributeMaxDynamicSharedMemorySize, QK_SMEM);
    cudaFuncSetAttribute(flash_mma, cudaFuncAttributeMaxDynamicSharedMemorySize, FA_SMEM);

    // launch 1: all weight converts (qkv concat + gate/fc1 interleave)
    WAll wa;
    wa.src[0] = wq;     wa.th[0] = wqkvh;              wa.tl[0] = wqkvl;
    wa.src[1] = wk;     wa.th[1] = wqkvh + DM*DM;      wa.tl[1] = wqkvl + DM*DM;
    wa.src[2] = wv;     wa.th[2] = wqkvh + 2*DM*DM;    wa.tl[2] = wqkvl + 2*DM*DM;
    wa.src[3] = wo;     wa.th[3] = woh;                wa.tl[3] = wol;
    wa.src[4] = gate_w; wa.th[4] = gf1h;               wa.tl[4] = gf1l;
    wa.src[5] = fc1_w;  wa.th[5] = gf1h;               wa.tl[5] = gf1l;
    wa.src[6] = fc2_w;  wa.th[6] = fch;                wa.tl[6] = fcl;
    wconv_all<<<4096, 256>>>(wa);

    // launch 2: mamba stages + pre-attn norm
    norm3_fused<<<NT, 256>>>(x, norm1_w, norm2_w, norm3_w, out, hh, hl);

    // launch 3: fused qkv projection -> token-major [NT, 3072] hi/lo
    gemm_mma<0,1><<<dim3(3*DM/128, NT/128), 256, GSMEM>>>(
        hh, hl, wqkvh, wqkvl, nullptr, nullptr, nullptr, nullptr, qkvh, qkvl, 3*DM, DM);

    // launch 4: per-head SiLU-MLP residual on q,k
    qk_mlp<<<dim3(NT/2, 2), 256, QK_SMEM>>>(qkvh, qkvl,
                                             qs_w1, qs_b1, qs_w2, qs_b2,
                                             ks_w1, ks_b1, ks_w2, ks_b2);

    // launch 5: causal attention
    flash_mma<<<dim3(SS_/128, NH, BB), 256, FA_SMEM>>>(qkvh, qkvl, ah, al);

    // launch 6: out projection + residual
    gemm_mma<1,0><<<dim3(DM/128, NT/128), 256, GSMEM>>>(
        ah, al, woh, wol, nullptr, nullptr, out, out, nullptr, nullptr, DM, DM);

    // launch 7: mlp norm
    rmsnorm_k<<<NT, 256>>>(out, mlpn_w, hh, hl);

    // launch 8: fused gate+fc1+silu-mul -> f2 hi/lo
    gemm_mma<5,0><<<dim3(2*DFF/128, NT/128), 256, GSMEM>>>(
        hh, hl, gf1h, gf1l, gate_b, fc1_b, nullptr, nullptr, f2h, f2l, 2*DFF, DM);

    // launch 9: fc2 + bias + residual
    gemm_mma<4,0><<<dim3(DM/128, NT/128), 256, GSMEM>>>(
        f2h, f2l, fch, fcl, fc2_b, nullptr, out, out, nullptr, nullptr, DM, DFF);
}

// round 8
// speedup vs baseline: 3.3119x; 1.0766x over previous
#include <cuda_runtime.h>
#include <cuda_bf16.h>
#include <math.h>
#include <stdint.h>

typedef __nv_bfloat16 bf16;

#define BB   2
#define SS_  2048
#define DM   1024
#define NT   (BB*SS_)
#define NH   16
#define HD   64
#define DSTATE 128
#define DFF  4096

// ---------------- device scratch ----------------
__device__ __align__(256) bf16 g_qkv_hi[NT*3*DM], g_qkv_lo[NT*3*DM];
__device__ __align__(256) bf16 g_h_hi[NT*DM],     g_h_lo[NT*DM];
__device__ __align__(256) bf16 g_attn_hi[NT*DM],  g_attn_lo[NT*DM];
__device__ __align__(256) bf16 g_ff2_hi[NT*DFF],  g_ff2_lo[NT*DFF];
__device__ __align__(256) bf16 g_wqkvT_hi[3*DM*DM], g_wqkvT_lo[3*DM*DM];
__device__ __align__(256) bf16 g_woT_hi[DM*DM],   g_woT_lo[DM*DM];
__device__ __align__(256) bf16 g_gf1T_hi[2*DFF*DM], g_gf1T_lo[2*DFF*DM];
__device__ __align__(256) bf16 g_f2T_hi[DFF*DM],  g_f2T_lo[DFF*DM];
// qk silu-mlp weights, transposed+split: w1T [128,64], w2T [64,128] per q/k
__device__ __align__(256) bf16 g_w1qT_hi[DSTATE*HD], g_w1qT_lo[DSTATE*HD];
__device__ __align__(256) bf16 g_w2qT_hi[HD*DSTATE], g_w2qT_lo[HD*DSTATE];
__device__ __align__(256) bf16 g_w1kT_hi[DSTATE*HD], g_w1kT_lo[DSTATE*HD];
__device__ __align__(256) bf16 g_w2kT_hi[HD*DSTATE], g_w2kT_lo[HD*DSTATE];

// ---------------- PTX helpers ----------------
__device__ __forceinline__ uint32_t s2u(const void* p) {
    uint32_t a;
    asm("{ .reg .u64 t; cvta.to.shared.u64 t, %1; cvt.u32.u64 %0, t; }" : "=r"(a) : "l"(p));
    return a;
}
#define CP16(d, s)   asm volatile("cp.async.cg.shared.global [%0], [%1], 16;" :: "r"(d), "l"(s))
#define CP_COMMIT()  asm volatile("cp.async.commit_group;" ::: "memory")
#define CP_WAIT1()   asm volatile("cp.async.wait_group 1;" ::: "memory")

__device__ __forceinline__ void ldm_x4(uint32_t* r, uint32_t addr) {
    asm volatile("ldmatrix.sync.aligned.m8n8.x4.shared.b16 {%0,%1,%2,%3}, [%4];"
        : "=r"(r[0]), "=r"(r[1]), "=r"(r[2]), "=r"(r[3]) : "r"(addr));
}
__device__ __forceinline__ void mma_bf16(float* d, const uint32_t* a, const uint32_t* b) {
    asm volatile("mma.sync.aligned.m16n8k16.row.col.f32.bf16.bf16.f32 "
        "{%0,%1,%2,%3}, {%4,%5,%6,%7}, {%8,%9}, {%0,%1,%2,%3};"
        : "+f"(d[0]), "+f"(d[1]), "+f"(d[2]), "+f"(d[3])
        : "r"(a[0]), "r"(a[1]), "r"(a[2]), "r"(a[3]), "r"(b[0]), "r"(b[1]));
}

// ---------------- misc ----------------
__device__ __forceinline__ float block_sum(float v, float* sbuf) {
    int lane = threadIdx.x & 31, w = threadIdx.x >> 5;
    #pragma unroll
    for (int o = 16; o; o >>= 1) v += __shfl_xor_sync(0xffffffffu, v, o);
    if (lane == 0) sbuf[w] = v;
    __syncthreads();
    if (w == 0) {
        v = (lane < 8) ? sbuf[lane] : 0.f;
        #pragma unroll
        for (int o = 4; o; o >>= 1) v += __shfl_xor_sync(0xffffffffu, v, o);
        if (lane == 0) sbuf[0] = v;
    }
    __syncthreads();
    float r = sbuf[0];
    __syncthreads();
    return r;
}
__device__ __forceinline__ void split_bf16(float x, bf16& h, bf16& l) {
    h = __float2bfloat16(x);
    l = __float2bfloat16(x - __bfloat162float(h));
}
__device__ __forceinline__ uint32_t pk(bf16 a, bf16 b) {
    return ((uint32_t)__bfloat16_as_ushort(b) << 16) | __bfloat16_as_ushort(a);
}

// ---------------- norm kernels ----------------
__global__ __launch_bounds__(256) void norm3_fused(
    const float* __restrict__ x,
    const float* __restrict__ w1, const float* __restrict__ w2, const float* __restrict__ w3,
    float* __restrict__ xout, bf16* __restrict__ h_hi, bf16* __restrict__ h_lo)
{
    __shared__ float sbuf[32];
    const int t = blockIdx.x;
    const int base = threadIdx.x * 4;
    float4 v  = *(const float4*)(x + (size_t)t*DM + base);
    float4 a1 = *(const float4*)(w1 + base);
    float4 a2 = *(const float4*)(w2 + base);
    float4 a3 = *(const float4*)(w3 + base);

    float ss = v.x*v.x + v.y*v.y + v.z*v.z + v.w*v.w;
    float r = rsqrtf(block_sum(ss, sbuf) * (1.f/DM) + 1e-6f);
    v.x += a1.x*v.x*r; v.y += a1.y*v.y*r; v.z += a1.z*v.z*r; v.w += a1.w*v.w*r;

    ss = v.x*v.x + v.y*v.y + v.z*v.z + v.w*v.w;
    r = rsqrtf(block_sum(ss, sbuf) * (1.f/DM) + 1e-6f);
    v.x += a2.x*v.x*r; v.y += a2.y*v.y*r; v.z += a2.z*v.z*r; v.w += a2.w*v.w*r;
    *(float4*)(xout + (size_t)t*DM + base) = v;

    ss = v.x*v.x + v.y*v.y + v.z*v.z + v.w*v.w;
    r = rsqrtf(block_sum(ss, sbuf) * (1.f/DM) + 1e-6f);
    float hv[4] = { a3.x*v.x*r, a3.y*v.y*r, a3.z*v.z*r, a3.w*v.w*r };
    __align__(8) bf16 hh[4], hl[4];
    #pragma unroll
    for (int i = 0; i < 4; i++) split_bf16(hv[i], hh[i], hl[i]);
    *(uint2*)(h_hi + (size_t)t*DM + base) = *(uint2*)hh;
    *(uint2*)(h_lo + (size_t)t*DM + base) = *(uint2*)hl;
}

__global__ __launch_bounds__(256) void rmsnorm_k(
    const float* __restrict__ x, const float* __restrict__ w,
    bf16* __restrict__ o_hi, bf16* __restrict__ o_lo)
{
    __shared__ float sbuf[32];
    const int t = blockIdx.x;
    const int base = threadIdx.x * 4;
    float4 v = *(const float4*)(x + (size_t)t*DM + base);
    float4 a = *(const float4*)(w + base);
    float ss = v.x*v.x + v.y*v.y + v.z*v.z + v.w*v.w;
    float r = rsqrtf(block_sum(ss, sbuf) * (1.f/DM) + 1e-6f);
    float ov[4] = { a.x*v.x*r, a.y*v.y*r, a.z*v.z*r, a.w*v.w*r };
    __align__(8) bf16 hh[4], hl[4];
    #pragma unroll
    for (int i = 0; i < 4; i++) split_bf16(ov[i], hh[i], hl[i]);
    *(uint2*)(o_hi + (size_t)t*DM + base) = *(uint2*)hh;
    *(uint2*)(o_lo + (size_t)t*DM + base) = *(uint2*)hl;
}

// ---------------- fused weight transpose + split (single launch) ----------------
// m 0..2: qkv | 3: wo | 4: gate, 5: fc1 (interleaved rows) | 6: fc2 | 7..10: qk mlp weights
struct WAll {
    const float* src[11];
    bf16* th[11];
    bf16* tl[11];
};

__global__ __launch_bounds__(256) void wconv_all(WAll wa)
{
    __shared__ float t[64][65];
    const int id = blockIdx.x;
    int m, tt;
    if (id < 1024)      { m = id >> 8; tt = id & 255; }
    else if (id < 2048) { m = 4; tt = id - 1024; }
    else if (id < 3072) { m = 5; tt = id - 2048; }
    else if (id < 4096) { m = 6; tt = id - 3072; }
    else                { int i2 = id - 4096; m = 7 + (i2 >> 1); tt = i2 & 1; }
    const int K = (m == 6) ? DFF : (m == 8 || m == 10) ? DSTATE : (m == 7 || m == 9) ? HD : DM;
    const int N = (m == 4 || m == 5) ? DFF : (m == 7 || m == 9) ? DSTATE : (m == 8 || m == 10) ? HD : DM;
    const int ntx = N / 64;
    const int n0 = (tt % ntx) * 64, k0 = (tt / ntx) * 64;
    const float* W = wa.src[m];
    bf16* Th = wa.th[m];
    bf16* Tl = wa.tl[m];
    const bool ilv = (m == 4 || m == 5);
    const int foff = (m == 5) ? 1 : 0;

    const int tid = threadIdx.x;
    {
        const int r = tid >> 2, c0 = (tid & 3) * 16;
        const float* src = W + (size_t)(k0 + r)*N + n0 + c0;
        #pragma unroll
        for (int j = 0; j < 4; j++) {
            float4 vv = *(const float4*)(src + j*4);
            t[r][c0 + j*4 + 0] = vv.x; t[r][c0 + j*4 + 1] = vv.y;
            t[r][c0 + j*4 + 2] = vv.z; t[r][c0 + j*4 + 3] = vv.w;
        }
    }
    __syncthreads();
    {
        const int n = tid >> 2, ks = (tid & 3) * 16;
        uint32_t ph[8], pl[8];
        #pragma unroll
        for (int j = 0; j < 8; j++) {
            float a = t[ks + j*2][n], c = t[ks + j*2 + 1][n];
            bf16 ha, la, hc, lc;
            split_bf16(a, ha, la); split_bf16(c, hc, lc);
            ph[j] = pk(ha, hc); pl[j] = pk(la, lc);
        }
        const size_t row_out = ilv ? (size_t)(2*(n0 + n) + foff) : (size_t)(n0 + n);
        const size_t ou = (row_out*K + k0 + ks) >> 1;
        uint32_t* dh = (uint32_t*)Th + ou;
        uint32_t* dl = (uint32_t*)Tl + ou;
        *(uint4*)(dh)     = make_uint4(ph[0], ph[1], ph[2], ph[3]);
        *(uint4*)(dh + 4) = make_uint4(ph[4], ph[5], ph[6], ph[7]);
        *(uint4*)(dl)     = make_uint4(pl[0], pl[1], pl[2], pl[3]);
        *(uint4*)(dl + 4) = make_uint4(pl[4], pl[5], pl[6], pl[7]);
    }
}

// ---------------- bf16x3 GEMM via mma.sync ----------------
// EPI: 0 none | 1 +extra | 4 +bias+extra | 5 gate/fc1 interleaved
#define GSTAGE 32768
#define GSMEM  (3*GSTAGE)

__device__ __forceinline__ uint32_t swz(int row, int chunk) {
    return (uint32_t)(row*64 + ((chunk ^ (row & 3) ^ ((row >> 2) & 1)) << 4));
}

template<int EPI, int OSPLIT>
__global__ __launch_bounds__(256) void gemm_mma(
    const bf16* __restrict__ Ahi, const bf16* __restrict__ Alo,
    const bf16* __restrict__ Bhi, const bf16* __restrict__ Blo,
    const float* __restrict__ bias, const float* __restrict__ bias2,
    const float* __restrict__ extra,
    float* __restrict__ C, bf16* __restrict__ Chi, bf16* __restrict__ Clo,
    int N, int K)
{
    extern __shared__ char smem[];
    const uint32_t sb = s2u(smem);
    const int tid = threadIdx.x;
    const int lane = tid & 31, wid = tid >> 5;
    const int wm = wid >> 2, wn = wid & 3;
    const int row0 = blockIdx.y * 128, col0 = blockIdx.x * 128;
    const int nc = K / 32;

    const int lr = tid >> 1, lc = tid & 1;
    const uint32_t off0 = swz(lr, lc), off1 = swz(lr, lc + 2);
    const bf16* gAh = Ahi + (size_t)(row0 + lr)*K + lc*8;
    const bf16* gAl = Alo + (size_t)(row0 + lr)*K + lc*8;
    const bf16* gBh = Bhi + (size_t)(col0 + lr)*K + lc*8;
    const bf16* gBl = Blo + (size_t)(col0 + lr)*K + lc*8;

    #define GLOAD(st, kc) do { \
        const uint32_t s0 = sb + (uint32_t)(st)*GSTAGE; \
        const int ko = (kc)*32; \
        CP16(s0 +          off0, gAh + ko); CP16(s0 +          off1, gAh + ko + 16); \
        CP16(s0 +  8192 + off0, gAl + ko); CP16(s0 +  8192 + off1, gAl + ko + 16); \
        CP16(s0 + 16384 + off0, gBh + ko); CP16(s0 + 16384 + off1, gBh + ko + 16); \
        CP16(s0 + 24576 + off0, gBl + ko); CP16(s0 + 24576 + off1, gBl + ko + 16); \
    } while (0)

    const int arow = wm*64 + (lane & 15);
    const int abit = lane >> 4;
    const int brow = wn*32 + (lane & 7) + ((lane >> 4) & 1)*8;
    const int bbit = (lane >> 3) & 1;

    float acc[4][4][4];
    #pragma unroll
    for (int i = 0; i < 4; i++)
        #pragma unroll
        for (int j = 0; j < 4; j++)
            #pragma unroll
            for (int d2 = 0; d2 < 4; d2++) acc[i][j][d2] = 0.f;

    GLOAD(0, 0); CP_COMMIT();
    GLOAD(1, 1); CP_COMMIT();

    for (int kc = 0; kc < nc; kc++) {
        CP_WAIT1();
        __syncthreads();
        const uint32_t s0 = sb + (uint32_t)(kc % 3)*GSTAGE;
        #pragma unroll
        for (int ks = 0; ks < 2; ks++) {
            uint32_t ah[4][4], al[4][4], bh[2][4], bl[2][4];
            #pragma unroll
            for (int mt = 0; mt < 4; mt++) {
                const uint32_t ao = swz(arow + mt*16, ks*2 + abit);
                ldm_x4(ah[mt], s0 + ao);
                ldm_x4(al[mt], s0 + 8192 + ao);
            }
            #pragma unroll
            for (int n2 = 0; n2 < 2; n2++) {
                const uint32_t bo = swz(brow + n2*16, ks*2 + bbit);
                ldm_x4(bh[n2], s0 + 16384 + bo);
                ldm_x4(bl[n2], s0 + 24576 + bo);
            }
            #pragma unroll
            for (int mt = 0; mt < 4; mt++)
                #pragma unroll
                for (int nt = 0; nt < 4; nt++) {
                    const uint32_t* ph = &bh[nt >> 1][(nt & 1)*2];
                    const uint32_t* pl = &bl[nt >> 1][(nt & 1)*2];
                    mma_bf16(acc[mt][nt], ah[mt], ph);
                    mma_bf16(acc[mt][nt], ah[mt], pl);
                    mma_bf16(acc[mt][nt], al[mt], ph);
                }
        }
        if (kc + 2 < nc) GLOAD((kc + 2) % 3, kc + 2);
        CP_COMMIT();
    }
    #undef GLOAD

    const int erow = lane >> 2;
    const int ecol = (lane & 3)*2;
    #pragma unroll
    for (int mt = 0; mt < 4; mt++)
        #pragma unroll
        for (int hf = 0; hf < 2; hf++) {
            const int row = row0 + wm*64 + mt*16 + erow + hf*8;
            #pragma unroll
            for (int nt = 0; nt < 4; nt++) {
                const int col = col0 + wn*32 + nt*8 + ecol;
                float v0 = acc[mt][nt][hf*2 + 0];
                float v1 = acc[mt][nt][hf*2 + 1];
                if (EPI == 5) {
                    const int j = col >> 1;
                    float g = v0 + bias[j];
                    float f = v1 + bias2[j];
                    g = g / (1.f + __expf(-g));
                    const float rv = g * f;
                    bf16 h0, l0; split_bf16(rv, h0, l0);
                    const size_t po = (size_t)row * (size_t)(N >> 1) + j;
                    Chi[po] = h0; Clo[po] = l0;
                    continue;
                }
                const size_t ro = (size_t)row * N + col;
                if (EPI == 1) { float2 e = *(const float2*)(extra + ro); v0 += e.x; v1 += e.y; }
                if (EPI == 4) {
                    float2 e = *(const float2*)(extra + ro);
                    v0 += bias[col] + e.x; v1 += bias[col + 1] + e.y;
                }
                if (OSPLIT) {
                    bf16 h0, l0, h1, l1;
                    split_bf16(v0, h0, l0); split_bf16(v1, h1, l1);
                    *(uint32_t*)(Chi + ro) = pk(h0, h1);
                    *(uint32_t*)(Clo + ro) = pk(l0, l1);
                } else {
                    float2 o; o.x = v0; o.y = v1;
                    *(float2*)(C + ro) = o;
                }
            }
        }
}

// ---------------- tensor-core qk silu-mlp residual ----------------
// Per block: 8 tokens (128 rows of (token,head)); warp = one token (16 head-rows).
// MMA1: X[16,64] @ W1T -> silu -> MMA2: H[16,128] @ W2T -> +resid -> store hi/lo.
#define QM_X_H 0u
#define QM_X_L 18432u
#define QM_W1H 36864u
#define QM_W1L 55296u
#define QM_W2H 73728u
#define QM_W2L 91136u
#define QM_B1  108544u
#define QM_B2  109056u
#define QM_SMEM 109312

__global__ __launch_bounds__(256) void qk_mlp_mma(
    bf16* __restrict__ qkvh, bf16* __restrict__ qkvl,
    const bf16* __restrict__ w1qh, const bf16* __restrict__ w1ql,
    const bf16* __restrict__ w2qh, const bf16* __restrict__ w2ql,
    const bf16* __restrict__ w1kh, const bf16* __restrict__ w1kl,
    const bf16* __restrict__ w2kh, const bf16* __restrict__ w2kl,
    const float* __restrict__ qb1, const float* __restrict__ qb2,
    const float* __restrict__ kb1, const float* __restrict__ kb2)
{
    extern __shared__ char sm_[];
    const uint32_t sb = s2u(sm_);
    const int tid = threadIdx.x, lane = tid & 31, wid = tid >> 5;
    const int t0 = blockIdx.x * 8;
    const int seg = blockIdx.y * 1024;
    const bf16* w1h = blockIdx.y ? w1kh : w1qh;
    const bf16* w1l = blockIdx.y ? w1kl : w1ql;
    const bf16* w2h = blockIdx.y ? w2kh : w2qh;
    const bf16* w2l = blockIdx.y ? w2kl : w2ql;
    const float* b1 = blockIdx.y ? kb1 : qb1;
    const float* b2 = blockIdx.y ? kb2 : qb2;

    // ---- stage weights, bias, X ----
    {
        const int r = tid >> 1, half = tid & 1;   // w1 rows 0..127
        const uint4* s1h = (const uint4*)(w1h + r*HD + half*32);
        const uint4* s1l = (const uint4*)(w1l + r*HD + half*32);
        uint4* d1h = (uint4*)(sm_ + QM_W1H + r*144 + half*64);
        uint4* d1l = (uint4*)(sm_ + QM_W1L + r*144 + half*64);
        #pragma unroll
        for (int j = 0; j < 4; j++) { d1h[j] = s1h[j]; d1l[j] = s1l[j]; }
    }
    {
        const int r = tid >> 2, q = tid & 3;      // w2 rows 0..63
        const uint4* s2h = (const uint4*)(w2h + r*DSTATE + q*32);
        const uint4* s2l = (const uint4*)(w2l + r*DSTATE + q*32);
        uint4* d2h = (uint4*)(sm_ + QM_W2H + r*272 + q*64);
        uint4* d2l = (uint4*)(sm_ + QM_W2L + r*272 + q*64);
        #pragma unroll
        for (int j = 0; j < 4; j++) { d2h[j] = s2h[j]; d2l[j] = s2l[j]; }
    }
    if (tid < 128) *(float*)(sm_ + QM_B1 + tid*4) = b1[tid];
    if (tid < 64)  *(float*)(sm_ + QM_B2 + tid*4) = b2[tid];
    {
        const int r = tid >> 1, half = tid & 1;   // X rows 0..127
        const size_t ga = (size_t)(t0 + (r >> 4))*3072 + seg + (size_t)(r & 15)*64 + half*32;
        const uint4* sxh = (const uint4*)(qkvh + ga);
        const uint4* sxl = (const uint4*)(qkvl + ga);
        uint4* dxh = (uint4*)(sm_ + QM_X_H + r*144 + half*64);
        uint4* dxl = (uint4*)(sm_ + QM_X_L + r*144 + half*64);
        #pragma unroll
        for (int j = 0; j < 4; j++) { dxh[j] = sxh[j]; dxl[j] = sxl[j]; }
    }
    __syncthreads();

    const int m0 = wid * 16;

    // ---- MMA1: S[16,128] = X @ W1^T (bf16x3) ----
    float s[16][4];
    #pragma unroll
    for (int i = 0; i < 16; i++)
        #pragma unroll
        for (int e = 0; e < 4; e++) s[i][e] = 0.f;

    #pragma unroll
    for (int ks = 0; ks < 4; ks++) {
        uint32_t xh4[4], xl4[4];
        const uint32_t ao = (uint32_t)((m0 + (lane & 15))*144 + ks*32 + (lane >> 4)*16);
        ldm_x4(xh4, sb + QM_X_H + ao);
        ldm_x4(xl4, sb + QM_X_L + ao);
        #pragma unroll
        for (int n2 = 0; n2 < 8; n2++) {
            uint32_t wh4[4], wl4[4];
            const uint32_t bo = (uint32_t)((n2*16 + (lane & 7) + ((lane >> 4) & 1)*8)*144
                                           + ks*32 + ((lane >> 3) & 1)*16);
            ldm_x4(wh4, sb + QM_W1H + bo);
            ldm_x4(wl4, sb + QM_W1L + bo);
            mma_bf16(s[n2*2],   xh4, &wh4[0]);
            mma_bf16(s[n2*2],   xh4, &wl4[0]);
            mma_bf16(s[n2*2],   xl4, &wh4[0]);
            mma_bf16(s[n2*2+1], xh4, &wh4[2]);
            mma_bf16(s[n2*2+1], xh4, &wl4[2]);
            mma_bf16(s[n2*2+1], xl4, &wh4[2]);
        }
    }

    // ---- bias + SiLU ----
    #pragma unroll
    for (int nt = 0; nt < 16; nt++)
        #pragma unroll
        for (int e = 0; e < 4; e++) {
            const int col = nt*8 + (lane & 3)*2 + (e & 1);
            float v = s[nt][e] + *(const float*)(sm_ + QM_B1 + col*4);
            s[nt][e] = v / (1.f + __expf(-v));
        }

    // ---- MMA2: O[16,64] = H @ W2^T (bf16x3, C-frag->A-frag) ----
    float o[8][4];
    #pragma unroll
    for (int i = 0; i < 8; i++)
        #pragma unroll
        for (int e = 0; e < 4; e++) o[i][e] = 0.f;

    #pragma unroll
    for (int ks2 = 0; ks2 < 8; ks2++) {
        uint32_t pah[4], pal[4];
        {
            bf16 h0,l0,h1,l1;
            split_bf16(s[2*ks2][0],h0,l0);   split_bf16(s[2*ks2][1],h1,l1);
            pah[0] = pk(h0,h1); pal[0] = pk(l0,l1);
            split_bf16(s[2*ks2][2],h0,l0);   split_bf16(s[2*ks2][3],h1,l1);
            pah[1] = pk(h0,h1); pal[1] = pk(l0,l1);
            split_bf16(s[2*ks2+1][0],h0,l0); split_bf16(s[2*ks2+1][1],h1,l1);
            pah[2] = pk(h0,h1); pal[2] = pk(l0,l1);
            split_bf16(s[2*ks2+1][2],h0,l0); split_bf16(s[2*ks2+1][3],h1,l1);
            pah[3] = pk(h0,h1); pal[3] = pk(l0,l1);
        }
        #pragma unroll
        for (int n2 = 0; n2 < 4; n2++) {
            uint32_t wh4[4], wl4[4];
            const uint32_t bo = (uint32_t)((n2*16 + (lane & 7) + ((lane >> 4) & 1)*8)*272
                                           + ks2*32 + ((lane >> 3) & 1)*16);
            ldm_x4(wh4, sb + QM_W2H + bo);
            ldm_x4(wl4, sb + QM_W2L + bo);
            mma_bf16(o[n2*2],   pah, &wh4[0]);
            mma_bf16(o[n2*2],   pah, &wl4[0]);
            mma_bf16(o[n2*2],   pal, &wh4[0]);
            mma_bf16(o[n2*2+1], pah, &wh4[2]);
            mma_bf16(o[n2*2+1], pah, &wl4[2]);
            mma_bf16(o[n2*2+1], pal, &wh4[2]);
        }
    }

    // ---- epilogue: + bias2 + residual, split, store ----
    #pragma unroll
    for (int nt = 0; nt < 8; nt++)
        #pragma unroll
        for (int hf = 0; hf < 2; hf++) {
            const int rl = (lane >> 2) + hf*8;       // row within warp tile (= head)
            const int c0 = nt*8 + (lane & 3)*2;
            const int rX = m0 + rl;
            const float rs0 = __bfloat162float(*(const bf16*)(sm_ + QM_X_H + rX*144 + c0*2))
                            + __bfloat162float(*(const bf16*)(sm_ + QM_X_L + rX*144 + c0*2));
            const float rs1 = __bfloat162float(*(const bf16*)(sm_ + QM_X_H + rX*144 + c0*2 + 2))
                            + __bfloat162float(*(const bf16*)(sm_ + QM_X_L + rX*144 + c0*2 + 2));
            const float v0 = o[nt][hf*2 + 0] + *(const float*)(sm_ + QM_B2 + c0*4)     + rs0;
            const float v1 = o[nt][hf*2 + 1] + *(const float*)(sm_ + QM_B2 + c0*4 + 4) + rs1;
            bf16 h0, l0, h1, l1;
            split_bf16(v0, h0, l0); split_bf16(v1, h1, l1);
            const size_t ga = (size_t)(t0 + wid)*3072 + seg + (size_t)rl*64 + c0;
            *(uint32_t*)(qkvh + ga) = pk(h0, h1);
            *(uint32_t*)(qkvl + ga) = pk(l0, l1);
        }
}

// ---------------- tensor-core causal flash attention (bf16x3, qkv layout) ----------------
#define FA_QH 0u
#define FA_QL 18432u
#define FA_KH 36864u
#define FA_KL 46080u
#define FA_VH 55296u
#define FA_VL 64512u
#define FA_SMEM 73728

__global__ __launch_bounds__(256) void flash_mma(
    const bf16* __restrict__ QKVh, const bf16* __restrict__ QKVl,
    bf16* __restrict__ Ohi, bf16* __restrict__ Olo)
{
    extern __shared__ char sm_[];
    const uint32_t sb = s2u(sm_);
    const int tid = threadIdx.x;
    const int lane = tid & 31, wid = tid >> 5;
    const int qt = (int)gridDim.x - 1 - (int)blockIdx.x;
    const int h = blockIdx.y, b = blockIdx.z;
    const int qb = qt * 128;
    const int m0 = wid * 16;

    {
        const int r = tid >> 1;
        const int half = tid & 1;
        const size_t go = (size_t)(b*SS_ + qb + r)*3072 + h*64 + half*32;
        const uint4* srcH = (const uint4*)(QKVh + go);
        const uint4* srcL = (const uint4*)(QKVl + go);
        uint4* dstH = (uint4*)(sm_ + FA_QH + r*144 + half*64);
        uint4* dstL = (uint4*)(sm_ + FA_QL + r*144 + half*64);
        #pragma unroll
        for (int j = 0; j < 4; j++) { dstH[j] = srcH[j]; dstL[j] = srcL[j]; }
    }

    float mstate[2] = {-1e30f, -1e30f};
    float lsum[2]   = {0.f, 0.f};
    float o[8][4];
    #pragma unroll
    for (int i = 0; i < 8; i++)
        #pragma unroll
        for (int e = 0; e < 4; e++) o[i][e] = 0.f;

    const int nk = 2*qt + 2;
    for (int kj = 0; kj < nk; kj++) {
        __syncthreads();
        {
            const int r = tid >> 2;
            const int d0 = (tid & 3) * 16;
            const size_t gb = (size_t)(b*SS_ + kj*64 + r)*3072 + 1024 + h*64 + d0;
            *(uint4*)(sm_ + FA_KH + r*144 + d0*2)      = *(const uint4*)(QKVh + gb);
            *(uint4*)(sm_ + FA_KH + r*144 + d0*2 + 16) = *(const uint4*)(QKVh + gb + 8);
            *(uint4*)(sm_ + FA_KL + r*144 + d0*2)      = *(const uint4*)(QKVl + gb);
            *(uint4*)(sm_ + FA_KL + r*144 + d0*2 + 16) = *(const uint4*)(QKVl + gb + 8);
            union { uint4 u[2]; bf16 b[16]; } vh, vl;
            vh.u[0] = *(const uint4*)(QKVh + gb + 1024); vh.u[1] = *(const uint4*)(QKVh + gb + 1032);
            vl.u[0] = *(const uint4*)(QKVl + gb + 1024); vl.u[1] = *(const uint4*)(QKVl + gb + 1032);
            #pragma unroll
            for (int t = 0; t < 16; t++) {
                *(bf16*)(sm_ + FA_VH + (d0 + t)*144 + r*2) = vh.b[t];
                *(bf16*)(sm_ + FA_VL + (d0 + t)*144 + r*2) = vl.b[t];
            }
        }
        __syncthreads();

        if (kj*64 > qb + m0 + 15) continue;

        float s[8][4];
        #pragma unroll
        for (int i = 0; i < 8; i++)
            #pragma unroll
            for (int e = 0; e < 4; e++) s[i][e] = 0.f;

        #pragma unroll
        for (int ks = 0; ks < 4; ks++) {
            uint32_t qh4[4], ql4[4];
            const uint32_t ao = (uint32_t)((m0 + (lane & 15))*144 + ks*32 + (lane >> 4)*16);
            ldm_x4(qh4, sb + FA_QH + ao);
            ldm_x4(ql4, sb + FA_QL + ao);
            #pragma unroll
            for (int n2 = 0; n2 < 4; n2++) {
                uint32_t kh4[4], kl4[4];
                const uint32_t bo = (uint32_t)((n2*16 + (lane & 7) + ((lane >> 4) & 1)*8)*144
                                               + ks*32 + ((lane >> 3) & 1)*16);
                ldm_x4(kh4, sb + FA_KH + bo);
                ldm_x4(kl4, sb + FA_KL + bo);
                mma_bf16(s[n2*2],   qh4, &kh4[0]);
                mma_bf16(s[n2*2],   qh4, &kl4[0]);
                mma_bf16(s[n2*2],   ql4, &kh4[0]);
                mma_bf16(s[n2*2+1], qh4, &kh4[2]);
                mma_bf16(s[n2*2+1], qh4, &kl4[2]);
                mma_bf16(s[n2*2+1], ql4, &kh4[2]);
            }
        }

        const bool need_mask = (kj*64 + 63 > qb + m0);
        #pragma unroll
        for (int nt = 0; nt < 8; nt++)
            #pragma unroll
            for (int e = 0; e < 4; e++) {
                float val = s[nt][e] * 0.125f;
                if (need_mask) {
                    const int col = kj*64 + nt*8 + (lane & 3)*2 + (e & 1);
                    const int row = qb + m0 + (lane >> 2) + (e >> 1)*8;
                    if (col > row) val = -1e30f;
                }
                s[nt][e] = val;
            }

        float mx[2] = {-1e30f, -1e30f};
        #pragma unroll
        for (int nt = 0; nt < 8; nt++) {
            mx[0] = fmaxf(mx[0], fmaxf(s[nt][0], s[nt][1]));
            mx[1] = fmaxf(mx[1], fmaxf(s[nt][2], s[nt][3]));
        }
        #pragma unroll
        for (int hf = 0; hf < 2; hf++) {
            mx[hf] = fmaxf(mx[hf], __shfl_xor_sync(0xffffffffu, mx[hf], 1));
            mx[hf] = fmaxf(mx[hf], __shfl_xor_sync(0xffffffffu, mx[hf], 2));
        }
        float al2[2];
        #pragma unroll
        for (int hf = 0; hf < 2; hf++) {
            const float mn = fmaxf(fmaxf(mstate[hf], mx[hf]), -1e20f);
            al2[hf] = __expf(mstate[hf] - mn);
            mstate[hf] = mn;
        }
        float sum[2] = {0.f, 0.f};
        #pragma unroll
        for (int nt = 0; nt < 8; nt++)
            #pragma unroll
            for (int e = 0; e < 4; e++) {
                const float p = __expf(s[nt][e] - mstate[e >> 1]);
                s[nt][e] = p;
                sum[e >> 1] += p;
            }
        #pragma unroll
        for (int hf = 0; hf < 2; hf++) {
            sum[hf] += __shfl_xor_sync(0xffffffffu, sum[hf], 1);
            sum[hf] += __shfl_xor_sync(0xffffffffu, sum[hf], 2);
            lsum[hf] = lsum[hf]*al2[hf] + sum[hf];
        }
        #pragma unroll
        for (int nt = 0; nt < 8; nt++)
            #pragma unroll
            for (int e = 0; e < 4; e++) o[nt][e] *= al2[e >> 1];

        #pragma unroll
        for (int ks2 = 0; ks2 < 4; ks2++) {
            uint32_t pah[4], pal[4];
            {
                bf16 h0,l0,h1,l1;
                split_bf16(s[2*ks2][0],h0,l0);   split_bf16(s[2*ks2][1],h1,l1);
                pah[0] = pk(h0,h1); pal[0] = pk(l0,l1);
                split_bf16(s[2*ks2][2],h0,l0);   split_bf16(s[2*ks2][3],h1,l1);
                pah[1] = pk(h0,h1); pal[1] = pk(l0,l1);
                split_bf16(s[2*ks2+1][0],h0,l0); split_bf16(s[2*ks2+1][1],h1,l1);
                pah[2] = pk(h0,h1); pal[2] = pk(l0,l1);
                split_bf16(s[2*ks2+1][2],h0,l0); split_bf16(s[2*ks2+1][3],h1,l1);
                pah[3] = pk(h0,h1); pal[3] = pk(l0,l1);
            }
            #pragma unroll
            for (int dn2 = 0; dn2 < 4; dn2++) {
                uint32_t vh4[4], vl4[4];
                const uint32_t bo = (uint32_t)((dn2*16 + (lane & 7) + ((lane >> 4) & 1)*8)*144
                                               + ks2*32 + ((lane >> 3) & 1)*16);
                ldm_x4(vh4, sb + FA_VH + bo);
                ldm_x4(vl4, sb + FA_VL + bo);
                mma_bf16(o[dn2*2],   pah, &vh4[0]);
                mma_bf16(o[dn2*2],   pah, &vl4[0]);
                mma_bf16(o[dn2*2],   pal, &vh4[0]);
                mma_bf16(o[dn2*2+1], pah, &vh4[2]);
                mma_bf16(o[dn2*2+1], pah, &vl4[2]);
                mma_bf16(o[dn2*2+1], pal, &vh4[2]);
            }
        }
    }

    const float inv0 = 1.f / lsum[0];
    const float inv1 = 1.f / lsum[1];
    #pragma unroll
    for (int nt = 0; nt < 8; nt++)
        #pragma unroll
        for (int hf = 0; hf < 2; hf++) {
            const float inv = hf ? inv1 : inv0;
            const float v0 = o[nt][hf*2 + 0] * inv;
            const float v1 = o[nt][hf*2 + 1] * inv;
            bf16 h0, l0, h1, l1;
            split_bf16(v0, h0, l0); split_bf16(v1, h1, l1);
            const int row = qb + m0 + (lane >> 2) + hf*8;
            const int d0 = nt*8 + (lane & 3)*2;
            const size_t ro = ((size_t)(b*SS_ + row)*NH + h)*HD + d0;
            *(uint32_t*)(Ohi + ro) = pk(h0, h1);
            *(uint32_t*)(Olo + ro) = pk(l0, l1);
        }
}

// ---------------- launcher ----------------
extern "C" void kernel_launch(void* const* d_in, const int* in_sizes, int n_in,
                              void* d_out, int out_size)
{
    const float* x       = (const float*)d_in[0];
    const float* norm1_w = (const float*)d_in[2];
    const float* norm2_w = (const float*)d_in[3];
    const float* norm3_w = (const float*)d_in[4];
    const float* mlpn_w  = (const float*)d_in[5];
    const float* wq      = (const float*)d_in[6];
    const float* wk      = (const float*)d_in[7];
    const float* wv      = (const float*)d_in[8];
    const float* wo      = (const float*)d_in[9];
    const float* qs_w1   = (const float*)d_in[10];
    const float* qs_b1   = (const float*)d_in[11];
    const float* qs_w2   = (const float*)d_in[12];
    const float* qs_b2   = (const float*)d_in[13];
    const float* ks_w1   = (const float*)d_in[14];
    const float* ks_b1   = (const float*)d_in[15];
    const float* ks_w2   = (const float*)d_in[16];
    const float* ks_b2   = (const float*)d_in[17];
    const float* fc1_w   = (const float*)d_in[18];
    const float* fc1_b   = (const float*)d_in[19];
    const float* fc2_w   = (const float*)d_in[20];
    const float* fc2_b   = (const float*)d_in[21];
    const float* gate_w  = (const float*)d_in[22];
    const float* gate_b  = (const float*)d_in[23];
    float* out = (float*)d_out;

    bf16 *qkvh, *qkvl, *hh, *hl, *ah, *al, *f2h, *f2l;
    bf16 *wqkvh, *wqkvl, *woh, *wol, *gf1h, *gf1l, *fch, *fcl;
    bf16 *w1qh, *w1ql, *w2qh, *w2ql, *w1kh, *w1kl, *w2kh, *w2kl;
    cudaGetSymbolAddress((void**)&qkvh, g_qkv_hi);   cudaGetSymbolAddress((void**)&qkvl, g_qkv_lo);
    cudaGetSymbolAddress((void**)&hh,  g_h_hi);      cudaGetSymbolAddress((void**)&hl,  g_h_lo);
    cudaGetSymbolAddress((void**)&ah,  g_attn_hi);   cudaGetSymbolAddress((void**)&al,  g_attn_lo);
    cudaGetSymbolAddress((void**)&f2h, g_ff2_hi);    cudaGetSymbolAddress((void**)&f2l, g_ff2_lo);
    cudaGetSymbolAddress((void**)&wqkvh, g_wqkvT_hi); cudaGetSymbolAddress((void**)&wqkvl, g_wqkvT_lo);
    cudaGetSymbolAddress((void**)&woh, g_woT_hi);    cudaGetSymbolAddress((void**)&wol, g_woT_lo);
    cudaGetSymbolAddress((void**)&gf1h, g_gf1T_hi);  cudaGetSymbolAddress((void**)&gf1l, g_gf1T_lo);
    cudaGetSymbolAddress((void**)&fch, g_f2T_hi);    cudaGetSymbolAddress((void**)&fcl, g_f2T_lo);
    cudaGetSymbolAddress((void**)&w1qh, g_w1qT_hi);  cudaGetSymbolAddress((void**)&w1ql, g_w1qT_lo);
    cudaGetSymbolAddress((void**)&w2qh, g_w2qT_hi);  cudaGetSymbolAddress((void**)&w2ql, g_w2qT_lo);
    cudaGetSymbolAddress((void**)&w1kh, g_w1kT_hi);  cudaGetSymbolAddress((void**)&w1kl, g_w1kT_lo);
    cudaGetSymbolAddress((void**)&w2kh, g_w2kT_hi);  cudaGetSymbolAddress((void**)&w2kl, g_w2kT_lo);

    cudaFuncSetAttribute(gemm_mma<0,1>, cudaFuncAttributeMaxDynamicSharedMemorySize, GSMEM);
    cudaFuncSetAttribute(gemm_mma<1,0>, cudaFuncAttributeMaxDynamicSharedMemorySize, GSMEM);
    cudaFuncSetAttribute(gemm_mma<5,0>, cudaFuncAttributeMaxDynamicSharedMemorySize, GSMEM);
    cudaFuncSetAttribute(gemm_mma<4,0>, cudaFuncAttributeMaxDynamicSharedMemorySize, GSMEM);
    cudaFuncSetAttribute(qk_mlp_mma, cudaFuncAttributeMaxDynamicSharedMemorySize, QM_SMEM);
    cudaFuncSetAttribute(flash_mma, cudaFuncAttributeMaxDynamicSharedMemorySize, FA_SMEM);

    // launch 1: all weight converts
    WAll wa;
    wa.src[0] = wq;     wa.th[0] = wqkvh;           wa.tl[0] = wqkvl;
    wa.src[1] = wk;     wa.th[1] = wqkvh + DM*DM;   wa.tl[1] = wqkvl + DM*DM;
    wa.src[2] = wv;     wa.th[2] = wqkvh + 2*DM*DM; wa.tl[2] = wqkvl + 2*DM*DM;
    wa.src[3] = wo;     wa.th[3] = woh;             wa.tl[3] = wol;
    wa.src[4] = gate_w; wa.th[4] = gf1h;            wa.tl[4] = gf1l;
    wa.src[5] = fc1_w;  wa.th[5] = gf1h;            wa.tl[5] = gf1l;
    wa.src[6] = fc2_w;  wa.th[6] = fch;             wa.tl[6] = fcl;
    wa.src[7] = qs_w1;  wa.th[7] = w1qh;            wa.tl[7] = w1ql;
    wa.src[8] = qs_w2;  wa.th[8] = w2qh;            wa.tl[8] = w2ql;
    wa.src[9] = ks_w1;  wa.th[9] = w1kh;            wa.tl[9] = w1kl;
    wa.src[10] = ks_w2; wa.th[10] = w2kh;           wa.tl[10] = w2kl;
    wconv_all<<<4104, 256>>>(wa);

    // launch 2: mamba stages + pre-attn norm
    norm3_fused<<<NT, 256>>>(x, norm1_w, norm2_w, norm3_w, out, hh, hl);

    // launch 3: fused qkv projection -> token-major [NT, 3072] hi/lo
    gemm_mma<0,1><<<dim3(3*DM/128, NT/128), 256, GSMEM>>>(
        hh, hl, wqkvh, wqkvl, nullptr, nullptr, nullptr, nullptr, qkvh, qkvl, 3*DM, DM);

    // launch 4: per-head SiLU-MLP residual on q,k (tensor cores)
    qk_mlp_mma<<<dim3(NT/8, 2), 256, QM_SMEM>>>(qkvh, qkvl,
        w1qh, w1ql, w2qh, w2ql, w1kh, w1kl, w2kh, w2kl,
        qs_b1, qs_b2, ks_b1, ks_b2);

    // launch 5: causal attention
    flash_mma<<<dim3(SS_/128, NH, BB), 256, FA_SMEM>>>(qkvh, qkvl, ah, al);

    // launch 6: out projection + residual
    gemm_mma<1,0><<<dim3(DM/128, NT/128), 256, GSMEM>>>(
        ah, al, woh, wol, nullptr, nullptr, out, out, nullptr, nullptr, DM, DM);

    // launch 7: mlp norm
    rmsnorm_k<<<NT, 256>>>(out, mlpn_w, hh, hl);

    // launch 8: fused gate+fc1+silu-mul -> f2 hi/lo
    gemm_mma<5,0><<<dim3(2*DFF/128, NT/128), 256, GSMEM>>>(
        hh, hl, gf1h, gf1l, gate_b, fc1_b, nullptr, nullptr, f2h, f2l, 2*DFF, DM);

    // launch 9: fc2 + bias + residual
    gemm_mma<4,0><<<dim3(DM/128, NT/128), 256, GSMEM>>>(
        f2h, f2l, fch, fcl, fc2_b, nullptr, out, out, nullptr, nullptr, DM, DFF);
}